// round 10
// baseline (speedup 1.0000x reference)
#include <cuda_runtime.h>
#include <math.h>

#define HID   300
#define G3    900
#define NSEQ  64
#define BATCH 64
#define EMB   1024
#define KCAT  2524
#define HSZ   (BATCH*NSEQ*HID)
#define NCTA  132
#define GEFFN 2100
#define DSMEM_FLOATS (16*604 + 600*64)
#define EW_BLOCKS 704
#define GEFF_TX 10
#define GEFF_TY 29

__device__ float g_H[5 * HSZ];
__device__ float g_XIP[BATCH * NSEQ * 1800];   // [XI | XP] per row
__device__ float g_WX[1800 * HID];             // [wih_c ; whh_p]
__device__ float g_bX[1800];                   // [bih_c ; bhh_p]
__device__ float g_Geff[GEFFN * 600];          // rows 0..1799: WG@Wr2, 1800..2099: Wr2
__device__ float g_uT[600 * BATCH];            // uT[d*64 + b]
__device__ float g_G2[BATCH * GEFFN];
__device__ int   g_start[BATCH * NSEQ];
__device__ float g_Hcat[BATCH * NSEQ * KCAT];
__device__ float g_h1[BATCH * NSEQ * HID];
__device__ float g_h2[BATCH * NSEQ * HID];

__device__ volatile unsigned g_cnt;
__device__ volatile unsigned g_gen;

__device__ __forceinline__ float sigf(float x) {
    return __fdividef(1.f, 1.f + __expf(-x));
}
__device__ __forceinline__ float tanhfast(float x) {
    return __fdividef(2.f, 1.f + __expf(-2.f * x)) - 1.f;
}

__device__ __forceinline__ float bsum(float v, float* s8) {
    int tid = threadIdx.x;
#pragma unroll
    for (int o = 16; o > 0; o >>= 1) v += __shfl_xor_sync(0xffffffffu, v, o);
    if ((tid & 31) == 0) s8[tid >> 5] = v;
    __syncthreads();
    if (tid < 32) {
        float t = (tid < 8) ? s8[tid] : 0.f;
#pragma unroll
        for (int o = 4; o > 0; o >>= 1) t += __shfl_xor_sync(0xffffffffu, t, o);
        if (tid == 0) s8[0] = t;
    }
    __syncthreads();
    float r = s8[0];
    __syncthreads();
    return r;
}

// grid barrier; master = last CTA (idle during phase A -> hot polling)
__device__ __forceinline__ void gbar(unsigned bar, int tid, int cta) {
    __syncthreads();
    if (tid == 0) {
        __threadfence();
        asm volatile("red.global.add.u32 [%0], %1;" :: "l"((const void*)&g_cnt), "r"(1u) : "memory");
        if (cta == NCTA - 1) {
            while (g_cnt < NCTA * bar) __nanosleep(20);
            __threadfence();
            g_gen = bar;
        } else {
            while (g_gen < bar) __nanosleep(20);
        }
        asm volatile("fence.acq_rel.gpu;" ::: "memory");
    }
    __syncthreads();
}

// ---- merged prep: starts + WX/bX/Geff-bottom elementwise + Geff-top GEMM ----
__global__ void __launch_bounds__(256) k_prep2(
    const int* __restrict__ spk,
    const float* __restrict__ wih_c, const float* __restrict__ whh_p,
    const float* __restrict__ bih_c, const float* __restrict__ bhh_p,
    const float* __restrict__ whh_c, const float* __restrict__ wih_p,
    const float* __restrict__ wr0,   const float* __restrict__ wr1)
{
    int bid = blockIdx.x;
    if (bid < EW_BLOCKS) {
        for (int idx = bid * 256 + threadIdx.x; idx < 1800 * 300; idx += EW_BLOCKS * 256) {
            int n = idx / 300, d = idx - n * 300;
            g_WX[idx] = (n < 900) ? wih_c[n * 300 + d] : whh_p[(n - 900) * 300 + d];
            if (idx < 300 * 600) {
                int d2 = idx / 600, e = idx - d2 * 600;
                g_Geff[(1800 + d2) * 600 + e] =
                    (e < 300) ? wr0[d2 * 300 + e] : wr1[d2 * 300 + (e - 300)];
            }
            if (idx < 1800) g_bX[idx] = (idx < 900) ? bih_c[idx] : bhh_p[idx - 900];
            if (idx < 4096) {
                int b = idx >> 6, i = idx & 63;
                int s = spk[b * NSEQ + i];
                int last = -1;
                for (int j = 0; j < i; j++)
                    if (spk[b * NSEQ + j] == s) last = j;
                g_start[b * NSEQ + i] = last > 0 ? last : 0;
            }
            if (idx == 0) { g_cnt = 0; g_gen = 0; }
        }
        return;
    }
    // Geff top rows: C[n][e] = sum_d WGsrc[n][d] * Wr2[d][e], n<1800, e<600, K=300
    int gb2 = bid - EW_BLOCKS;
    int n0 = (gb2 / GEFF_TX) * 64, e0 = (gb2 % GEFF_TX) * 64;
    __shared__ float sA[16][65];
    __shared__ float sB[16][65];
    int tid = threadIdx.x;
    int tm = tid >> 4, tn = tid & 15;
    int lr = tid >> 2, lk = (tid & 3) * 4;
    float acc[4][4];
#pragma unroll
    for (int i = 0; i < 4; i++)
#pragma unroll
        for (int j = 0; j < 4; j++) acc[i][j] = 0.f;
    for (int k0 = 0; k0 < 300; k0 += 16) {
#pragma unroll
        for (int q = 0; q < 4; q++) {
            int k = k0 + lk + q;
            int n = n0 + lr;
            float av = 0.f;
            if (k < 300 && n < 1800)
                av = (n < 900) ? whh_c[n * 300 + k] : wih_p[(n - 900) * 300 + k];
            sA[lk + q][lr] = av;
            int e = e0 + lr;
            float bv = 0.f;
            if (k < 300 && e < 600)
                bv = (e < 300) ? wr0[k * 300 + e] : wr1[k * 300 + (e - 300)];
            sB[lk + q][lr] = bv;
        }
        __syncthreads();
#pragma unroll
        for (int kk = 0; kk < 16; kk++) {
            float a[4], bv[4];
#pragma unroll
            for (int i = 0; i < 4; i++) { a[i] = sA[kk][tm * 4 + i]; bv[i] = sB[kk][tn * 4 + i]; }
#pragma unroll
            for (int i = 0; i < 4; i++)
#pragma unroll
                for (int j = 0; j < 4; j++) acc[i][j] += a[i] * bv[j];
        }
        __syncthreads();
    }
#pragma unroll
    for (int i = 0; i < 4; i++) {
        int n = n0 + tm * 4 + i;
        if (n >= 1800) continue;
#pragma unroll
        for (int j = 0; j < 4; j++) {
            int e = e0 + tn * 4 + j;
            if (e >= 600) continue;
            g_Geff[(size_t)n * 600 + e] = acc[i][j];
        }
    }
}

// ---- dense GEMM: C=A@B^T+bias (opt relu). BM=128,BN=128,BK=16, 8x8 micro ----
__global__ void __launch_bounds__(256, 2) gemm8x8(
    const float* __restrict__ A, const float* __restrict__ B,
    const float* __restrict__ bias, float* __restrict__ C,
    int M, int N, int K, int relu)
{
    __shared__ float sA[16 * 132];
    __shared__ float sB[16 * 132];
    int tid = threadIdx.x;
    int m0 = blockIdx.y * 128, n0 = blockIdx.x * 128;
    int tm = tid & 15, tn = tid >> 4;
    int lr = tid >> 2, lk = (tid & 3) * 4;
    float acc[8][8];
#pragma unroll
    for (int i = 0; i < 8; i++)
#pragma unroll
        for (int j = 0; j < 8; j++) acc[i][j] = 0.f;

    for (int k0 = 0; k0 < K; k0 += 16) {
#pragma unroll
        for (int h = 0; h < 2; h++) {
            int m = lr + h * 64, gm = m0 + m, kb = k0 + lk;
            float4 av = make_float4(0.f, 0.f, 0.f, 0.f);
            if (gm < M) {
                if (kb + 3 < K) av = *(const float4*)(A + (size_t)gm * K + kb);
                else {
                    if (kb     < K) av.x = A[(size_t)gm * K + kb];
                    if (kb + 1 < K) av.y = A[(size_t)gm * K + kb + 1];
                    if (kb + 2 < K) av.z = A[(size_t)gm * K + kb + 2];
                }
            }
            sA[(lk + 0) * 132 + m] = av.x;
            sA[(lk + 1) * 132 + m] = av.y;
            sA[(lk + 2) * 132 + m] = av.z;
            sA[(lk + 3) * 132 + m] = av.w;

            int gn = n0 + m;
            float4 bv = make_float4(0.f, 0.f, 0.f, 0.f);
            if (gn < N) {
                if (kb + 3 < K) bv = *(const float4*)(B + (size_t)gn * K + kb);
                else {
                    if (kb     < K) bv.x = B[(size_t)gn * K + kb];
                    if (kb + 1 < K) bv.y = B[(size_t)gn * K + kb + 1];
                    if (kb + 2 < K) bv.z = B[(size_t)gn * K + kb + 2];
                }
            }
            sB[(lk + 0) * 132 + m] = bv.x;
            sB[(lk + 1) * 132 + m] = bv.y;
            sB[(lk + 2) * 132 + m] = bv.z;
            sB[(lk + 3) * 132 + m] = bv.w;
        }
        __syncthreads();
#pragma unroll
        for (int kk = 0; kk < 16; kk++) {
            float4 xa0 = *(const float4*)(sA + kk * 132 + tm * 4);
            float4 xa1 = *(const float4*)(sA + kk * 132 + 64 + tm * 4);
            float4 xb0 = *(const float4*)(sB + kk * 132 + tn * 4);
            float4 xb1 = *(const float4*)(sB + kk * 132 + 64 + tn * 4);
            float a[8] = {xa0.x, xa0.y, xa0.z, xa0.w, xa1.x, xa1.y, xa1.z, xa1.w};
            float bv[8] = {xb0.x, xb0.y, xb0.z, xb0.w, xb1.x, xb1.y, xb1.z, xb1.w};
#pragma unroll
            for (int i = 0; i < 8; i++)
#pragma unroll
                for (int j = 0; j < 8; j++) acc[i][j] += a[i] * bv[j];
        }
        __syncthreads();
    }
#pragma unroll
    for (int i = 0; i < 8; i++) {
        int m = m0 + ((i < 4) ? (tm * 4 + i) : (64 + tm * 4 + i - 4));
        if (m >= M) continue;
#pragma unroll
        for (int j = 0; j < 8; j++) {
            int n = n0 + ((j < 4) ? (tn * 4 + j) : (64 + tn * 4 + j - 4));
            if (n >= N) continue;
            float v = acc[i][j] + (bias ? bias[n] : 0.f);
            if (relu) v = fmaxf(v, 0.f);
            C[(size_t)m * N + n] = v;
        }
    }
}

// ---------------- persistent per-layer scan kernel ----------------
__global__ void __launch_bounds__(256, 1) persist_layer(
    const float* __restrict__ Hin, float* __restrict__ H1,
    const float* __restrict__ XIP,
    const float* __restrict__ wq, const float* __restrict__ wk,
    const float* __restrict__ gatb, int layer,
    const int* __restrict__ spk, const int* __restrict__ start,
    const float* __restrict__ bhh_c, const float* __restrict__ bih_p,
    const float* __restrict__ Geff, float* __restrict__ uT,
    float* __restrict__ G2)
{
    extern __shared__ float dsm[];
    float* sW = dsm;                 // 16*604
    float* sU = dsm + 16 * 604;      // 600*64, layout [d*64 + b]

    __shared__ float s8[8];
    __shared__ float s_w0[64];
    __shared__ float s_w1[64];
    __shared__ float s_kdot[64];
    __shared__ float s_qd[64];       // qd(i) + gat_b, precomputed per layer

    const int tid = threadIdx.x;
    const int cta = blockIdx.x;
    const int b = cta;
    const int n0 = cta * 16;
    const int wid = tid >> 5, lid = tid & 31;

    for (int idx = tid; idx < 16 * 600; idx += 256) {
        int c = idx / 600, k = idx - c * 600;
        int n = n0 + c;
        sW[c * 604 + k] = (n < GEFFN) ? Geff[(size_t)n * 600 + k] : 0.f;
    }

    const int cB = tid & 15, bpg = tid >> 4;
    const int nB = n0 + cB;
    float biasv = 0.f;
    if (nB < 900) biasv = bhh_c[nB];
    else if (nB < 1800) biasv = bih_p[nB - 900];
    const float4* wrow = (const float4*)(sW + cB * 604);
    unsigned uAddr = (unsigned)__cvta_generic_to_shared(sU) + bpg * 16;
    const float4* src4 = (const float4*)uT;
    float4* dst4 = (float4*)sU;
    const int K4C[5] = {0, 38, 76, 114, 150};

    unsigned bar = 0;
    const float gb = gatb[layer];

    if (cta < 64) {
        // precompute qd(i)+gb for all i
        for (int i = wid; i < 64; i += 8) {
            float p = 0.f;
            const float* hr = Hin + ((size_t)b * NSEQ + i) * HID;
            for (int j = lid; j < HID; j += 32) p += hr[j] * wq[j];
#pragma unroll
            for (int o = 16; o > 0; o >>= 1) p += __shfl_xor_sync(0xffffffffu, p, o);
            if (lid == 0) s_qd[i] = p + gb;
        }
        // init row 0
        const float* xi = XIP + (size_t)b * NSEQ * 1800;
        const float* xp = xi + 900;
        const float* x0 = Hin + (size_t)b * NSEQ * HID;
        float* h1 = H1 + (size_t)b * NSEQ * HID;
        float kp = 0.f;
        for (int d = tid; d < HID; d += 256) {
            float r  = sigf(xi[d] + bhh_c[d]);
            float z  = sigf(xi[300 + d] + bhh_c[300 + d]);
            float nn = tanhfast(xi[600 + d] + r * bhh_c[600 + d]);
            float C0 = (1.f - z) * nn;
            float r2 = sigf(bih_p[d] + xp[d]);
            float z2 = sigf(bih_p[300 + d] + xp[300 + d]);
            float n2 = tanhfast(bih_p[600 + d] + r2 * xp[600 + d]);
            float P0 = (1.f - z2) * n2 + z2 * x0[d];
            float h = C0 + P0;
            h1[d] = h;
            kp += h * wk[d];
        }
        float ks = bsum(kp, s8);
        if (tid == 0) s_kdot[0] = ks;
    }
    __syncthreads();

    for (int i = 1; i <= 63; i++) {
        // ===== phase A (CTAs 0..63): GRU row i-1, attention -> uT =====
        if (cta < 64) {
            if (i >= 2) {
                int row = i - 1;
                const float* Gp = G2 + (size_t)b * GEFFN;
                const float* xi = XIP + ((size_t)b * NSEQ + row) * 1800;
                const float* xp = xi + 900;
                const float* q  = Hin + ((size_t)b * NSEQ + row) * HID;
                float* h1r = H1 + ((size_t)b * NSEQ + row) * HID;
                float kp = 0.f;
                for (int d = tid; d < HID; d += 256) {
                    float Md = __ldcg(Gp + 1800 + d);
                    float r  = sigf(xi[d]       + __ldcg(Gp + d));
                    float z  = sigf(xi[300 + d] + __ldcg(Gp + 300 + d));
                    float nn = tanhfast(xi[600 + d] + r * __ldcg(Gp + 600 + d));
                    float Cc = (1.f - z) * nn + z * Md;
                    float r2 = sigf(__ldcg(Gp + 900 + d)  + xp[d]);
                    float z2 = sigf(__ldcg(Gp + 1200 + d) + xp[300 + d]);
                    float n2 = tanhfast(__ldcg(Gp + 1500 + d) + r2 * xp[600 + d]);
                    float Pp = (1.f - z2) * n2 + z2 * q[d];
                    float h = Cc + Pp;
                    h1r[d] = h;
                    kp += h * wk[d];
                }
                float ks = bsum(kp, s8);
                if (tid == 0) s_kdot[row] = ks;
                __syncthreads();
            }
            int st = start[b * NSEQ + i];
            int cnt = i - st;
            // single-warp softmax over window (cnt <= 63)
            if (tid < 32) {
                int spki = spk[b * NSEQ + i];
                float qd = s_qd[i];
                float a1 = (tid < cnt)      ? qd + s_kdot[st + tid]      : -1e30f;
                float a2 = (tid + 32 < cnt) ? qd + s_kdot[st + tid + 32] : -1e30f;
                float m = fmaxf(a1, a2);
#pragma unroll
                for (int o = 16; o > 0; o >>= 1) m = fmaxf(m, __shfl_xor_sync(0xffffffffu, m, o));
                float e1 = (tid < cnt)      ? __expf(a1 - m) : 0.f;
                float e2 = (tid + 32 < cnt) ? __expf(a2 - m) : 0.f;
                float s = e1 + e2;
#pragma unroll
                for (int o = 16; o > 0; o >>= 1) s += __shfl_xor_sync(0xffffffffu, s, o);
                float inv = __fdividef(1.f, s);
                if (tid < cnt) {
                    float w = e1 * inv;
                    float smv = (spk[b * NSEQ + st + tid] == spki) ? 1.f : 0.f;
                    s_w0[tid] = w * smv;
                    s_w1[tid] = w * (1.f - smv);
                }
                if (tid + 32 < cnt) {
                    float w = e2 * inv;
                    float smv = (spk[b * NSEQ + st + tid + 32] == spki) ? 1.f : 0.f;
                    s_w0[tid + 32] = w * smv;
                    s_w1[tid + 32] = w * (1.f - smv);
                }
            }
            __syncthreads();
            for (int d = tid; d < 600; d += 256) {
                int ei = (d < 300) ? d : d - 300;
                const float* wt = (d < 300) ? s_w0 : s_w1;
                const float* base = H1 + ((size_t)b * NSEQ + st) * HID + ei;
                float acc = 0.f;
                for (int j = 0; j < cnt; j++)
                    acc += wt[j] * base[j * HID];
                __stcg(uT + d * 64 + b, acc);
            }
        }
        gbar(++bar, tid, cta);   // u ready

        // ===== phase B: stage uT chunks pipelined with f32x2 GEMM =====
        {
            // copy chunk 0
            for (int idx = K4C[0] * 64 + tid; idx < K4C[1] * 64; idx += 256)
                dst4[idx] = __ldcg(src4 + idx);
            __syncthreads();

            unsigned long long a01 = 0ull, a23 = 0ull;
#pragma unroll
            for (int c = 0; c < 4; c++) {
                if (c < 3) {
                    for (int idx = K4C[c + 1] * 64 + tid; idx < K4C[c + 2] * 64; idx += 256)
                        dst4[idx] = __ldcg(src4 + idx);
                }
                for (int k4 = K4C[c]; k4 < K4C[c + 1]; k4++) {
                    float4 w = wrow[k4];
                    unsigned base = uAddr + (unsigned)(k4 * 1024);
#define PB_STEP(OFF, WC) { \
                    unsigned long long p01, p23, wp; \
                    asm volatile("ld.shared.v2.u64 {%0,%1},[%2];" : "=l"(p01), "=l"(p23) : "r"(base + OFF)); \
                    asm volatile("mov.b64 %0,{%1,%1};" : "=l"(wp) : "f"(WC)); \
                    asm volatile("fma.rn.f32x2 %0,%1,%2,%0;" : "+l"(a01) : "l"(p01), "l"(wp)); \
                    asm volatile("fma.rn.f32x2 %0,%1,%2,%0;" : "+l"(a23) : "l"(p23), "l"(wp)); }
                    PB_STEP(0u,   w.x)
                    PB_STEP(256u, w.y)
                    PB_STEP(512u, w.z)
                    PB_STEP(768u, w.w)
#undef PB_STEP
                }
                if (c < 3) __syncthreads();
            }
            float r0, r1, r2, r3;
            asm volatile("mov.b64 {%0,%1},%2;" : "=f"(r0), "=f"(r1) : "l"(a01));
            asm volatile("mov.b64 {%0,%1},%2;" : "=f"(r2), "=f"(r3) : "l"(a23));
            if (nB < GEFFN) {
                int bb = bpg * 4;
                G2[(size_t)(bb + 0) * GEFFN + nB] = r0 + biasv;
                G2[(size_t)(bb + 1) * GEFFN + nB] = r1 + biasv;
                G2[(size_t)(bb + 2) * GEFFN + nB] = r2 + biasv;
                G2[(size_t)(bb + 3) * GEFFN + nB] = r3 + biasv;
            }
        }
        gbar(++bar, tid, cta);   // G2 ready
    }

    // final GRU update: row 63
    if (cta < 64) {
        int row = 63;
        const float* Gp = G2 + (size_t)b * GEFFN;
        const float* xi = XIP + ((size_t)b * NSEQ + row) * 1800;
        const float* xp = xi + 900;
        const float* q  = Hin + ((size_t)b * NSEQ + row) * HID;
        float* h1r = H1 + ((size_t)b * NSEQ + row) * HID;
        for (int d = tid; d < HID; d += 256) {
            float Md = __ldcg(Gp + 1800 + d);
            float r  = sigf(xi[d]       + __ldcg(Gp + d));
            float z  = sigf(xi[300 + d] + __ldcg(Gp + 300 + d));
            float nn = tanhfast(xi[600 + d] + r * __ldcg(Gp + 600 + d));
            float Cc = (1.f - z) * nn + z * Md;
            float r2 = sigf(__ldcg(Gp + 900 + d)  + xp[d]);
            float z2 = sigf(__ldcg(Gp + 1200 + d) + xp[300 + d]);
            float n2 = tanhfast(__ldcg(Gp + 1500 + d) + r2 * xp[600 + d]);
            float Pp = (1.f - z2) * n2 + z2 * q[d];
            h1r[d] = Cc + Pp;
        }
    }
}

__global__ void k_concat(const float* __restrict__ feat) {
    int r = blockIdx.x;
    for (int c = threadIdx.x; c < KCAT; c += blockDim.x) {
        float v;
        if (c < 1500) {
            int seg = c / 300, off = c - seg * 300;
            v = g_H[seg * HSZ + r * HID + off];
        } else {
            v = feat[r * EMB + (c - 1500)];
        }
        g_Hcat[r * KCAT + c] = v;
    }
}

extern "C" void kernel_launch(void* const* d_in, const int* in_sizes, int n_in,
                              void* d_out, int out_size) {
    const float* features = (const float*)d_in[0];
    const int*   speakers = (const int*)d_in[1];
    const float* w_in   = (const float*)d_in[2];
    const float* b_in   = (const float*)d_in[3];
    const float* gat_wq = (const float*)d_in[4];
    const float* gat_wk = (const float*)d_in[5];
    const float* gat_b  = (const float*)d_in[6];
    const float* wr0    = (const float*)d_in[7];
    const float* wr1    = (const float*)d_in[8];
    const float* wih_c  = (const float*)d_in[9];
    const float* whh_c  = (const float*)d_in[10];
    const float* bih_c  = (const float*)d_in[11];
    const float* bhh_c  = (const float*)d_in[12];
    const float* wih_p  = (const float*)d_in[13];
    const float* whh_p  = (const float*)d_in[14];
    const float* bih_p  = (const float*)d_in[15];
    const float* bhh_p  = (const float*)d_in[16];
    const float* w1 = (const float*)d_in[17];
    const float* b1 = (const float*)d_in[18];
    const float* w2 = (const float*)d_in[19];
    const float* b2 = (const float*)d_in[20];
    const float* w3 = (const float*)d_in[21];
    const float* b3 = (const float*)d_in[22];

    float *H, *XIPp, *WXp, *bXp, *Geffp, *uTp, *G2p, *Hcatp, *h1p, *h2p;
    int *startp;
    cudaGetSymbolAddress((void**)&H,     g_H);
    cudaGetSymbolAddress((void**)&XIPp,  g_XIP);
    cudaGetSymbolAddress((void**)&WXp,   g_WX);
    cudaGetSymbolAddress((void**)&bXp,   g_bX);
    cudaGetSymbolAddress((void**)&Geffp, g_Geff);
    cudaGetSymbolAddress((void**)&uTp,   g_uT);
    cudaGetSymbolAddress((void**)&G2p,   g_G2);
    cudaGetSymbolAddress((void**)&startp,g_start);
    cudaGetSymbolAddress((void**)&Hcatp, g_Hcat);
    cudaGetSymbolAddress((void**)&h1p,   g_h1);
    cudaGetSymbolAddress((void**)&h2p,   g_h2);

    cudaFuncSetAttribute(persist_layer,
                         cudaFuncAttributeMaxDynamicSharedMemorySize,
                         DSMEM_FLOATS * 4);

    const int MROWS = BATCH * NSEQ;
    const int PREP_GRID = EW_BLOCKS + GEFF_TX * GEFF_TY;

    for (int l = 0; l < 4; l++) {
        // per-layer prep (starts + barrier reset are idempotent/per-layer safe)
        k_prep2<<<PREP_GRID, 256>>>(
            speakers,
            wih_c + l * G3 * HID, whh_p + l * G3 * HID,
            bih_c + l * G3, bhh_p + l * G3,
            whh_c + l * G3 * HID, wih_p + l * G3 * HID,
            wr0 + l * HID * HID, wr1 + l * HID * HID);

        if (l == 0) {
            gemm8x8<<<dim3((HID + 127) / 128, MROWS / 128), 256>>>(
                features, w_in, b_in, H, MROWS, HID, EMB, 1);
        }
        const float* Hin = H + l * HSZ;
        float* H1 = H + (l + 1) * HSZ;

        gemm8x8<<<dim3((1800 + 127) / 128, MROWS / 128), 256>>>(
            Hin, WXp, bXp, XIPp, MROWS, 1800, HID, 0);

        persist_layer<<<NCTA, 256, DSMEM_FLOATS * 4>>>(
            Hin, H1, XIPp, gat_wq + l * HID, gat_wk + l * HID, gat_b, l,
            speakers, startp, bhh_c + l * G3, bih_p + l * G3, Geffp, uTp, G2p);
    }

    k_concat<<<MROWS, 256>>>(features);

    gemm8x8<<<dim3((HID + 127) / 128, MROWS / 128), 256>>>(
        Hcatp, w1, b1, h1p, MROWS, HID, KCAT, 1);
    gemm8x8<<<dim3((HID + 127) / 128, MROWS / 128), 256>>>(
        h1p, w2, b2, h2p, MROWS, HID, HID, 1);
    gemm8x8<<<dim3(1, MROWS / 128), 256>>>(
        h2p, w3, b3, (float*)d_out, MROWS, 7, HID, 0);
}

// round 11
// speedup vs baseline: 1.3577x; 1.3577x over previous
#include <cuda_runtime.h>
#include <math.h>

#define HID   300
#define G3    900
#define NSEQ  64
#define BATCH 64
#define EMB   1024
#define KCAT  2524
#define HSZ   (BATCH*NSEQ*HID)
#define NCTA  132
#define GEFFN 2100
#define SWT_F 9600
#define SU_F  38400
#define DSMEM_F (SWT_F + SU_F)      /* 48000 floats = 192000 B */
#define EW_BLOCKS 704
#define GEFF_TX 10
#define GEFF_TY 29

__device__ float g_H[5 * HSZ];
__device__ float g_XIP[BATCH * NSEQ * 1800];   // [XI | XP] per row
__device__ float g_WX[1800 * HID];             // [wih_c ; whh_p]
__device__ float g_bX[1800];                   // [bih_c ; bhh_p]
__device__ float g_Geff[GEFFN * 600];          // rows 0..1799: WG@Wr2, 1800..2099: Wr2
__device__ float g_uT[600 * BATCH];            // uT[d*64 + b]
__device__ float g_G2T[2112 * BATCH];          // transposed: G2T[n*64 + b]
__device__ int   g_start[BATCH * NSEQ];
__device__ float g_Hcat[BATCH * NSEQ * KCAT];
__device__ float g_h1[BATCH * NSEQ * HID];
__device__ float g_h2[BATCH * NSEQ * HID];

__device__ volatile unsigned g_cnt;
__device__ volatile unsigned g_gen;

__device__ __forceinline__ float sigf(float x) {
    return __fdividef(1.f, 1.f + __expf(-x));
}
__device__ __forceinline__ float tanhfast(float x) {
    return __fdividef(2.f, 1.f + __expf(-2.f * x)) - 1.f;
}

__device__ __forceinline__ float bsum(float v, float* s8) {
    int tid = threadIdx.x;
#pragma unroll
    for (int o = 16; o > 0; o >>= 1) v += __shfl_xor_sync(0xffffffffu, v, o);
    if ((tid & 31) == 0) s8[tid >> 5] = v;
    __syncthreads();
    if (tid < 32) {
        float t = (tid < 8) ? s8[tid] : 0.f;
#pragma unroll
        for (int o = 4; o > 0; o >>= 1) t += __shfl_xor_sync(0xffffffffu, t, o);
        if (tid == 0) s8[0] = t;
    }
    __syncthreads();
    float r = s8[0];
    __syncthreads();
    return r;
}

// grid barrier; master = last CTA
__device__ __forceinline__ void gbar(unsigned bar, int tid, int cta) {
    __syncthreads();
    if (tid == 0) {
        __threadfence();
        asm volatile("red.global.add.u32 [%0], %1;" :: "l"((const void*)&g_cnt), "r"(1u) : "memory");
        if (cta == NCTA - 1) {
            while (g_cnt < NCTA * bar) __nanosleep(20);
            __threadfence();
            g_gen = bar;
        } else {
            while (g_gen < bar) __nanosleep(20);
        }
        asm volatile("fence.acq_rel.gpu;" ::: "memory");
    }
    __syncthreads();
}

// ---- merged prep: starts + WX/bX/Geff-bottom elementwise + Geff-top GEMM ----
__global__ void __launch_bounds__(256) k_prep2(
    const int* __restrict__ spk,
    const float* __restrict__ wih_c, const float* __restrict__ whh_p,
    const float* __restrict__ bih_c, const float* __restrict__ bhh_p,
    const float* __restrict__ whh_c, const float* __restrict__ wih_p,
    const float* __restrict__ wr0,   const float* __restrict__ wr1)
{
    int bid = blockIdx.x;
    if (bid < EW_BLOCKS) {
        for (int idx = bid * 256 + threadIdx.x; idx < 1800 * 300; idx += EW_BLOCKS * 256) {
            int n = idx / 300, d = idx - n * 300;
            g_WX[idx] = (n < 900) ? wih_c[n * 300 + d] : whh_p[(n - 900) * 300 + d];
            if (idx < 300 * 600) {
                int d2 = idx / 600, e = idx - d2 * 600;
                g_Geff[(1800 + d2) * 600 + e] =
                    (e < 300) ? wr0[d2 * 300 + e] : wr1[d2 * 300 + (e - 300)];
            }
            if (idx < 1800) g_bX[idx] = (idx < 900) ? bih_c[idx] : bhh_p[idx - 900];
            if (idx < 4096) {
                int b = idx >> 6, i = idx & 63;
                int s = spk[b * NSEQ + i];
                int last = -1;
                for (int j = 0; j < i; j++)
                    if (spk[b * NSEQ + j] == s) last = j;
                g_start[b * NSEQ + i] = last > 0 ? last : 0;
            }
            if (idx == 0) { g_cnt = 0; g_gen = 0; }
        }
        return;
    }
    // Geff top rows: C[n][e] = sum_d WGsrc[n][d] * Wr2[d][e]
    int gb2 = bid - EW_BLOCKS;
    int n0 = (gb2 / GEFF_TX) * 64, e0 = (gb2 % GEFF_TX) * 64;
    __shared__ float sA[16][65];
    __shared__ float sB[16][65];
    int tid = threadIdx.x;
    int tm = tid >> 4, tn = tid & 15;
    int lr = tid >> 2, lk = (tid & 3) * 4;
    float acc[4][4];
#pragma unroll
    for (int i = 0; i < 4; i++)
#pragma unroll
        for (int j = 0; j < 4; j++) acc[i][j] = 0.f;
    for (int k0 = 0; k0 < 300; k0 += 16) {
#pragma unroll
        for (int q = 0; q < 4; q++) {
            int k = k0 + lk + q;
            int n = n0 + lr;
            float av = 0.f;
            if (k < 300 && n < 1800)
                av = (n < 900) ? whh_c[n * 300 + k] : wih_p[(n - 900) * 300 + k];
            sA[lk + q][lr] = av;
            int e = e0 + lr;
            float bv = 0.f;
            if (k < 300 && e < 600)
                bv = (e < 300) ? wr0[k * 300 + e] : wr1[k * 300 + (e - 300)];
            sB[lk + q][lr] = bv;
        }
        __syncthreads();
#pragma unroll
        for (int kk = 0; kk < 16; kk++) {
            float a[4], bv[4];
#pragma unroll
            for (int i = 0; i < 4; i++) { a[i] = sA[kk][tm * 4 + i]; bv[i] = sB[kk][tn * 4 + i]; }
#pragma unroll
            for (int i = 0; i < 4; i++)
#pragma unroll
                for (int j = 0; j < 4; j++) acc[i][j] += a[i] * bv[j];
        }
        __syncthreads();
    }
#pragma unroll
    for (int i = 0; i < 4; i++) {
        int n = n0 + tm * 4 + i;
        if (n >= 1800) continue;
#pragma unroll
        for (int j = 0; j < 4; j++) {
            int e = e0 + tn * 4 + j;
            if (e >= 600) continue;
            g_Geff[(size_t)n * 600 + e] = acc[i][j];
        }
    }
}

// ---- dense GEMM: C=A@B^T+bias (opt relu). BM=128,BN=128,BK=16, 8x8 micro ----
__global__ void __launch_bounds__(256, 2) gemm8x8(
    const float* __restrict__ A, const float* __restrict__ B,
    const float* __restrict__ bias, float* __restrict__ C,
    int M, int N, int K, int relu)
{
    __shared__ float sA[16 * 132];
    __shared__ float sB[16 * 132];
    int tid = threadIdx.x;
    int m0 = blockIdx.y * 128, n0 = blockIdx.x * 128;
    int tm = tid & 15, tn = tid >> 4;
    int lr = tid >> 2, lk = (tid & 3) * 4;
    float acc[8][8];
#pragma unroll
    for (int i = 0; i < 8; i++)
#pragma unroll
        for (int j = 0; j < 8; j++) acc[i][j] = 0.f;

    for (int k0 = 0; k0 < K; k0 += 16) {
#pragma unroll
        for (int h = 0; h < 2; h++) {
            int m = lr + h * 64, gm = m0 + m, kb = k0 + lk;
            float4 av = make_float4(0.f, 0.f, 0.f, 0.f);
            if (gm < M) {
                if (kb + 3 < K) av = *(const float4*)(A + (size_t)gm * K + kb);
                else {
                    if (kb     < K) av.x = A[(size_t)gm * K + kb];
                    if (kb + 1 < K) av.y = A[(size_t)gm * K + kb + 1];
                    if (kb + 2 < K) av.z = A[(size_t)gm * K + kb + 2];
                }
            }
            sA[(lk + 0) * 132 + m] = av.x;
            sA[(lk + 1) * 132 + m] = av.y;
            sA[(lk + 2) * 132 + m] = av.z;
            sA[(lk + 3) * 132 + m] = av.w;

            int gn = n0 + m;
            float4 bv = make_float4(0.f, 0.f, 0.f, 0.f);
            if (gn < N) {
                if (kb + 3 < K) bv = *(const float4*)(B + (size_t)gn * K + kb);
                else {
                    if (kb     < K) bv.x = B[(size_t)gn * K + kb];
                    if (kb + 1 < K) bv.y = B[(size_t)gn * K + kb + 1];
                    if (kb + 2 < K) bv.z = B[(size_t)gn * K + kb + 2];
                }
            }
            sB[(lk + 0) * 132 + m] = bv.x;
            sB[(lk + 1) * 132 + m] = bv.y;
            sB[(lk + 2) * 132 + m] = bv.z;
            sB[(lk + 3) * 132 + m] = bv.w;
        }
        __syncthreads();
#pragma unroll
        for (int kk = 0; kk < 16; kk++) {
            float4 xa0 = *(const float4*)(sA + kk * 132 + tm * 4);
            float4 xa1 = *(const float4*)(sA + kk * 132 + 64 + tm * 4);
            float4 xb0 = *(const float4*)(sB + kk * 132 + tn * 4);
            float4 xb1 = *(const float4*)(sB + kk * 132 + 64 + tn * 4);
            float a[8] = {xa0.x, xa0.y, xa0.z, xa0.w, xa1.x, xa1.y, xa1.z, xa1.w};
            float bv[8] = {xb0.x, xb0.y, xb0.z, xb0.w, xb1.x, xb1.y, xb1.z, xb1.w};
#pragma unroll
            for (int i = 0; i < 8; i++)
#pragma unroll
                for (int j = 0; j < 8; j++) acc[i][j] += a[i] * bv[j];
        }
        __syncthreads();
    }
#pragma unroll
    for (int i = 0; i < 8; i++) {
        int m = m0 + ((i < 4) ? (tm * 4 + i) : (64 + tm * 4 + i - 4));
        if (m >= M) continue;
#pragma unroll
        for (int j = 0; j < 8; j++) {
            int n = n0 + ((j < 4) ? (tn * 4 + j) : (64 + tn * 4 + j - 4));
            if (n >= N) continue;
            float v = acc[i][j] + (bias ? bias[n] : 0.f);
            if (relu) v = fmaxf(v, 0.f);
            C[(size_t)m * N + n] = v;
        }
    }
}

// ---------------- persistent per-layer scan kernel ----------------
__global__ void __launch_bounds__(256, 1) persist_layer(
    const float* __restrict__ Hin, float* __restrict__ H1,
    const float* __restrict__ XIP,
    const float* __restrict__ wq, const float* __restrict__ wk,
    const float* __restrict__ gatb, int layer,
    const int* __restrict__ spk, const int* __restrict__ start,
    const float* __restrict__ bhh_c, const float* __restrict__ bih_p,
    const float* __restrict__ Geff, float* __restrict__ uT,
    float* __restrict__ G2T)
{
    extern __shared__ float dsm[];
    float* sWT = dsm;                 // [k*16 + r] transposed weights, 9600 f
    float* sU  = dsm + SWT_F;         // u copy [d*64+b], 38400 f; overlaid by partials

    __shared__ float s8[8];
    __shared__ float s_w0[64];
    __shared__ float s_w1[64];
    __shared__ float s_kdot[64];
    __shared__ float s_qd[64];
    __shared__ float s_bias[16];

    const int tid = threadIdx.x;
    const int cta = blockIdx.x;
    const int b = cta;
    const int n0 = cta * 16;
    const int wid = tid >> 5, lid = tid & 31;

    // transposed persistent weight slice
    for (int idx = tid; idx < SWT_F; idx += 256) {
        int k = idx >> 4, r = idx & 15;
        int n = n0 + r;
        sWT[idx] = (n < GEFFN) ? Geff[(size_t)n * 600 + k] : 0.f;
    }
    if (tid < 16) {
        int n = n0 + tid;
        float bv = 0.f;
        if (n < 900) bv = bhh_c[n];
        else if (n < 1800) bv = bih_p[n - 900];
        s_bias[tid] = bv;
    }

    // phase-B mapping: ks = warp (k-slice of 75), rg = row half, bg = batch group
    const int bg = tid & 15, rg = (tid >> 4) & 1, ks = tid >> 5;
    const unsigned suBase = (unsigned)__cvta_generic_to_shared(sU)
                          + (unsigned)((ks * 75 * 64 + bg * 4) * 4);
    const float4* src4 = (const float4*)uT;
    float4* dst4 = (float4*)sU;
    unsigned long long* sP = (unsigned long long*)sU;

    unsigned bar = 0;
    const float gb = gatb[layer];

    if (cta < 64) {
        for (int i = wid; i < 64; i += 8) {
            float p = 0.f;
            const float* hr = Hin + ((size_t)b * NSEQ + i) * HID;
            for (int j = lid; j < HID; j += 32) p += hr[j] * wq[j];
#pragma unroll
            for (int o = 16; o > 0; o >>= 1) p += __shfl_xor_sync(0xffffffffu, p, o);
            if (lid == 0) s_qd[i] = p + gb;
        }
        const float* xi = XIP + (size_t)b * NSEQ * 1800;
        const float* xp = xi + 900;
        const float* x0 = Hin + (size_t)b * NSEQ * HID;
        float* h1 = H1 + (size_t)b * NSEQ * HID;
        float kp = 0.f;
        for (int d = tid; d < HID; d += 256) {
            float r  = sigf(xi[d] + bhh_c[d]);
            float z  = sigf(xi[300 + d] + bhh_c[300 + d]);
            float nn = tanhfast(xi[600 + d] + r * bhh_c[600 + d]);
            float C0 = (1.f - z) * nn;
            float r2 = sigf(bih_p[d] + xp[d]);
            float z2 = sigf(bih_p[300 + d] + xp[300 + d]);
            float n2 = tanhfast(bih_p[600 + d] + r2 * xp[600 + d]);
            float P0 = (1.f - z2) * n2 + z2 * x0[d];
            float h = C0 + P0;
            h1[d] = h;
            kp += h * wk[d];
        }
        float kss = bsum(kp, s8);
        if (tid == 0) s_kdot[0] = kss;
    }
    __syncthreads();

    for (int i = 1; i <= 63; i++) {
        // ===== phase A (CTAs 0..63): GRU row i-1, attention -> uT =====
        if (cta < 64) {
            if (i >= 2) {
                int row = i - 1;
                const float* xi = XIP + ((size_t)b * NSEQ + row) * 1800;
                const float* xp = xi + 900;
                const float* q  = Hin + ((size_t)b * NSEQ + row) * HID;
                float* h1r = H1 + ((size_t)b * NSEQ + row) * HID;
                float kp = 0.f;
                for (int d = tid; d < HID; d += 256) {
                    float Md = __ldcg(G2T + (size_t)(1800 + d) * 64 + b);
                    float r  = sigf(xi[d]       + __ldcg(G2T + (size_t)d * 64 + b));
                    float z  = sigf(xi[300 + d] + __ldcg(G2T + (size_t)(300 + d) * 64 + b));
                    float nn = tanhfast(xi[600 + d] + r * __ldcg(G2T + (size_t)(600 + d) * 64 + b));
                    float Cc = (1.f - z) * nn + z * Md;
                    float r2 = sigf(__ldcg(G2T + (size_t)(900 + d) * 64 + b)  + xp[d]);
                    float z2 = sigf(__ldcg(G2T + (size_t)(1200 + d) * 64 + b) + xp[300 + d]);
                    float n2 = tanhfast(__ldcg(G2T + (size_t)(1500 + d) * 64 + b) + r2 * xp[600 + d]);
                    float Pp = (1.f - z2) * n2 + z2 * q[d];
                    float h = Cc + Pp;
                    h1r[d] = h;
                    kp += h * wk[d];
                }
                float kss = bsum(kp, s8);
                if (tid == 0) s_kdot[row] = kss;
                __syncthreads();
            }
            int st = start[b * NSEQ + i];
            int cnt = i - st;
            if (tid < 32) {
                int spki = spk[b * NSEQ + i];
                float qd = s_qd[i];
                float a1 = (tid < cnt)      ? qd + s_kdot[st + tid]      : -1e30f;
                float a2 = (tid + 32 < cnt) ? qd + s_kdot[st + tid + 32] : -1e30f;
                float m = fmaxf(a1, a2);
#pragma unroll
                for (int o = 16; o > 0; o >>= 1) m = fmaxf(m, __shfl_xor_sync(0xffffffffu, m, o));
                float e1 = (tid < cnt)      ? __expf(a1 - m) : 0.f;
                float e2 = (tid + 32 < cnt) ? __expf(a2 - m) : 0.f;
                float s = e1 + e2;
#pragma unroll
                for (int o = 16; o > 0; o >>= 1) s += __shfl_xor_sync(0xffffffffu, s, o);
                float inv = __fdividef(1.f, s);
                if (tid < cnt) {
                    float w = e1 * inv;
                    float smv = (spk[b * NSEQ + st + tid] == spki) ? 1.f : 0.f;
                    s_w0[tid] = w * smv;
                    s_w1[tid] = w * (1.f - smv);
                }
                if (tid + 32 < cnt) {
                    float w = e2 * inv;
                    float smv = (spk[b * NSEQ + st + tid + 32] == spki) ? 1.f : 0.f;
                    s_w0[tid + 32] = w * smv;
                    s_w1[tid + 32] = w * (1.f - smv);
                }
            }
            __syncthreads();
            for (int d = tid; d < 600; d += 256) {
                int ei = (d < 300) ? d : d - 300;
                const float* wt = (d < 300) ? s_w0 : s_w1;
                const float* base = H1 + ((size_t)b * NSEQ + st) * HID + ei;
                float acc = 0.f;
                for (int j = 0; j < cnt; j++)
                    acc += wt[j] * base[j * HID];
                __stcg(uT + d * 64 + b, acc);
            }
        }
        gbar(++bar, tid, cta);   // u ready

        // ===== stage uT -> sU (bulk, deep MLP) =====
        for (int idx = tid; idx < SU_F / 4; idx += 256)
            dst4[idx] = __ldcg(src4 + idx);
        __syncthreads();

        // ===== phase B main: 8 rows x 4 batches x 75-k slice per thread =====
        unsigned long long a01[8], a23[8];
#pragma unroll
        for (int r = 0; r < 8; r++) { a01[r] = 0ull; a23[r] = 0ull; }
        {
            unsigned suA = suBase;
#pragma unroll 5
            for (int kk = 0; kk < 75; kk++) {
                unsigned long long u01, u23;
                asm volatile("ld.shared.v2.u64 {%0,%1},[%2];"
                             : "=l"(u01), "=l"(u23) : "r"(suA));
                suA += 256u;
                const float* wr = sWT + (ks * 75 + kk) * 16 + rg * 8;
                float4 w0 = *(const float4*)wr;
                float4 w1 = *(const float4*)(wr + 4);
                float wf[8] = {w0.x, w0.y, w0.z, w0.w, w1.x, w1.y, w1.z, w1.w};
#pragma unroll
                for (int r = 0; r < 8; r++) {
                    unsigned long long wp;
                    asm("mov.b64 %0,{%1,%1};" : "=l"(wp) : "f"(wf[r]));
                    asm("fma.rn.f32x2 %0,%1,%2,%0;" : "+l"(a01[r]) : "l"(u01), "l"(wp));
                    asm("fma.rn.f32x2 %0,%1,%2,%0;" : "+l"(a23[r]) : "l"(u23), "l"(wp));
                }
            }
        }
        __syncthreads();   // done reading sU; safe to overlay partials
        // store k-partials
#pragma unroll
        for (int r = 0; r < 8; r++) {
            int row = rg * 8 + r;
            sP[((ks * 16 + row) * 16 + bg) * 2 + 0] = a01[r];
            sP[((ks * 16 + row) * 16 + bg) * 2 + 1] = a23[r];
        }
        __syncthreads();
        // reduce over 8 k-slices: 512 u64 outputs, 2 per thread
        {
#pragma unroll
            for (int t = 0; t < 2; t++) {
                int o = tid * 2 + t;
                int row = o >> 5, rem = o & 31;
                int bg2 = rem >> 1, p = rem & 1;
                unsigned long long s = sP[(row * 16 + bg2) * 2 + p];
#pragma unroll
                for (int k2 = 1; k2 < 8; k2++) {
                    unsigned long long v = sP[((k2 * 16 + row) * 16 + bg2) * 2 + p];
                    asm("add.rn.f32x2 %0,%1,%2;" : "=l"(s) : "l"(s), "l"(v));
                }
                unsigned long long bp;
                asm("mov.b64 %0,{%1,%1};" : "=l"(bp) : "f"(s_bias[row]));
                asm("add.rn.f32x2 %0,%1,%2;" : "=l"(s) : "l"(s), "l"(bp));
                int n = n0 + row;
                if (n < GEFFN)
                    *(unsigned long long*)(G2T + (size_t)n * 64 + bg2 * 4 + p * 2) = s;
            }
        }
        gbar(++bar, tid, cta);   // G2T ready
    }

    // final GRU update: row 63
    if (cta < 64) {
        int row = 63;
        const float* xi = XIP + ((size_t)b * NSEQ + row) * 1800;
        const float* xp = xi + 900;
        const float* q  = Hin + ((size_t)b * NSEQ + row) * HID;
        float* h1r = H1 + ((size_t)b * NSEQ + row) * HID;
        for (int d = tid; d < HID; d += 256) {
            float Md = __ldcg(G2T + (size_t)(1800 + d) * 64 + b);
            float r  = sigf(xi[d]       + __ldcg(G2T + (size_t)d * 64 + b));
            float z  = sigf(xi[300 + d] + __ldcg(G2T + (size_t)(300 + d) * 64 + b));
            float nn = tanhfast(xi[600 + d] + r * __ldcg(G2T + (size_t)(600 + d) * 64 + b));
            float Cc = (1.f - z) * nn + z * Md;
            float r2 = sigf(__ldcg(G2T + (size_t)(900 + d) * 64 + b)  + xp[d]);
            float z2 = sigf(__ldcg(G2T + (size_t)(1200 + d) * 64 + b) + xp[300 + d]);
            float n2 = tanhfast(__ldcg(G2T + (size_t)(1500 + d) * 64 + b) + r2 * xp[600 + d]);
            float Pp = (1.f - z2) * n2 + z2 * q[d];
            h1r[d] = Cc + Pp;
        }
    }
}

__global__ void k_concat(const float* __restrict__ feat) {
    int r = blockIdx.x;
    for (int c = threadIdx.x; c < KCAT; c += blockDim.x) {
        float v;
        if (c < 1500) {
            int seg = c / 300, off = c - seg * 300;
            v = g_H[seg * HSZ + r * HID + off];
        } else {
            v = feat[r * EMB + (c - 1500)];
        }
        g_Hcat[r * KCAT + c] = v;
    }
}

extern "C" void kernel_launch(void* const* d_in, const int* in_sizes, int n_in,
                              void* d_out, int out_size) {
    const float* features = (const float*)d_in[0];
    const int*   speakers = (const int*)d_in[1];
    const float* w_in   = (const float*)d_in[2];
    const float* b_in   = (const float*)d_in[3];
    const float* gat_wq = (const float*)d_in[4];
    const float* gat_wk = (const float*)d_in[5];
    const float* gat_b  = (const float*)d_in[6];
    const float* wr0    = (const float*)d_in[7];
    const float* wr1    = (const float*)d_in[8];
    const float* wih_c  = (const float*)d_in[9];
    const float* whh_c  = (const float*)d_in[10];
    const float* bih_c  = (const float*)d_in[11];
    const float* bhh_c  = (const float*)d_in[12];
    const float* wih_p  = (const float*)d_in[13];
    const float* whh_p  = (const float*)d_in[14];
    const float* bih_p  = (const float*)d_in[15];
    const float* bhh_p  = (const float*)d_in[16];
    const float* w1 = (const float*)d_in[17];
    const float* b1 = (const float*)d_in[18];
    const float* w2 = (const float*)d_in[19];
    const float* b2 = (const float*)d_in[20];
    const float* w3 = (const float*)d_in[21];
    const float* b3 = (const float*)d_in[22];

    float *H, *XIPp, *WXp, *bXp, *Geffp, *uTp, *G2Tp, *Hcatp, *h1p, *h2p;
    int *startp;
    cudaGetSymbolAddress((void**)&H,     g_H);
    cudaGetSymbolAddress((void**)&XIPp,  g_XIP);
    cudaGetSymbolAddress((void**)&WXp,   g_WX);
    cudaGetSymbolAddress((void**)&bXp,   g_bX);
    cudaGetSymbolAddress((void**)&Geffp, g_Geff);
    cudaGetSymbolAddress((void**)&uTp,   g_uT);
    cudaGetSymbolAddress((void**)&G2Tp,  g_G2T);
    cudaGetSymbolAddress((void**)&startp,g_start);
    cudaGetSymbolAddress((void**)&Hcatp, g_Hcat);
    cudaGetSymbolAddress((void**)&h1p,   g_h1);
    cudaGetSymbolAddress((void**)&h2p,   g_h2);

    cudaFuncSetAttribute(persist_layer,
                         cudaFuncAttributeMaxDynamicSharedMemorySize,
                         DSMEM_F * 4);

    const int MROWS = BATCH * NSEQ;
    const int PREP_GRID = EW_BLOCKS + GEFF_TX * GEFF_TY;

    for (int l = 0; l < 4; l++) {
        k_prep2<<<PREP_GRID, 256>>>(
            speakers,
            wih_c + l * G3 * HID, whh_p + l * G3 * HID,
            bih_c + l * G3, bhh_p + l * G3,
            whh_c + l * G3 * HID, wih_p + l * G3 * HID,
            wr0 + l * HID * HID, wr1 + l * HID * HID);

        if (l == 0) {
            gemm8x8<<<dim3((HID + 127) / 128, MROWS / 128), 256>>>(
                features, w_in, b_in, H, MROWS, HID, EMB, 1);
        }
        const float* Hin = H + l * HSZ;
        float* H1 = H + (l + 1) * HSZ;

        gemm8x8<<<dim3((1800 + 127) / 128, MROWS / 128), 256>>>(
            Hin, WXp, bXp, XIPp, MROWS, 1800, HID, 0);

        persist_layer<<<NCTA, 256, DSMEM_F * 4>>>(
            Hin, H1, XIPp, gat_wq + l * HID, gat_wk + l * HID, gat_b, l,
            speakers, startp, bhh_c + l * G3, bih_p + l * G3, Geffp, uTp, G2Tp);
    }

    k_concat<<<MROWS, 256>>>(features);

    gemm8x8<<<dim3((HID + 127) / 128, MROWS / 128), 256>>>(
        Hcatp, w1, b1, h1p, MROWS, HID, KCAT, 1);
    gemm8x8<<<dim3((HID + 127) / 128, MROWS / 128), 256>>>(
        h1p, w2, b2, h2p, MROWS, HID, HID, 1);
    gemm8x8<<<dim3(1, MROWS / 128), 256>>>(
        h2p, w3, b3, (float*)d_out, MROWS, 7, HID, 0);
}

// round 12
// speedup vs baseline: 1.4059x; 1.0355x over previous
#include <cuda_runtime.h>
#include <math.h>

#define HID   300
#define G3    900
#define NSEQ  64
#define BATCH 64
#define EMB   1024
#define KCAT  2524
#define HSZ   (BATCH*NSEQ*HID)
#define NCTA  132
#define GEFFN 2100
#define SWT_F 9600
#define SU_F  38400
#define DSMEM_F (SWT_F + SU_F)      /* 48000 floats = 192000 B */
#define EW_BLOCKS 704
#define GEFF_TX 10
#define GEFF_TY 29

__device__ float g_H[5 * HSZ];
__device__ float g_XIP[BATCH * NSEQ * 1800];   // [XI | XP] per row
__device__ float g_WX[1800 * HID];             // [wih_c ; whh_p]
__device__ float g_bX[1800];                   // [bih_c ; bhh_p]
__device__ float g_Geff[GEFFN * 600];          // rows 0..1799: WG@Wr2, 1800..2099: Wr2
__device__ float g_uT[600 * BATCH];            // uT[d*64 + b]
__device__ float g_G2T[2112 * BATCH];          // transposed: G2T[n*64 + b]
__device__ int   g_start[BATCH * NSEQ];
__device__ float g_Hcat[BATCH * NSEQ * KCAT];
__device__ float g_h1[BATCH * NSEQ * HID];
__device__ float g_h2[BATCH * NSEQ * HID];

__device__ volatile unsigned g_ucnt;   // A arrivals (u ready), 64/step
__device__ volatile unsigned g_gcnt;   // all arrivals (G2 ready), 132/step

__device__ __forceinline__ float sigf(float x) {
    return __fdividef(1.f, 1.f + __expf(-x));
}
__device__ __forceinline__ float tanhfast(float x) {
    return __fdividef(2.f, 1.f + __expf(-2.f * x)) - 1.f;
}

__device__ __forceinline__ float bsum(float v, float* s8) {
    int tid = threadIdx.x;
#pragma unroll
    for (int o = 16; o > 0; o >>= 1) v += __shfl_xor_sync(0xffffffffu, v, o);
    if ((tid & 31) == 0) s8[tid >> 5] = v;
    __syncthreads();
    if (tid < 32) {
        float t = (tid < 8) ? s8[tid] : 0.f;
#pragma unroll
        for (int o = 4; o > 0; o >>= 1) t += __shfl_xor_sync(0xffffffffu, t, o);
        if (tid == 0) s8[0] = t;
    }
    __syncthreads();
    float r = s8[0];
    __syncthreads();
    return r;
}

__device__ __forceinline__ void red_inc(volatile unsigned* p) {
    asm volatile("red.global.add.u32 [%0], %1;" :: "l"((const void*)p), "r"(1u) : "memory");
}
// single-thread poll: counter >= t, then acquire
__device__ __forceinline__ void waitge(volatile unsigned* p, unsigned t) {
    while (*p < t) { }
    asm volatile("fence.acq_rel.gpu;" ::: "memory");
}

// ---- merged prep: starts + WX/bX/Geff-bottom elementwise + Geff-top GEMM ----
__global__ void __launch_bounds__(256) k_prep2(
    const int* __restrict__ spk,
    const float* __restrict__ wih_c, const float* __restrict__ whh_p,
    const float* __restrict__ bih_c, const float* __restrict__ bhh_p,
    const float* __restrict__ whh_c, const float* __restrict__ wih_p,
    const float* __restrict__ wr0,   const float* __restrict__ wr1)
{
    int bid = blockIdx.x;
    if (bid < EW_BLOCKS) {
        for (int idx = bid * 256 + threadIdx.x; idx < 1800 * 300; idx += EW_BLOCKS * 256) {
            int n = idx / 300, d = idx - n * 300;
            g_WX[idx] = (n < 900) ? wih_c[n * 300 + d] : whh_p[(n - 900) * 300 + d];
            if (idx < 300 * 600) {
                int d2 = idx / 600, e = idx - d2 * 600;
                g_Geff[(1800 + d2) * 600 + e] =
                    (e < 300) ? wr0[d2 * 300 + e] : wr1[d2 * 300 + (e - 300)];
            }
            if (idx < 1800) g_bX[idx] = (idx < 900) ? bih_c[idx] : bhh_p[idx - 900];
            if (idx < 4096) {
                int b = idx >> 6, i = idx & 63;
                int s = spk[b * NSEQ + i];
                int last = -1;
                for (int j = 0; j < i; j++)
                    if (spk[b * NSEQ + j] == s) last = j;
                g_start[b * NSEQ + i] = last > 0 ? last : 0;
            }
            if (idx == 0) { g_ucnt = 0; g_gcnt = 0; }
        }
        return;
    }
    int gb2 = bid - EW_BLOCKS;
    int n0 = (gb2 / GEFF_TX) * 64, e0 = (gb2 % GEFF_TX) * 64;
    __shared__ float sA[16][65];
    __shared__ float sB[16][65];
    int tid = threadIdx.x;
    int tm = tid >> 4, tn = tid & 15;
    int lr = tid >> 2, lk = (tid & 3) * 4;
    float acc[4][4];
#pragma unroll
    for (int i = 0; i < 4; i++)
#pragma unroll
        for (int j = 0; j < 4; j++) acc[i][j] = 0.f;
    for (int k0 = 0; k0 < 300; k0 += 16) {
#pragma unroll
        for (int q = 0; q < 4; q++) {
            int k = k0 + lk + q;
            int n = n0 + lr;
            float av = 0.f;
            if (k < 300 && n < 1800)
                av = (n < 900) ? whh_c[n * 300 + k] : wih_p[(n - 900) * 300 + k];
            sA[lk + q][lr] = av;
            int e = e0 + lr;
            float bv = 0.f;
            if (k < 300 && e < 600)
                bv = (e < 300) ? wr0[k * 300 + e] : wr1[k * 300 + (e - 300)];
            sB[lk + q][lr] = bv;
        }
        __syncthreads();
#pragma unroll
        for (int kk = 0; kk < 16; kk++) {
            float a[4], bv[4];
#pragma unroll
            for (int i = 0; i < 4; i++) { a[i] = sA[kk][tm * 4 + i]; bv[i] = sB[kk][tn * 4 + i]; }
#pragma unroll
            for (int i = 0; i < 4; i++)
#pragma unroll
                for (int j = 0; j < 4; j++) acc[i][j] += a[i] * bv[j];
        }
        __syncthreads();
    }
#pragma unroll
    for (int i = 0; i < 4; i++) {
        int n = n0 + tm * 4 + i;
        if (n >= 1800) continue;
#pragma unroll
        for (int j = 0; j < 4; j++) {
            int e = e0 + tn * 4 + j;
            if (e >= 600) continue;
            g_Geff[(size_t)n * 600 + e] = acc[i][j];
        }
    }
}

// ---- dense GEMM: C=A@B^T+bias (opt relu). BM=128,BN=128,BK=16, 8x8, f32x2 ----
__global__ void __launch_bounds__(256, 2) gemm8x8(
    const float* __restrict__ A, const float* __restrict__ B,
    const float* __restrict__ bias, float* __restrict__ C,
    int M, int N, int K, int relu)
{
    __shared__ float sA[16 * 132];
    __shared__ float sB[16 * 132];
    int tid = threadIdx.x;
    int m0 = blockIdx.y * 128, n0 = blockIdx.x * 128;
    int tm = tid & 15, tn = tid >> 4;
    int lr = tid >> 2, lk = (tid & 3) * 4;
    unsigned long long acc2[8][4];
#pragma unroll
    for (int i = 0; i < 8; i++)
#pragma unroll
        for (int j = 0; j < 4; j++) acc2[i][j] = 0ull;

    for (int k0 = 0; k0 < K; k0 += 16) {
#pragma unroll
        for (int h = 0; h < 2; h++) {
            int m = lr + h * 64, gm = m0 + m, kb = k0 + lk;
            float4 av = make_float4(0.f, 0.f, 0.f, 0.f);
            if (gm < M) {
                if (kb + 3 < K) av = *(const float4*)(A + (size_t)gm * K + kb);
                else {
                    if (kb     < K) av.x = A[(size_t)gm * K + kb];
                    if (kb + 1 < K) av.y = A[(size_t)gm * K + kb + 1];
                    if (kb + 2 < K) av.z = A[(size_t)gm * K + kb + 2];
                }
            }
            sA[(lk + 0) * 132 + m] = av.x;
            sA[(lk + 1) * 132 + m] = av.y;
            sA[(lk + 2) * 132 + m] = av.z;
            sA[(lk + 3) * 132 + m] = av.w;

            int gn = n0 + m;
            float4 bv = make_float4(0.f, 0.f, 0.f, 0.f);
            if (gn < N) {
                if (kb + 3 < K) bv = *(const float4*)(B + (size_t)gn * K + kb);
                else {
                    if (kb     < K) bv.x = B[(size_t)gn * K + kb];
                    if (kb + 1 < K) bv.y = B[(size_t)gn * K + kb + 1];
                    if (kb + 2 < K) bv.z = B[(size_t)gn * K + kb + 2];
                }
            }
            sB[(lk + 0) * 132 + m] = bv.x;
            sB[(lk + 1) * 132 + m] = bv.y;
            sB[(lk + 2) * 132 + m] = bv.z;
            sB[(lk + 3) * 132 + m] = bv.w;
        }
        __syncthreads();
#pragma unroll
        for (int kk = 0; kk < 16; kk++) {
            float4 xa0 = *(const float4*)(sA + kk * 132 + tm * 4);
            float4 xa1 = *(const float4*)(sA + kk * 132 + 64 + tm * 4);
            float4 xb0 = *(const float4*)(sB + kk * 132 + tn * 4);
            float4 xb1 = *(const float4*)(sB + kk * 132 + 64 + tn * 4);
            unsigned long long bp[4];
            asm("mov.b64 %0,{%1,%2};" : "=l"(bp[0]) : "f"(xb0.x), "f"(xb0.y));
            asm("mov.b64 %0,{%1,%2};" : "=l"(bp[1]) : "f"(xb0.z), "f"(xb0.w));
            asm("mov.b64 %0,{%1,%2};" : "=l"(bp[2]) : "f"(xb1.x), "f"(xb1.y));
            asm("mov.b64 %0,{%1,%2};" : "=l"(bp[3]) : "f"(xb1.z), "f"(xb1.w));
            float a[8] = {xa0.x, xa0.y, xa0.z, xa0.w, xa1.x, xa1.y, xa1.z, xa1.w};
#pragma unroll
            for (int i = 0; i < 8; i++) {
                unsigned long long ap;
                asm("mov.b64 %0,{%1,%1};" : "=l"(ap) : "f"(a[i]));
#pragma unroll
                for (int j = 0; j < 4; j++)
                    asm("fma.rn.f32x2 %0,%1,%2,%0;" : "+l"(acc2[i][j]) : "l"(ap), "l"(bp[j]));
            }
        }
        __syncthreads();
    }
#pragma unroll
    for (int i = 0; i < 8; i++) {
        int m = m0 + ((i < 4) ? (tm * 4 + i) : (64 + tm * 4 + i - 4));
        if (m >= M) continue;
#pragma unroll
        for (int j = 0; j < 8; j++) {
            int n = n0 + ((j < 4) ? (tn * 4 + j) : (64 + tn * 4 + j - 4));
            if (n >= N) continue;
            float lo, hi;
            asm("mov.b64 {%0,%1},%2;" : "=f"(lo), "=f"(hi) : "l"(acc2[i][j >> 1]));
            float v = ((j & 1) ? hi : lo) + (bias ? bias[n] : 0.f);
            if (relu) v = fmaxf(v, 0.f);
            C[(size_t)m * N + n] = v;
        }
    }
}

// ---------------- persistent per-layer scan kernel ----------------
__global__ void __launch_bounds__(256, 1) persist_layer(
    const float* __restrict__ Hin, float* __restrict__ H1,
    const float* __restrict__ XIP,
    const float* __restrict__ wq, const float* __restrict__ wk,
    const float* __restrict__ gatb, int layer,
    const int* __restrict__ spk, const int* __restrict__ start,
    const float* __restrict__ bhh_c, const float* __restrict__ bih_p,
    const float* __restrict__ Geff, float* __restrict__ uT,
    float* __restrict__ G2T)
{
    extern __shared__ float dsm[];
    float* sWT = dsm;                 // [k*16 + r] transposed weights, 9600 f
    float* sU  = dsm + SWT_F;         // u copy [d*64+b], 38400 f; overlaid by partials

    __shared__ float s8[8];
    __shared__ float s_w0[64];
    __shared__ float s_w1[64];
    __shared__ float s_kdot[64];
    __shared__ float s_qd[64];
    __shared__ float s_bias[16];

    const int tid = threadIdx.x;
    const int cta = blockIdx.x;
    const int b = cta;
    const int n0 = cta * 16;
    const int wid = tid >> 5, lid = tid & 31;

    for (int idx = tid; idx < SWT_F; idx += 256) {
        int k = idx >> 4, r = idx & 15;
        int n = n0 + r;
        sWT[idx] = (n < GEFFN) ? Geff[(size_t)n * 600 + k] : 0.f;
    }
    if (tid < 16) {
        int n = n0 + tid;
        float bv = 0.f;
        if (n < 900) bv = bhh_c[n];
        else if (n < 1800) bv = bih_p[n - 900];
        s_bias[tid] = bv;
    }

    const int bg = tid & 15, rg = (tid >> 4) & 1, ks = tid >> 5;
    const unsigned suBase = (unsigned)__cvta_generic_to_shared(sU)
                          + (unsigned)((ks * 75 * 64 + bg * 4) * 4);
    const float4* src4 = (const float4*)uT;
    float4* dst4 = (float4*)sU;
    unsigned long long* sP = (unsigned long long*)sU;

    const float gb = gatb[layer];

    if (cta < 64) {
        for (int i = wid; i < 64; i += 8) {
            float p = 0.f;
            const float* hr = Hin + ((size_t)b * NSEQ + i) * HID;
            for (int j = lid; j < HID; j += 32) p += hr[j] * wq[j];
#pragma unroll
            for (int o = 16; o > 0; o >>= 1) p += __shfl_xor_sync(0xffffffffu, p, o);
            if (lid == 0) s_qd[i] = p + gb;
        }
        const float* xi = XIP + (size_t)b * NSEQ * 1800;
        const float* xp = xi + 900;
        const float* x0 = Hin + (size_t)b * NSEQ * HID;
        float* h1 = H1 + (size_t)b * NSEQ * HID;
        float kp = 0.f;
        for (int d = tid; d < HID; d += 256) {
            float r  = sigf(xi[d] + bhh_c[d]);
            float z  = sigf(xi[300 + d] + bhh_c[300 + d]);
            float nn = tanhfast(xi[600 + d] + r * bhh_c[600 + d]);
            float C0 = (1.f - z) * nn;
            float r2 = sigf(bih_p[d] + xp[d]);
            float z2 = sigf(bih_p[300 + d] + xp[300 + d]);
            float n2 = tanhfast(bih_p[600 + d] + r2 * xp[600 + d]);
            float P0 = (1.f - z2) * n2 + z2 * x0[d];
            float h = C0 + P0;
            h1[d] = h;
            kp += h * wk[d];
        }
        float kss = bsum(kp, s8);
        if (tid == 0) s_kdot[0] = kss;
    }
    __syncthreads();

    for (int i = 1; i <= 63; i++) {
        // ===== phase A (CTAs 0..63): GRU row i-1, attention -> uT(i) =====
        if (cta < 64) {
            if (i >= 2) {
                if (tid == 0) waitge(&g_gcnt, NCTA * (unsigned)(i - 1));
                __syncthreads();
                int row = i - 1;
                const float* xi = XIP + ((size_t)b * NSEQ + row) * 1800;
                const float* xp = xi + 900;
                const float* q  = Hin + ((size_t)b * NSEQ + row) * HID;
                float* h1r = H1 + ((size_t)b * NSEQ + row) * HID;
                float kp = 0.f;
                for (int d = tid; d < HID; d += 256) {
                    float Md = __ldcg(G2T + (size_t)(1800 + d) * 64 + b);
                    float r  = sigf(xi[d]       + __ldcg(G2T + (size_t)d * 64 + b));
                    float z  = sigf(xi[300 + d] + __ldcg(G2T + (size_t)(300 + d) * 64 + b));
                    float nn = tanhfast(xi[600 + d] + r * __ldcg(G2T + (size_t)(600 + d) * 64 + b));
                    float Cc = (1.f - z) * nn + z * Md;
                    float r2 = sigf(__ldcg(G2T + (size_t)(900 + d) * 64 + b)  + xp[d]);
                    float z2 = sigf(__ldcg(G2T + (size_t)(1200 + d) * 64 + b) + xp[300 + d]);
                    float n2 = tanhfast(__ldcg(G2T + (size_t)(1500 + d) * 64 + b) + r2 * xp[600 + d]);
                    float Pp = (1.f - z2) * n2 + z2 * q[d];
                    float h = Cc + Pp;
                    h1r[d] = h;
                    kp += h * wk[d];
                }
                float kss = bsum(kp, s8);
                if (tid == 0) s_kdot[row] = kss;
                __syncthreads();
            }
            int st = start[b * NSEQ + i];
            int cnt = i - st;
            if (tid < 32) {
                int spki = spk[b * NSEQ + i];
                float qd = s_qd[i];
                float a1 = (tid < cnt)      ? qd + s_kdot[st + tid]      : -1e30f;
                float a2 = (tid + 32 < cnt) ? qd + s_kdot[st + tid + 32] : -1e30f;
                float m = fmaxf(a1, a2);
#pragma unroll
                for (int o = 16; o > 0; o >>= 1) m = fmaxf(m, __shfl_xor_sync(0xffffffffu, m, o));
                float e1 = (tid < cnt)      ? __expf(a1 - m) : 0.f;
                float e2 = (tid + 32 < cnt) ? __expf(a2 - m) : 0.f;
                float s = e1 + e2;
#pragma unroll
                for (int o = 16; o > 0; o >>= 1) s += __shfl_xor_sync(0xffffffffu, s, o);
                float inv = __fdividef(1.f, s);
                if (tid < cnt) {
                    float w = e1 * inv;
                    float smv = (spk[b * NSEQ + st + tid] == spki) ? 1.f : 0.f;
                    s_w0[tid] = w * smv;
                    s_w1[tid] = w * (1.f - smv);
                }
                if (tid + 32 < cnt) {
                    float w = e2 * inv;
                    float smv = (spk[b * NSEQ + st + tid + 32] == spki) ? 1.f : 0.f;
                    s_w0[tid + 32] = w * smv;
                    s_w1[tid + 32] = w * (1.f - smv);
                }
            }
            __syncthreads();
            for (int d = tid; d < 600; d += 256) {
                int ei = (d < 300) ? d : d - 300;
                const float* wt = (d < 300) ? s_w0 : s_w1;
                const float* base = H1 + ((size_t)b * NSEQ + st) * HID + ei;
                float acc = 0.f;
                for (int j = 0; j < cnt; j++)
                    acc += wt[j] * base[j * HID];
                __stcg(uT + d * 64 + b, acc);
            }
            __threadfence();
            __syncthreads();
            if (tid == 0) red_inc(&g_ucnt);
        }
        // ===== all CTAs: wait u(i), stage, B =====
        if (tid == 0) waitge(&g_ucnt, 64u * (unsigned)i);
        __syncthreads();

        for (int idx = tid; idx < SU_F / 4; idx += 256)
            dst4[idx] = __ldcg(src4 + idx);
        __syncthreads();

        unsigned long long a01[8], a23[8];
#pragma unroll
        for (int r = 0; r < 8; r++) { a01[r] = 0ull; a23[r] = 0ull; }
        {
            unsigned suA = suBase;
#pragma unroll 5
            for (int kk = 0; kk < 75; kk++) {
                unsigned long long u01, u23;
                asm volatile("ld.shared.v2.u64 {%0,%1},[%2];"
                             : "=l"(u01), "=l"(u23) : "r"(suA));
                suA += 256u;
                const float* wr = sWT + (ks * 75 + kk) * 16 + rg * 8;
                float4 w0 = *(const float4*)wr;
                float4 w1 = *(const float4*)(wr + 4);
                float wf[8] = {w0.x, w0.y, w0.z, w0.w, w1.x, w1.y, w1.z, w1.w};
#pragma unroll
                for (int r = 0; r < 8; r++) {
                    unsigned long long wp;
                    asm("mov.b64 %0,{%1,%1};" : "=l"(wp) : "f"(wf[r]));
                    asm("fma.rn.f32x2 %0,%1,%2,%0;" : "+l"(a01[r]) : "l"(u01), "l"(wp));
                    asm("fma.rn.f32x2 %0,%1,%2,%0;" : "+l"(a23[r]) : "l"(u23), "l"(wp));
                }
            }
        }
        __syncthreads();
#pragma unroll
        for (int r = 0; r < 8; r++) {
            int row = rg * 8 + r;
            sP[((ks * 16 + row) * 16 + bg) * 2 + 0] = a01[r];
            sP[((ks * 16 + row) * 16 + bg) * 2 + 1] = a23[r];
        }
        __syncthreads();
        {
#pragma unroll
            for (int t = 0; t < 2; t++) {
                int o = tid * 2 + t;
                int row = o >> 5, rem = o & 31;
                int bg2 = rem >> 1, p = rem & 1;
                unsigned long long s = sP[(row * 16 + bg2) * 2 + p];
#pragma unroll
                for (int k2 = 1; k2 < 8; k2++) {
                    unsigned long long v = sP[((k2 * 16 + row) * 16 + bg2) * 2 + p];
                    asm("add.rn.f32x2 %0,%1,%2;" : "=l"(s) : "l"(s), "l"(v));
                }
                unsigned long long bp;
                asm("mov.b64 %0,{%1,%1};" : "=l"(bp) : "f"(s_bias[row]));
                asm("add.rn.f32x2 %0,%1,%2;" : "=l"(s) : "l"(s), "l"(bp));
                int n = n0 + row;
                if (n < GEFFN)
                    *(unsigned long long*)(G2T + (size_t)n * 64 + bg2 * 4 + p * 2) = s;
            }
        }
        __threadfence();
        __syncthreads();
        if (tid == 0) red_inc(&g_gcnt);
    }

    // final GRU update: row 63
    if (cta < 64) {
        if (tid == 0) waitge(&g_gcnt, NCTA * 63u);
        __syncthreads();
        int row = 63;
        const float* xi = XIP + ((size_t)b * NSEQ + row) * 1800;
        const float* xp = xi + 900;
        const float* q  = Hin + ((size_t)b * NSEQ + row) * HID;
        float* h1r = H1 + ((size_t)b * NSEQ + row) * HID;
        for (int d = tid; d < HID; d += 256) {
            float Md = __ldcg(G2T + (size_t)(1800 + d) * 64 + b);
            float r  = sigf(xi[d]       + __ldcg(G2T + (size_t)d * 64 + b));
            float z  = sigf(xi[300 + d] + __ldcg(G2T + (size_t)(300 + d) * 64 + b));
            float nn = tanhfast(xi[600 + d] + r * __ldcg(G2T + (size_t)(600 + d) * 64 + b));
            float Cc = (1.f - z) * nn + z * Md;
            float r2 = sigf(__ldcg(G2T + (size_t)(900 + d) * 64 + b)  + xp[d]);
            float z2 = sigf(__ldcg(G2T + (size_t)(1200 + d) * 64 + b) + xp[300 + d]);
            float n2 = tanhfast(__ldcg(G2T + (size_t)(1500 + d) * 64 + b) + r2 * xp[600 + d]);
            float Pp = (1.f - z2) * n2 + z2 * q[d];
            h1r[d] = Cc + Pp;
        }
    }
}

__global__ void k_concat(const float* __restrict__ feat) {
    int r = blockIdx.x;
    for (int c = threadIdx.x; c < KCAT; c += blockDim.x) {
        float v;
        if (c < 1500) {
            int seg = c / 300, off = c - seg * 300;
            v = g_H[seg * HSZ + r * HID + off];
        } else {
            v = feat[r * EMB + (c - 1500)];
        }
        g_Hcat[r * KCAT + c] = v;
    }
}

extern "C" void kernel_launch(void* const* d_in, const int* in_sizes, int n_in,
                              void* d_out, int out_size) {
    const float* features = (const float*)d_in[0];
    const int*   speakers = (const int*)d_in[1];
    const float* w_in   = (const float*)d_in[2];
    const float* b_in   = (const float*)d_in[3];
    const float* gat_wq = (const float*)d_in[4];
    const float* gat_wk = (const float*)d_in[5];
    const float* gat_b  = (const float*)d_in[6];
    const float* wr0    = (const float*)d_in[7];
    const float* wr1    = (const float*)d_in[8];
    const float* wih_c  = (const float*)d_in[9];
    const float* whh_c  = (const float*)d_in[10];
    const float* bih_c  = (const float*)d_in[11];
    const float* bhh_c  = (const float*)d_in[12];
    const float* wih_p  = (const float*)d_in[13];
    const float* whh_p  = (const float*)d_in[14];
    const float* bih_p  = (const float*)d_in[15];
    const float* bhh_p  = (const float*)d_in[16];
    const float* w1 = (const float*)d_in[17];
    const float* b1 = (const float*)d_in[18];
    const float* w2 = (const float*)d_in[19];
    const float* b2 = (const float*)d_in[20];
    const float* w3 = (const float*)d_in[21];
    const float* b3 = (const float*)d_in[22];

    float *H, *XIPp, *WXp, *bXp, *Geffp, *uTp, *G2Tp, *Hcatp, *h1p, *h2p;
    int *startp;
    cudaGetSymbolAddress((void**)&H,     g_H);
    cudaGetSymbolAddress((void**)&XIPp,  g_XIP);
    cudaGetSymbolAddress((void**)&WXp,   g_WX);
    cudaGetSymbolAddress((void**)&bXp,   g_bX);
    cudaGetSymbolAddress((void**)&Geffp, g_Geff);
    cudaGetSymbolAddress((void**)&uTp,   g_uT);
    cudaGetSymbolAddress((void**)&G2Tp,  g_G2T);
    cudaGetSymbolAddress((void**)&startp,g_start);
    cudaGetSymbolAddress((void**)&Hcatp, g_Hcat);
    cudaGetSymbolAddress((void**)&h1p,   g_h1);
    cudaGetSymbolAddress((void**)&h2p,   g_h2);

    cudaFuncSetAttribute(persist_layer,
                         cudaFuncAttributeMaxDynamicSharedMemorySize,
                         DSMEM_F * 4);

    const int MROWS = BATCH * NSEQ;
    const int PREP_GRID = EW_BLOCKS + GEFF_TX * GEFF_TY;

    for (int l = 0; l < 4; l++) {
        k_prep2<<<PREP_GRID, 256>>>(
            speakers,
            wih_c + l * G3 * HID, whh_p + l * G3 * HID,
            bih_c + l * G3, bhh_p + l * G3,
            whh_c + l * G3 * HID, wih_p + l * G3 * HID,
            wr0 + l * HID * HID, wr1 + l * HID * HID);

        if (l == 0) {
            gemm8x8<<<dim3((HID + 127) / 128, MROWS / 128), 256>>>(
                features, w_in, b_in, H, MROWS, HID, EMB, 1);
        }
        const float* Hin = H + l * HSZ;
        float* H1 = H + (l + 1) * HSZ;

        gemm8x8<<<dim3((1800 + 127) / 128, MROWS / 128), 256>>>(
            Hin, WXp, bXp, XIPp, MROWS, 1800, HID, 0);

        persist_layer<<<NCTA, 256, DSMEM_F * 4>>>(
            Hin, H1, XIPp, gat_wq + l * HID, gat_wk + l * HID, gat_b, l,
            speakers, startp, bhh_c + l * G3, bih_p + l * G3, Geffp, uTp, G2Tp);
    }

    k_concat<<<MROWS, 256>>>(features);

    gemm8x8<<<dim3((HID + 127) / 128, MROWS / 128), 256>>>(
        Hcatp, w1, b1, h1p, MROWS, HID, KCAT, 1);
    gemm8x8<<<dim3((HID + 127) / 128, MROWS / 128), 256>>>(
        h1p, w2, b2, h2p, MROWS, HID, HID, 1);
    gemm8x8<<<dim3(1, MROWS / 128), 256>>>(
        h2p, w3, b3, (float*)d_out, MROWS, 7, HID, 0);
}

// round 13
// speedup vs baseline: 1.5079x; 1.0725x over previous
#include <cuda_runtime.h>
#include <math.h>

#define HID   300
#define G3    900
#define NSEQ  64
#define BATCH 64
#define EMB   1024
#define KCAT  2524
#define HSZ   (BATCH*NSEQ*HID)
#define NCTA  132
#define GEFFN 2100
#define G2LD  2112
#define SWT_F 9600
#define SP_F  8192                  /* 4096 u64 partials */
#define DSMEM_F (SWT_F + SP_F)      /* 17792 floats = 71168 B */
#define EW_BLOCKS 704
#define GEFF_TX 10
#define GEFF_TY 29

__device__ float g_H[5 * HSZ];
__device__ float g_XIP[BATCH * NSEQ * 1800];   // [XI | XP] per row
__device__ float g_WX[1800 * HID];             // [wih_c ; whh_p]
__device__ float g_bX[1800];                   // [bih_c ; bhh_p]
__device__ float g_Geff[GEFFN * 600];          // rows 0..1799: WG@Wr2, 1800..2099: Wr2
__device__ float g_uT[600 * BATCH];            // uT[d*64 + b]
__device__ float g_G2[BATCH * G2LD];           // per-batch row-major: G2[b*2112 + n]
__device__ int   g_start[BATCH * NSEQ];
__device__ float g_Hcat[BATCH * NSEQ * KCAT];
__device__ float g_h1[BATCH * NSEQ * HID];
__device__ float g_h2[BATCH * NSEQ * HID];

__device__ volatile unsigned g_ucnt;   // A arrivals (u ready), 64/step
__device__ volatile unsigned g_gcnt;   // all arrivals (G2 ready), 132/step

__device__ __forceinline__ float sigf(float x) {
    return __fdividef(1.f, 1.f + __expf(-x));
}
__device__ __forceinline__ float tanhfast(float x) {
    return __fdividef(2.f, 1.f + __expf(-2.f * x)) - 1.f;
}

__device__ __forceinline__ float bsum(float v, float* s8) {
    int tid = threadIdx.x;
#pragma unroll
    for (int o = 16; o > 0; o >>= 1) v += __shfl_xor_sync(0xffffffffu, v, o);
    if ((tid & 31) == 0) s8[tid >> 5] = v;
    __syncthreads();
    if (tid < 32) {
        float t = (tid < 8) ? s8[tid] : 0.f;
#pragma unroll
        for (int o = 4; o > 0; o >>= 1) t += __shfl_xor_sync(0xffffffffu, t, o);
        if (tid == 0) s8[0] = t;
    }
    __syncthreads();
    float r = s8[0];
    __syncthreads();
    return r;
}

__device__ __forceinline__ void red_inc(volatile unsigned* p) {
    asm volatile("red.global.add.u32 [%0], %1;" :: "l"((const void*)p), "r"(1u) : "memory");
}
__device__ __forceinline__ void waitge(volatile unsigned* p, unsigned t) {
    while (*p < t) { }
    asm volatile("fence.acq_rel.gpu;" ::: "memory");
}

// ---- merged prep: starts + WX/bX/Geff-bottom elementwise + Geff-top GEMM ----
__global__ void __launch_bounds__(256) k_prep2(
    const int* __restrict__ spk,
    const float* __restrict__ wih_c, const float* __restrict__ whh_p,
    const float* __restrict__ bih_c, const float* __restrict__ bhh_p,
    const float* __restrict__ whh_c, const float* __restrict__ wih_p,
    const float* __restrict__ wr0,   const float* __restrict__ wr1)
{
    int bid = blockIdx.x;
    if (bid < EW_BLOCKS) {
        for (int idx = bid * 256 + threadIdx.x; idx < 1800 * 300; idx += EW_BLOCKS * 256) {
            int n = idx / 300, d = idx - n * 300;
            g_WX[idx] = (n < 900) ? wih_c[n * 300 + d] : whh_p[(n - 900) * 300 + d];
            if (idx < 300 * 600) {
                int d2 = idx / 600, e = idx - d2 * 600;
                g_Geff[(1800 + d2) * 600 + e] =
                    (e < 300) ? wr0[d2 * 300 + e] : wr1[d2 * 300 + (e - 300)];
            }
            if (idx < 1800) g_bX[idx] = (idx < 900) ? bih_c[idx] : bhh_p[idx - 900];
            if (idx < 4096) {
                int b = idx >> 6, i = idx & 63;
                int s = spk[b * NSEQ + i];
                int last = -1;
                for (int j = 0; j < i; j++)
                    if (spk[b * NSEQ + j] == s) last = j;
                g_start[b * NSEQ + i] = last > 0 ? last : 0;
            }
            if (idx == 0) { g_ucnt = 0; g_gcnt = 0; }
        }
        return;
    }
    int gb2 = bid - EW_BLOCKS;
    int n0 = (gb2 / GEFF_TX) * 64, e0 = (gb2 % GEFF_TX) * 64;
    __shared__ float sA[16][65];
    __shared__ float sB[16][65];
    int tid = threadIdx.x;
    int tm = tid >> 4, tn = tid & 15;
    int lr = tid >> 2, lk = (tid & 3) * 4;
    float acc[4][4];
#pragma unroll
    for (int i = 0; i < 4; i++)
#pragma unroll
        for (int j = 0; j < 4; j++) acc[i][j] = 0.f;
    for (int k0 = 0; k0 < 300; k0 += 16) {
#pragma unroll
        for (int q = 0; q < 4; q++) {
            int k = k0 + lk + q;
            int n = n0 + lr;
            float av = 0.f;
            if (k < 300 && n < 1800)
                av = (n < 900) ? whh_c[n * 300 + k] : wih_p[(n - 900) * 300 + k];
            sA[lk + q][lr] = av;
            int e = e0 + lr;
            float bv = 0.f;
            if (k < 300 && e < 600)
                bv = (e < 300) ? wr0[k * 300 + e] : wr1[k * 300 + (e - 300)];
            sB[lk + q][lr] = bv;
        }
        __syncthreads();
#pragma unroll
        for (int kk = 0; kk < 16; kk++) {
            float a[4], bv[4];
#pragma unroll
            for (int i = 0; i < 4; i++) { a[i] = sA[kk][tm * 4 + i]; bv[i] = sB[kk][tn * 4 + i]; }
#pragma unroll
            for (int i = 0; i < 4; i++)
#pragma unroll
                for (int j = 0; j < 4; j++) acc[i][j] += a[i] * bv[j];
        }
        __syncthreads();
    }
#pragma unroll
    for (int i = 0; i < 4; i++) {
        int n = n0 + tm * 4 + i;
        if (n >= 1800) continue;
#pragma unroll
        for (int j = 0; j < 4; j++) {
            int e = e0 + tn * 4 + j;
            if (e >= 600) continue;
            g_Geff[(size_t)n * 600 + e] = acc[i][j];
        }
    }
}

// ---- dense GEMM: C=A@B^T+bias (opt relu). BM=128,BN=128,BK=16, 8x8, f32x2 ----
__global__ void __launch_bounds__(256, 2) gemm8x8(
    const float* __restrict__ A, const float* __restrict__ B,
    const float* __restrict__ bias, float* __restrict__ C,
    int M, int N, int K, int relu)
{
    __shared__ float sA[16 * 132];
    __shared__ float sB[16 * 132];
    int tid = threadIdx.x;
    int m0 = blockIdx.y * 128, n0 = blockIdx.x * 128;
    int tm = tid & 15, tn = tid >> 4;
    int lr = tid >> 2, lk = (tid & 3) * 4;
    unsigned long long acc2[8][4];
#pragma unroll
    for (int i = 0; i < 8; i++)
#pragma unroll
        for (int j = 0; j < 4; j++) acc2[i][j] = 0ull;

    for (int k0 = 0; k0 < K; k0 += 16) {
#pragma unroll
        for (int h = 0; h < 2; h++) {
            int m = lr + h * 64, gm = m0 + m, kb = k0 + lk;
            float4 av = make_float4(0.f, 0.f, 0.f, 0.f);
            if (gm < M) {
                if (kb + 3 < K) av = *(const float4*)(A + (size_t)gm * K + kb);
                else {
                    if (kb     < K) av.x = A[(size_t)gm * K + kb];
                    if (kb + 1 < K) av.y = A[(size_t)gm * K + kb + 1];
                    if (kb + 2 < K) av.z = A[(size_t)gm * K + kb + 2];
                }
            }
            sA[(lk + 0) * 132 + m] = av.x;
            sA[(lk + 1) * 132 + m] = av.y;
            sA[(lk + 2) * 132 + m] = av.z;
            sA[(lk + 3) * 132 + m] = av.w;

            int gn = n0 + m;
            float4 bv = make_float4(0.f, 0.f, 0.f, 0.f);
            if (gn < N) {
                if (kb + 3 < K) bv = *(const float4*)(B + (size_t)gn * K + kb);
                else {
                    if (kb     < K) bv.x = B[(size_t)gn * K + kb];
                    if (kb + 1 < K) bv.y = B[(size_t)gn * K + kb + 1];
                    if (kb + 2 < K) bv.z = B[(size_t)gn * K + kb + 2];
                }
            }
            sB[(lk + 0) * 132 + m] = bv.x;
            sB[(lk + 1) * 132 + m] = bv.y;
            sB[(lk + 2) * 132 + m] = bv.z;
            sB[(lk + 3) * 132 + m] = bv.w;
        }
        __syncthreads();
#pragma unroll
        for (int kk = 0; kk < 16; kk++) {
            float4 xa0 = *(const float4*)(sA + kk * 132 + tm * 4);
            float4 xa1 = *(const float4*)(sA + kk * 132 + 64 + tm * 4);
            float4 xb0 = *(const float4*)(sB + kk * 132 + tn * 4);
            float4 xb1 = *(const float4*)(sB + kk * 132 + 64 + tn * 4);
            unsigned long long bp[4];
            asm("mov.b64 %0,{%1,%2};" : "=l"(bp[0]) : "f"(xb0.x), "f"(xb0.y));
            asm("mov.b64 %0,{%1,%2};" : "=l"(bp[1]) : "f"(xb0.z), "f"(xb0.w));
            asm("mov.b64 %0,{%1,%2};" : "=l"(bp[2]) : "f"(xb1.x), "f"(xb1.y));
            asm("mov.b64 %0,{%1,%2};" : "=l"(bp[3]) : "f"(xb1.z), "f"(xb1.w));
            float a[8] = {xa0.x, xa0.y, xa0.z, xa0.w, xa1.x, xa1.y, xa1.z, xa1.w};
#pragma unroll
            for (int i = 0; i < 8; i++) {
                unsigned long long ap;
                asm("mov.b64 %0,{%1,%1};" : "=l"(ap) : "f"(a[i]));
#pragma unroll
                for (int j = 0; j < 4; j++)
                    asm("fma.rn.f32x2 %0,%1,%2,%0;" : "+l"(acc2[i][j]) : "l"(ap), "l"(bp[j]));
            }
        }
        __syncthreads();
    }
#pragma unroll
    for (int i = 0; i < 8; i++) {
        int m = m0 + ((i < 4) ? (tm * 4 + i) : (64 + tm * 4 + i - 4));
        if (m >= M) continue;
#pragma unroll
        for (int j = 0; j < 8; j++) {
            int n = n0 + ((j < 4) ? (tn * 4 + j) : (64 + tn * 4 + j - 4));
            if (n >= N) continue;
            float lo, hi;
            asm("mov.b64 {%0,%1},%2;" : "=f"(lo), "=f"(hi) : "l"(acc2[i][j >> 1]));
            float v = ((j & 1) ? hi : lo) + (bias ? bias[n] : 0.f);
            if (relu) v = fmaxf(v, 0.f);
            C[(size_t)m * N + n] = v;
        }
    }
}

// ---------------- persistent per-layer scan kernel ----------------
__global__ void __launch_bounds__(256, 1) persist_layer(
    const float* __restrict__ Hin, float* __restrict__ H1,
    const float* __restrict__ XIP,
    const float* __restrict__ wq, const float* __restrict__ wk,
    const float* __restrict__ gatb, int layer,
    const int* __restrict__ spk, const int* __restrict__ start,
    const float* __restrict__ bhh_c, const float* __restrict__ bih_p,
    const float* __restrict__ Geff, float* __restrict__ uT,
    float* __restrict__ G2)
{
    extern __shared__ float dsm[];
    float* sWT = dsm;                                 // 9600 f
    unsigned long long* sP = (unsigned long long*)(dsm + SWT_F);  // 4096 u64

    __shared__ float s8[8];
    __shared__ float s_w0[64];
    __shared__ float s_w1[64];
    __shared__ float s_kdot[64];
    __shared__ float s_qd[64];
    __shared__ float s_bias[16];

    const int tid = threadIdx.x;
    const int cta = blockIdx.x;
    const int b = cta;
    const int n0 = cta * 16;
    const int wid = tid >> 5, lid = tid & 31;

    for (int idx = tid; idx < SWT_F; idx += 256) {
        int k = idx >> 4, r = idx & 15;
        int n = n0 + r;
        sWT[idx] = (n < GEFFN) ? Geff[(size_t)n * 600 + k] : 0.f;
    }
    if (tid < 16) {
        int n = n0 + tid;
        float bv = 0.f;
        if (n < 900) bv = bhh_c[n];
        else if (n < 1800) bv = bih_p[n - 900];
        s_bias[tid] = bv;
    }

    const int bg = tid & 15, rg = (tid >> 4) & 1, ks = tid >> 5;
    const float* G2row = G2 + (size_t)b * G2LD;
    const ulonglong2* uTv = (const ulonglong2*)uT;   // [k][bg] 16B chunks

    const float gb = gatb[layer];

    if (cta < 64) {
        for (int i = wid; i < 64; i += 8) {
            float p = 0.f;
            const float* hr = Hin + ((size_t)b * NSEQ + i) * HID;
            for (int j = lid; j < HID; j += 32) p += hr[j] * wq[j];
#pragma unroll
            for (int o = 16; o > 0; o >>= 1) p += __shfl_xor_sync(0xffffffffu, p, o);
            if (lid == 0) s_qd[i] = p + gb;
        }
        const float* xi = XIP + (size_t)b * NSEQ * 1800;
        const float* xp = xi + 900;
        const float* x0 = Hin + (size_t)b * NSEQ * HID;
        float* h1 = H1 + (size_t)b * NSEQ * HID;
        float kp = 0.f;
        for (int d = tid; d < HID; d += 256) {
            float r  = sigf(xi[d] + bhh_c[d]);
            float z  = sigf(xi[300 + d] + bhh_c[300 + d]);
            float nn = tanhfast(xi[600 + d] + r * bhh_c[600 + d]);
            float C0 = (1.f - z) * nn;
            float r2 = sigf(bih_p[d] + xp[d]);
            float z2 = sigf(bih_p[300 + d] + xp[300 + d]);
            float n2 = tanhfast(bih_p[600 + d] + r2 * xp[600 + d]);
            float P0 = (1.f - z2) * n2 + z2 * x0[d];
            float h = C0 + P0;
            h1[d] = h;
            kp += h * wk[d];
        }
        float kss = bsum(kp, s8);
        if (tid == 0) s_kdot[0] = kss;
    }
    __syncthreads();

    for (int i = 1; i <= 63; i++) {
        // ===== phase A (CTAs 0..63): GRU row i-1, attention -> uT(i) =====
        if (cta < 64) {
            if (i >= 2) {
                int row = i - 1;
                const float* xi = XIP + ((size_t)b * NSEQ + row) * 1800;
                const float* xp = xi + 900;
                const float* q  = Hin + ((size_t)b * NSEQ + row) * HID;
                float* h1r = H1 + ((size_t)b * NSEQ + row) * HID;
                // prefetch layer-constant inputs before the wait
                float pxi[2][3], pxp[2][3], pq[2];
#pragma unroll
                for (int t = 0; t < 2; t++) {
                    int d = tid + t * 256;
                    if (d < HID) {
                        pxi[t][0] = xi[d]; pxi[t][1] = xi[300 + d]; pxi[t][2] = xi[600 + d];
                        pxp[t][0] = xp[d]; pxp[t][1] = xp[300 + d]; pxp[t][2] = xp[600 + d];
                        pq[t] = q[d];
                    }
                }
                if (tid == 0) waitge(&g_gcnt, NCTA * (unsigned)(i - 1));
                __syncthreads();
                float kp = 0.f;
#pragma unroll
                for (int t = 0; t < 2; t++) {
                    int d = tid + t * 256;
                    if (d < HID) {
                        float Md = __ldcg(G2row + 1800 + d);
                        float r  = sigf(pxi[t][0] + __ldcg(G2row + d));
                        float z  = sigf(pxi[t][1] + __ldcg(G2row + 300 + d));
                        float nn = tanhfast(pxi[t][2] + r * __ldcg(G2row + 600 + d));
                        float Cc = (1.f - z) * nn + z * Md;
                        float r2 = sigf(__ldcg(G2row + 900 + d)  + pxp[t][0]);
                        float z2 = sigf(__ldcg(G2row + 1200 + d) + pxp[t][1]);
                        float n2 = tanhfast(__ldcg(G2row + 1500 + d) + r2 * pxp[t][2]);
                        float Pp = (1.f - z2) * n2 + z2 * pq[t];
                        float h = Cc + Pp;
                        h1r[d] = h;
                        kp += h * wk[d];
                    }
                }
                float kss = bsum(kp, s8);
                if (tid == 0) s_kdot[row] = kss;
                __syncthreads();
            }
            int st = start[b * NSEQ + i];
            int cnt = i - st;
            if (tid < 32) {
                int spki = spk[b * NSEQ + i];
                float qd = s_qd[i];
                float a1 = (tid < cnt)      ? qd + s_kdot[st + tid]      : -1e30f;
                float a2 = (tid + 32 < cnt) ? qd + s_kdot[st + tid + 32] : -1e30f;
                float m = fmaxf(a1, a2);
#pragma unroll
                for (int o = 16; o > 0; o >>= 1) m = fmaxf(m, __shfl_xor_sync(0xffffffffu, m, o));
                float e1 = (tid < cnt)      ? __expf(a1 - m) : 0.f;
                float e2 = (tid + 32 < cnt) ? __expf(a2 - m) : 0.f;
                float s = e1 + e2;
#pragma unroll
                for (int o = 16; o > 0; o >>= 1) s += __shfl_xor_sync(0xffffffffu, s, o);
                float inv = __fdividef(1.f, s);
                if (tid < cnt) {
                    float w = e1 * inv;
                    float smv = (spk[b * NSEQ + st + tid] == spki) ? 1.f : 0.f;
                    s_w0[tid] = w * smv;
                    s_w1[tid] = w * (1.f - smv);
                }
                if (tid + 32 < cnt) {
                    float w = e2 * inv;
                    float smv = (spk[b * NSEQ + st + tid + 32] == spki) ? 1.f : 0.f;
                    s_w0[tid + 32] = w * smv;
                    s_w1[tid + 32] = w * (1.f - smv);
                }
            }
            __syncthreads();
            for (int d = tid; d < 600; d += 256) {
                int ei = (d < 300) ? d : d - 300;
                const float* wt = (d < 300) ? s_w0 : s_w1;
                const float* base = H1 + ((size_t)b * NSEQ + st) * HID + ei;
                float acc = 0.f;
                for (int j = 0; j < cnt; j++)
                    acc += wt[j] * base[j * HID];
                __stcg(uT + d * 64 + b, acc);
            }
            __threadfence();
            __syncthreads();
            if (tid == 0) red_inc(&g_ucnt);
        }
        // ===== all CTAs: wait u(i), then B with direct-L2 u reads =====
        if (tid == 0) waitge(&g_ucnt, 64u * (unsigned)i);
        __syncthreads();

        unsigned long long a01[8], a23[8];
#pragma unroll
        for (int r = 0; r < 8; r++) { a01[r] = 0ull; a23[r] = 0ull; }
        {
            const ulonglong2* up = uTv + (ks * 75) * 16 + bg;
#pragma unroll 5
            for (int kk = 0; kk < 75; kk++) {
                ulonglong2 uv = __ldcg(up);
                up += 16;
                const float* wr = sWT + (ks * 75 + kk) * 16 + rg * 8;
                float4 w0 = *(const float4*)wr;
                float4 w1 = *(const float4*)(wr + 4);
                float wf[8] = {w0.x, w0.y, w0.z, w0.w, w1.x, w1.y, w1.z, w1.w};
#pragma unroll
                for (int r = 0; r < 8; r++) {
                    unsigned long long wp;
                    asm("mov.b64 %0,{%1,%1};" : "=l"(wp) : "f"(wf[r]));
                    asm("fma.rn.f32x2 %0,%1,%2,%0;" : "+l"(a01[r]) : "l"(uv.x), "l"(wp));
                    asm("fma.rn.f32x2 %0,%1,%2,%0;" : "+l"(a23[r]) : "l"(uv.y), "l"(wp));
                }
            }
        }
#pragma unroll
        for (int r = 0; r < 8; r++) {
            int row = rg * 8 + r;
            sP[((ks * 16 + row) * 16 + bg) * 2 + 0] = a01[r];
            sP[((ks * 16 + row) * 16 + bg) * 2 + 1] = a23[r];
        }
        __syncthreads();
        {
#pragma unroll
            for (int t = 0; t < 2; t++) {
                int o = tid * 2 + t;
                int row = o >> 5, rem = o & 31;
                int bg2 = rem >> 1, p = rem & 1;
                unsigned long long s = sP[(row * 16 + bg2) * 2 + p];
#pragma unroll
                for (int k2 = 1; k2 < 8; k2++) {
                    unsigned long long v = sP[((k2 * 16 + row) * 16 + bg2) * 2 + p];
                    asm("add.rn.f32x2 %0,%1,%2;" : "=l"(s) : "l"(s), "l"(v));
                }
                unsigned long long bp;
                asm("mov.b64 %0,{%1,%1};" : "=l"(bp) : "f"(s_bias[row]));
                asm("add.rn.f32x2 %0,%1,%2;" : "=l"(s) : "l"(s), "l"(bp));
                int n = n0 + row;
                if (n < GEFFN) {
                    float lo, hi;
                    asm("mov.b64 {%0,%1},%2;" : "=f"(lo), "=f"(hi) : "l"(s));
                    int b0 = bg2 * 4 + p * 2;
                    __stcg(G2 + (size_t)b0 * G2LD + n, lo);
                    __stcg(G2 + (size_t)(b0 + 1) * G2LD + n, hi);
                }
            }
        }
        __threadfence();
        __syncthreads();
        if (tid == 0) red_inc(&g_gcnt);
        __syncthreads();   // keep sP write (next iter) after all reads
    }

    // final GRU update: row 63
    if (cta < 64) {
        if (tid == 0) waitge(&g_gcnt, NCTA * 63u);
        __syncthreads();
        int row = 63;
        const float* xi = XIP + ((size_t)b * NSEQ + row) * 1800;
        const float* xp = xi + 900;
        const float* q  = Hin + ((size_t)b * NSEQ + row) * HID;
        float* h1r = H1 + ((size_t)b * NSEQ + row) * HID;
        for (int d = tid; d < HID; d += 256) {
            float Md = __ldcg(G2row + 1800 + d);
            float r  = sigf(xi[d]       + __ldcg(G2row + d));
            float z  = sigf(xi[300 + d] + __ldcg(G2row + 300 + d));
            float nn = tanhfast(xi[600 + d] + r * __ldcg(G2row + 600 + d));
            float Cc = (1.f - z) * nn + z * Md;
            float r2 = sigf(__ldcg(G2row + 900 + d)  + xp[d]);
            float z2 = sigf(__ldcg(G2row + 1200 + d) + xp[300 + d]);
            float n2 = tanhfast(__ldcg(G2row + 1500 + d) + r2 * xp[600 + d]);
            float Pp = (1.f - z2) * n2 + z2 * q[d];
            h1r[d] = Cc + Pp;
        }
    }
}

__global__ void k_concat(const float* __restrict__ feat) {
    int r = blockIdx.x;
    for (int c = threadIdx.x; c < KCAT; c += blockDim.x) {
        float v;
        if (c < 1500) {
            int seg = c / 300, off = c - seg * 300;
            v = g_H[seg * HSZ + r * HID + off];
        } else {
            v = feat[r * EMB + (c - 1500)];
        }
        g_Hcat[r * KCAT + c] = v;
    }
}

extern "C" void kernel_launch(void* const* d_in, const int* in_sizes, int n_in,
                              void* d_out, int out_size) {
    const float* features = (const float*)d_in[0];
    const int*   speakers = (const int*)d_in[1];
    const float* w_in   = (const float*)d_in[2];
    const float* b_in   = (const float*)d_in[3];
    const float* gat_wq = (const float*)d_in[4];
    const float* gat_wk = (const float*)d_in[5];
    const float* gat_b  = (const float*)d_in[6];
    const float* wr0    = (const float*)d_in[7];
    const float* wr1    = (const float*)d_in[8];
    const float* wih_c  = (const float*)d_in[9];
    const float* whh_c  = (const float*)d_in[10];
    const float* bih_c  = (const float*)d_in[11];
    const float* bhh_c  = (const float*)d_in[12];
    const float* wih_p  = (const float*)d_in[13];
    const float* whh_p  = (const float*)d_in[14];
    const float* bih_p  = (const float*)d_in[15];
    const float* bhh_p  = (const float*)d_in[16];
    const float* w1 = (const float*)d_in[17];
    const float* b1 = (const float*)d_in[18];
    const float* w2 = (const float*)d_in[19];
    const float* b2 = (const float*)d_in[20];
    const float* w3 = (const float*)d_in[21];
    const float* b3 = (const float*)d_in[22];

    float *H, *XIPp, *WXp, *bXp, *Geffp, *uTp, *G2p, *Hcatp, *h1p, *h2p;
    int *startp;
    cudaGetSymbolAddress((void**)&H,     g_H);
    cudaGetSymbolAddress((void**)&XIPp,  g_XIP);
    cudaGetSymbolAddress((void**)&WXp,   g_WX);
    cudaGetSymbolAddress((void**)&bXp,   g_bX);
    cudaGetSymbolAddress((void**)&Geffp, g_Geff);
    cudaGetSymbolAddress((void**)&uTp,   g_uT);
    cudaGetSymbolAddress((void**)&G2p,   g_G2);
    cudaGetSymbolAddress((void**)&startp,g_start);
    cudaGetSymbolAddress((void**)&Hcatp, g_Hcat);
    cudaGetSymbolAddress((void**)&h1p,   g_h1);
    cudaGetSymbolAddress((void**)&h2p,   g_h2);

    cudaFuncSetAttribute(persist_layer,
                         cudaFuncAttributeMaxDynamicSharedMemorySize,
                         DSMEM_F * 4);

    const int MROWS = BATCH * NSEQ;
    const int PREP_GRID = EW_BLOCKS + GEFF_TX * GEFF_TY;

    for (int l = 0; l < 4; l++) {
        k_prep2<<<PREP_GRID, 256>>>(
            speakers,
            wih_c + l * G3 * HID, whh_p + l * G3 * HID,
            bih_c + l * G3, bhh_p + l * G3,
            whh_c + l * G3 * HID, wih_p + l * G3 * HID,
            wr0 + l * HID * HID, wr1 + l * HID * HID);

        if (l == 0) {
            gemm8x8<<<dim3((HID + 127) / 128, MROWS / 128), 256>>>(
                features, w_in, b_in, H, MROWS, HID, EMB, 1);
        }
        const float* Hin = H + l * HSZ;
        float* H1 = H + (l + 1) * HSZ;

        gemm8x8<<<dim3((1800 + 127) / 128, MROWS / 128), 256>>>(
            Hin, WXp, bXp, XIPp, MROWS, 1800, HID, 0);

        persist_layer<<<NCTA, 256, DSMEM_F * 4>>>(
            Hin, H1, XIPp, gat_wq + l * HID, gat_wk + l * HID, gat_b, l,
            speakers, startp, bhh_c + l * G3, bih_p + l * G3, Geffp, uTp, G2p);
    }

    k_concat<<<MROWS, 256>>>(features);

    gemm8x8<<<dim3((HID + 127) / 128, MROWS / 128), 256>>>(
        Hcatp, w1, b1, h1p, MROWS, HID, KCAT, 1);
    gemm8x8<<<dim3((HID + 127) / 128, MROWS / 128), 256>>>(
        h1p, w2, b2, h2p, MROWS, HID, HID, 1);
    gemm8x8<<<dim3(1, MROWS / 128), 256>>>(
        h2p, w3, b3, (float*)d_out, MROWS, 7, HID, 0);
}

// round 14
// speedup vs baseline: 1.5672x; 1.0394x over previous
#include <cuda_runtime.h>
#include <math.h>

#define HID   300
#define G3    900
#define NSEQ  64
#define BATCH 64
#define EMB   1024
#define KCAT  2524
#define HSZ   (BATCH*NSEQ*HID)
#define NCTA  132
#define GEFFN 2100
#define G2LD  2112
#define SW64_N 9600                   /* u64 duplicated weight pairs */
#define SP_N   4096                   /* u64 partials */
#define DSMEM_B ((SW64_N + SP_N) * 8) /* 109568 bytes */
#define EW_BLOCKS 704
#define GEFF_TX 10
#define GEFF_TY 29

__device__ float g_H[5 * HSZ];
__device__ float g_XIP[BATCH * NSEQ * 1800];   // [XI | XP] per row
__device__ float g_WX[1800 * HID];             // [wih_c ; whh_p]
__device__ float g_bX[1800];                   // [bih_c ; bhh_p]
__device__ float g_Geff[GEFFN * 600];          // rows 0..1799: WG@Wr2, 1800..2099: Wr2
__device__ float g_uT[600 * BATCH];            // uT[d*64 + b]
__device__ float g_G2[BATCH * G2LD];           // per-batch row-major: G2[b*2112 + n]
__device__ int   g_start[BATCH * NSEQ];
__device__ float g_Hcat[BATCH * NSEQ * KCAT];
__device__ float g_h1[BATCH * NSEQ * HID];
__device__ float g_h2[BATCH * NSEQ * HID];

__device__ volatile unsigned g_ucnt;   // A arrivals (u ready), 64/step
__device__ volatile unsigned g_gcnt;   // all arrivals (G2 ready), 132/step

__device__ __forceinline__ float sigf(float x) {
    return __fdividef(1.f, 1.f + __expf(-x));
}
__device__ __forceinline__ float tanhfast(float x) {
    return __fdividef(2.f, 1.f + __expf(-2.f * x)) - 1.f;
}

__device__ __forceinline__ float bsum(float v, float* s8) {
    int tid = threadIdx.x;
#pragma unroll
    for (int o = 16; o > 0; o >>= 1) v += __shfl_xor_sync(0xffffffffu, v, o);
    if ((tid & 31) == 0) s8[tid >> 5] = v;
    __syncthreads();
    if (tid < 32) {
        float t = (tid < 8) ? s8[tid] : 0.f;
#pragma unroll
        for (int o = 4; o > 0; o >>= 1) t += __shfl_xor_sync(0xffffffffu, t, o);
        if (tid == 0) s8[0] = t;
    }
    __syncthreads();
    float r = s8[0];
    __syncthreads();
    return r;
}

__device__ __forceinline__ void red_inc(volatile unsigned* p) {
    asm volatile("red.global.add.u32 [%0], %1;" :: "l"((const void*)p), "r"(1u) : "memory");
}
__device__ __forceinline__ void waitge(volatile unsigned* p, unsigned t) {
    while (*p < t) { }
    asm volatile("fence.acq_rel.gpu;" ::: "memory");
}

// ---- merged prep: starts + WX/bX/Geff-bottom elementwise + Geff-top GEMM ----
__global__ void __launch_bounds__(256) k_prep2(
    const int* __restrict__ spk,
    const float* __restrict__ wih_c, const float* __restrict__ whh_p,
    const float* __restrict__ bih_c, const float* __restrict__ bhh_p,
    const float* __restrict__ whh_c, const float* __restrict__ wih_p,
    const float* __restrict__ wr0,   const float* __restrict__ wr1)
{
    int bid = blockIdx.x;
    if (bid < EW_BLOCKS) {
        for (int idx = bid * 256 + threadIdx.x; idx < 1800 * 300; idx += EW_BLOCKS * 256) {
            int n = idx / 300, d = idx - n * 300;
            g_WX[idx] = (n < 900) ? wih_c[n * 300 + d] : whh_p[(n - 900) * 300 + d];
            if (idx < 300 * 600) {
                int d2 = idx / 600, e = idx - d2 * 600;
                g_Geff[(1800 + d2) * 600 + e] =
                    (e < 300) ? wr0[d2 * 300 + e] : wr1[d2 * 300 + (e - 300)];
            }
            if (idx < 1800) g_bX[idx] = (idx < 900) ? bih_c[idx] : bhh_p[idx - 900];
            if (idx < 4096) {
                int b = idx >> 6, i = idx & 63;
                int s = spk[b * NSEQ + i];
                int last = -1;
                for (int j = 0; j < i; j++)
                    if (spk[b * NSEQ + j] == s) last = j;
                g_start[b * NSEQ + i] = last > 0 ? last : 0;
            }
            if (idx == 0) { g_ucnt = 0; g_gcnt = 0; }
        }
        return;
    }
    int gb2 = bid - EW_BLOCKS;
    int n0 = (gb2 / GEFF_TX) * 64, e0 = (gb2 % GEFF_TX) * 64;
    __shared__ float sA[16][65];
    __shared__ float sB[16][65];
    int tid = threadIdx.x;
    int tm = tid >> 4, tn = tid & 15;
    int lr = tid >> 2, lk = (tid & 3) * 4;
    float acc[4][4];
#pragma unroll
    for (int i = 0; i < 4; i++)
#pragma unroll
        for (int j = 0; j < 4; j++) acc[i][j] = 0.f;
    for (int k0 = 0; k0 < 300; k0 += 16) {
#pragma unroll
        for (int q = 0; q < 4; q++) {
            int k = k0 + lk + q;
            int n = n0 + lr;
            float av = 0.f;
            if (k < 300 && n < 1800)
                av = (n < 900) ? whh_c[n * 300 + k] : wih_p[(n - 900) * 300 + k];
            sA[lk + q][lr] = av;
            int e = e0 + lr;
            float bv = 0.f;
            if (k < 300 && e < 600)
                bv = (e < 300) ? wr0[k * 300 + e] : wr1[k * 300 + (e - 300)];
            sB[lk + q][lr] = bv;
        }
        __syncthreads();
#pragma unroll
        for (int kk = 0; kk < 16; kk++) {
            float a[4], bv[4];
#pragma unroll
            for (int i = 0; i < 4; i++) { a[i] = sA[kk][tm * 4 + i]; bv[i] = sB[kk][tn * 4 + i]; }
#pragma unroll
            for (int i = 0; i < 4; i++)
#pragma unroll
                for (int j = 0; j < 4; j++) acc[i][j] += a[i] * bv[j];
        }
        __syncthreads();
    }
#pragma unroll
    for (int i = 0; i < 4; i++) {
        int n = n0 + tm * 4 + i;
        if (n >= 1800) continue;
#pragma unroll
        for (int j = 0; j < 4; j++) {
            int e = e0 + tn * 4 + j;
            if (e >= 600) continue;
            g_Geff[(size_t)n * 600 + e] = acc[i][j];
        }
    }
}

// ---- fetch macro for gemm8x8 prefetch double-buffer ----
#define GFETCH(K0) do { \
    int kb = (K0) + lk; \
    pA0 = make_float4(0.f, 0.f, 0.f, 0.f); pA1 = pA0; pB0 = pA0; pB1 = pA0; \
    int gm0 = m0 + lr, gm1 = m0 + lr + 64; \
    int gn0 = n0 + lr, gn1 = n0 + lr + 64; \
    if (kb + 3 < K) { \
        if (gm0 < M) pA0 = *(const float4*)(A + (size_t)gm0 * K + kb); \
        if (gm1 < M) pA1 = *(const float4*)(A + (size_t)gm1 * K + kb); \
        if (gn0 < N) pB0 = *(const float4*)(B + (size_t)gn0 * K + kb); \
        if (gn1 < N) pB1 = *(const float4*)(B + (size_t)gn1 * K + kb); \
    } else { \
        if (gm0 < M) { if (kb < K) pA0.x = A[(size_t)gm0*K+kb]; if (kb+1 < K) pA0.y = A[(size_t)gm0*K+kb+1]; if (kb+2 < K) pA0.z = A[(size_t)gm0*K+kb+2]; } \
        if (gm1 < M) { if (kb < K) pA1.x = A[(size_t)gm1*K+kb]; if (kb+1 < K) pA1.y = A[(size_t)gm1*K+kb+1]; if (kb+2 < K) pA1.z = A[(size_t)gm1*K+kb+2]; } \
        if (gn0 < N) { if (kb < K) pB0.x = B[(size_t)gn0*K+kb]; if (kb+1 < K) pB0.y = B[(size_t)gn0*K+kb+1]; if (kb+2 < K) pB0.z = B[(size_t)gn0*K+kb+2]; } \
        if (gn1 < N) { if (kb < K) pB1.x = B[(size_t)gn1*K+kb]; if (kb+1 < K) pB1.y = B[(size_t)gn1*K+kb+1]; if (kb+2 < K) pB1.z = B[(size_t)gn1*K+kb+2]; } \
    } \
} while (0)

// ---- dense GEMM: C=A@B^T+bias (opt relu). BM=128,BN=128,BK=16, 8x8, f32x2,
//      register-prefetch double-buffer ----
__global__ void __launch_bounds__(256, 2) gemm8x8(
    const float* __restrict__ A, const float* __restrict__ B,
    const float* __restrict__ bias, float* __restrict__ C,
    int M, int N, int K, int relu)
{
    __shared__ float sA[16 * 132];
    __shared__ float sB[16 * 132];
    int tid = threadIdx.x;
    int m0 = blockIdx.y * 128, n0 = blockIdx.x * 128;
    int tm = tid & 15, tn = tid >> 4;
    int lr = tid >> 2, lk = (tid & 3) * 4;
    unsigned long long acc2[8][4];
#pragma unroll
    for (int i = 0; i < 8; i++)
#pragma unroll
        for (int j = 0; j < 4; j++) acc2[i][j] = 0ull;

    float4 pA0, pA1, pB0, pB1;
    int T = (K + 15) / 16;
    GFETCH(0);

    for (int t = 0; t < T; t++) {
        // store prefetched tile
        sA[(lk + 0) * 132 + lr] = pA0.x;
        sA[(lk + 1) * 132 + lr] = pA0.y;
        sA[(lk + 2) * 132 + lr] = pA0.z;
        sA[(lk + 3) * 132 + lr] = pA0.w;
        sA[(lk + 0) * 132 + 64 + lr] = pA1.x;
        sA[(lk + 1) * 132 + 64 + lr] = pA1.y;
        sA[(lk + 2) * 132 + 64 + lr] = pA1.z;
        sA[(lk + 3) * 132 + 64 + lr] = pA1.w;
        sB[(lk + 0) * 132 + lr] = pB0.x;
        sB[(lk + 1) * 132 + lr] = pB0.y;
        sB[(lk + 2) * 132 + lr] = pB0.z;
        sB[(lk + 3) * 132 + lr] = pB0.w;
        sB[(lk + 0) * 132 + 64 + lr] = pB1.x;
        sB[(lk + 1) * 132 + 64 + lr] = pB1.y;
        sB[(lk + 2) * 132 + 64 + lr] = pB1.z;
        sB[(lk + 3) * 132 + 64 + lr] = pB1.w;
        __syncthreads();
        if (t + 1 < T) GFETCH((t + 1) * 16);   // LDGs fly during compute
#pragma unroll
        for (int kk = 0; kk < 16; kk++) {
            float4 xa0 = *(const float4*)(sA + kk * 132 + tm * 4);
            float4 xa1 = *(const float4*)(sA + kk * 132 + 64 + tm * 4);
            float4 xb0 = *(const float4*)(sB + kk * 132 + tn * 4);
            float4 xb1 = *(const float4*)(sB + kk * 132 + 64 + tn * 4);
            unsigned long long bp[4];
            asm("mov.b64 %0,{%1,%2};" : "=l"(bp[0]) : "f"(xb0.x), "f"(xb0.y));
            asm("mov.b64 %0,{%1,%2};" : "=l"(bp[1]) : "f"(xb0.z), "f"(xb0.w));
            asm("mov.b64 %0,{%1,%2};" : "=l"(bp[2]) : "f"(xb1.x), "f"(xb1.y));
            asm("mov.b64 %0,{%1,%2};" : "=l"(bp[3]) : "f"(xb1.z), "f"(xb1.w));
            float a[8] = {xa0.x, xa0.y, xa0.z, xa0.w, xa1.x, xa1.y, xa1.z, xa1.w};
#pragma unroll
            for (int i = 0; i < 8; i++) {
                unsigned long long ap;
                asm("mov.b64 %0,{%1,%1};" : "=l"(ap) : "f"(a[i]));
#pragma unroll
                for (int j = 0; j < 4; j++)
                    asm("fma.rn.f32x2 %0,%1,%2,%0;" : "+l"(acc2[i][j]) : "l"(ap), "l"(bp[j]));
            }
        }
        __syncthreads();
    }
#pragma unroll
    for (int i = 0; i < 8; i++) {
        int m = m0 + ((i < 4) ? (tm * 4 + i) : (64 + tm * 4 + i - 4));
        if (m >= M) continue;
#pragma unroll
        for (int j = 0; j < 8; j++) {
            int n = n0 + ((j < 4) ? (tn * 4 + j) : (64 + tn * 4 + j - 4));
            if (n >= N) continue;
            float lo, hi;
            asm("mov.b64 {%0,%1},%2;" : "=f"(lo), "=f"(hi) : "l"(acc2[i][j >> 1]));
            float v = ((j & 1) ? hi : lo) + (bias ? bias[n] : 0.f);
            if (relu) v = fmaxf(v, 0.f);
            C[(size_t)m * N + n] = v;
        }
    }
}

// ---------------- persistent per-layer scan kernel ----------------
__global__ void __launch_bounds__(256, 1) persist_layer(
    const float* __restrict__ Hin, float* __restrict__ H1,
    const float* __restrict__ XIP,
    const float* __restrict__ wq, const float* __restrict__ wk,
    const float* __restrict__ gatb, int layer,
    const int* __restrict__ spk, const int* __restrict__ start,
    const float* __restrict__ bhh_c, const float* __restrict__ bih_p,
    const float* __restrict__ Geff, float* __restrict__ uT,
    float* __restrict__ G2)
{
    extern __shared__ float dsm[];
    unsigned long long* sW64 = (unsigned long long*)dsm;     // 9600 u64 dup pairs
    unsigned long long* sP   = sW64 + SW64_N;                // 4096 u64 partials

    __shared__ float s8[8];
    __shared__ float s_w0[64];
    __shared__ float s_w1[64];
    __shared__ float s_kdot[64];
    __shared__ float s_qd[64];
    __shared__ float s_bias[16];

    const int tid = threadIdx.x;
    const int cta = blockIdx.x;
    const int b = cta;
    const int n0 = cta * 16;
    const int wid = tid >> 5, lid = tid & 31;

    // duplicated-pair weight slice: sW64[k*16+r] = {w, w}
    for (int idx = tid; idx < SW64_N; idx += 256) {
        int k = idx >> 4, r = idx & 15;
        int n = n0 + r;
        float w = (n < GEFFN) ? Geff[(size_t)n * 600 + k] : 0.f;
        unsigned long long p;
        asm("mov.b64 %0,{%1,%1};" : "=l"(p) : "f"(w));
        sW64[idx] = p;
    }
    if (tid < 16) {
        int n = n0 + tid;
        float bv = 0.f;
        if (n < 900) bv = bhh_c[n];
        else if (n < 1800) bv = bih_p[n - 900];
        s_bias[tid] = bv;
    }

    const int bg = tid & 15, rg = (tid >> 4) & 1, ks = tid >> 5;
    const float* G2row = G2 + (size_t)b * G2LD;
    const ulonglong2* uTv = (const ulonglong2*)uT;
    const unsigned sWaddr = (unsigned)__cvta_generic_to_shared(sW64)
                          + (unsigned)(((ks * 75) * 16 + rg * 8) * 8);

    const float gb = gatb[layer];

    if (cta < 64) {
        for (int i = wid; i < 64; i += 8) {
            float p = 0.f;
            const float* hr = Hin + ((size_t)b * NSEQ + i) * HID;
            for (int j = lid; j < HID; j += 32) p += hr[j] * wq[j];
#pragma unroll
            for (int o = 16; o > 0; o >>= 1) p += __shfl_xor_sync(0xffffffffu, p, o);
            if (lid == 0) s_qd[i] = p + gb;
        }
        const float* xi = XIP + (size_t)b * NSEQ * 1800;
        const float* xp = xi + 900;
        const float* x0 = Hin + (size_t)b * NSEQ * HID;
        float* h1 = H1 + (size_t)b * NSEQ * HID;
        float kp = 0.f;
        for (int d = tid; d < HID; d += 256) {
            float r  = sigf(xi[d] + bhh_c[d]);
            float z  = sigf(xi[300 + d] + bhh_c[300 + d]);
            float nn = tanhfast(xi[600 + d] + r * bhh_c[600 + d]);
            float C0 = (1.f - z) * nn;
            float r2 = sigf(bih_p[d] + xp[d]);
            float z2 = sigf(bih_p[300 + d] + xp[300 + d]);
            float n2 = tanhfast(bih_p[600 + d] + r2 * xp[600 + d]);
            float P0 = (1.f - z2) * n2 + z2 * x0[d];
            float h = C0 + P0;
            h1[d] = h;
            kp += h * wk[d];
        }
        float kss = bsum(kp, s8);
        if (tid == 0) s_kdot[0] = kss;
    }
    __syncthreads();

    for (int i = 1; i <= 63; i++) {
        // ===== phase A (CTAs 0..63): GRU row i-1, attention -> uT(i) =====
        if (cta < 64) {
            if (i >= 2) {
                int row = i - 1;
                const float* xi = XIP + ((size_t)b * NSEQ + row) * 1800;
                const float* xp = xi + 900;
                const float* q  = Hin + ((size_t)b * NSEQ + row) * HID;
                float* h1r = H1 + ((size_t)b * NSEQ + row) * HID;
                float pxi[2][3], pxp[2][3], pq[2];
#pragma unroll
                for (int t = 0; t < 2; t++) {
                    int d = tid + t * 256;
                    if (d < HID) {
                        pxi[t][0] = xi[d]; pxi[t][1] = xi[300 + d]; pxi[t][2] = xi[600 + d];
                        pxp[t][0] = xp[d]; pxp[t][1] = xp[300 + d]; pxp[t][2] = xp[600 + d];
                        pq[t] = q[d];
                    }
                }
                if (tid == 0) waitge(&g_gcnt, NCTA * (unsigned)(i - 1));
                __syncthreads();
                float kp = 0.f;
#pragma unroll
                for (int t = 0; t < 2; t++) {
                    int d = tid + t * 256;
                    if (d < HID) {
                        float Md = __ldcg(G2row + 1800 + d);
                        float r  = sigf(pxi[t][0] + __ldcg(G2row + d));
                        float z  = sigf(pxi[t][1] + __ldcg(G2row + 300 + d));
                        float nn = tanhfast(pxi[t][2] + r * __ldcg(G2row + 600 + d));
                        float Cc = (1.f - z) * nn + z * Md;
                        float r2 = sigf(__ldcg(G2row + 900 + d)  + pxp[t][0]);
                        float z2 = sigf(__ldcg(G2row + 1200 + d) + pxp[t][1]);
                        float n2 = tanhfast(__ldcg(G2row + 1500 + d) + r2 * pxp[t][2]);
                        float Pp = (1.f - z2) * n2 + z2 * pq[t];
                        float h = Cc + Pp;
                        h1r[d] = h;
                        kp += h * wk[d];
                    }
                }
                float kss = bsum(kp, s8);
                if (tid == 0) s_kdot[row] = kss;
                __syncthreads();
            }
            int st = start[b * NSEQ + i];
            int cnt = i - st;
            if (tid < 32) {
                int spki = spk[b * NSEQ + i];
                float qd = s_qd[i];
                float a1 = (tid < cnt)      ? qd + s_kdot[st + tid]      : -1e30f;
                float a2 = (tid + 32 < cnt) ? qd + s_kdot[st + tid + 32] : -1e30f;
                float m = fmaxf(a1, a2);
#pragma unroll
                for (int o = 16; o > 0; o >>= 1) m = fmaxf(m, __shfl_xor_sync(0xffffffffu, m, o));
                float e1 = (tid < cnt)      ? __expf(a1 - m) : 0.f;
                float e2 = (tid + 32 < cnt) ? __expf(a2 - m) : 0.f;
                float s = e1 + e2;
#pragma unroll
                for (int o = 16; o > 0; o >>= 1) s += __shfl_xor_sync(0xffffffffu, s, o);
                float inv = __fdividef(1.f, s);
                if (tid < cnt) {
                    float w = e1 * inv;
                    float smv = (spk[b * NSEQ + st + tid] == spki) ? 1.f : 0.f;
                    s_w0[tid] = w * smv;
                    s_w1[tid] = w * (1.f - smv);
                }
                if (tid + 32 < cnt) {
                    float w = e2 * inv;
                    float smv = (spk[b * NSEQ + st + tid + 32] == spki) ? 1.f : 0.f;
                    s_w0[tid + 32] = w * smv;
                    s_w1[tid + 32] = w * (1.f - smv);
                }
            }
            __syncthreads();
            for (int d = tid; d < 600; d += 256) {
                int ei = (d < 300) ? d : d - 300;
                const float* wt = (d < 300) ? s_w0 : s_w1;
                const float* base = H1 + ((size_t)b * NSEQ + st) * HID + ei;
                float acc = 0.f;
                for (int j = 0; j < cnt; j++)
                    acc += wt[j] * base[j * HID];
                __stcg(uT + d * 64 + b, acc);
            }
            __threadfence();
            __syncthreads();
            if (tid == 0) red_inc(&g_ucnt);
        }
        // ===== all CTAs: wait u(i), then B with direct-L2 u reads =====
        if (tid == 0) waitge(&g_ucnt, 64u * (unsigned)i);
        __syncthreads();

        unsigned long long a01[8], a23[8];
#pragma unroll
        for (int r = 0; r < 8; r++) { a01[r] = 0ull; a23[r] = 0ull; }
        {
            const ulonglong2* up = uTv + (ks * 75) * 16 + bg;
            unsigned wA = sWaddr;
#pragma unroll 5
            for (int kk = 0; kk < 75; kk++) {
                ulonglong2 uv = __ldcg(up);
                up += 16;
                unsigned long long w0, w1, w2, w3, w4, w5, w6, w7;
                asm volatile("ld.shared.v2.u64 {%0,%1},[%2];" : "=l"(w0), "=l"(w1) : "r"(wA));
                asm volatile("ld.shared.v2.u64 {%0,%1},[%2];" : "=l"(w2), "=l"(w3) : "r"(wA + 16u));
                asm volatile("ld.shared.v2.u64 {%0,%1},[%2];" : "=l"(w4), "=l"(w5) : "r"(wA + 32u));
                asm volatile("ld.shared.v2.u64 {%0,%1},[%2];" : "=l"(w6), "=l"(w7) : "r"(wA + 48u));
                wA += 128u;
                asm("fma.rn.f32x2 %0,%1,%2,%0;" : "+l"(a01[0]) : "l"(uv.x), "l"(w0));
                asm("fma.rn.f32x2 %0,%1,%2,%0;" : "+l"(a23[0]) : "l"(uv.y), "l"(w0));
                asm("fma.rn.f32x2 %0,%1,%2,%0;" : "+l"(a01[1]) : "l"(uv.x), "l"(w1));
                asm("fma.rn.f32x2 %0,%1,%2,%0;" : "+l"(a23[1]) : "l"(uv.y), "l"(w1));
                asm("fma.rn.f32x2 %0,%1,%2,%0;" : "+l"(a01[2]) : "l"(uv.x), "l"(w2));
                asm("fma.rn.f32x2 %0,%1,%2,%0;" : "+l"(a23[2]) : "l"(uv.y), "l"(w2));
                asm("fma.rn.f32x2 %0,%1,%2,%0;" : "+l"(a01[3]) : "l"(uv.x), "l"(w3));
                asm("fma.rn.f32x2 %0,%1,%2,%0;" : "+l"(a23[3]) : "l"(uv.y), "l"(w3));
                asm("fma.rn.f32x2 %0,%1,%2,%0;" : "+l"(a01[4]) : "l"(uv.x), "l"(w4));
                asm("fma.rn.f32x2 %0,%1,%2,%0;" : "+l"(a23[4]) : "l"(uv.y), "l"(w4));
                asm("fma.rn.f32x2 %0,%1,%2,%0;" : "+l"(a01[5]) : "l"(uv.x), "l"(w5));
                asm("fma.rn.f32x2 %0,%1,%2,%0;" : "+l"(a23[5]) : "l"(uv.y), "l"(w5));
                asm("fma.rn.f32x2 %0,%1,%2,%0;" : "+l"(a01[6]) : "l"(uv.x), "l"(w6));
                asm("fma.rn.f32x2 %0,%1,%2,%0;" : "+l"(a23[6]) : "l"(uv.y), "l"(w6));
                asm("fma.rn.f32x2 %0,%1,%2,%0;" : "+l"(a01[7]) : "l"(uv.x), "l"(w7));
                asm("fma.rn.f32x2 %0,%1,%2,%0;" : "+l"(a23[7]) : "l"(uv.y), "l"(w7));
            }
        }
#pragma unroll
        for (int r = 0; r < 8; r++) {
            int row = rg * 8 + r;
            sP[((ks * 16 + row) * 16 + bg) * 2 + 0] = a01[r];
            sP[((ks * 16 + row) * 16 + bg) * 2 + 1] = a23[r];
        }
        __syncthreads();
        {
#pragma unroll
            for (int t = 0; t < 2; t++) {
                int o = tid * 2 + t;
                int row = o >> 5, rem = o & 31;
                int bg2 = rem >> 1, p = rem & 1;
                unsigned long long s = sP[(row * 16 + bg2) * 2 + p];
#pragma unroll
                for (int k2 = 1; k2 < 8; k2++) {
                    unsigned long long v = sP[((k2 * 16 + row) * 16 + bg2) * 2 + p];
                    asm("add.rn.f32x2 %0,%1,%2;" : "=l"(s) : "l"(s), "l"(v));
                }
                unsigned long long bp;
                asm("mov.b64 %0,{%1,%1};" : "=l"(bp) : "f"(s_bias[row]));
                asm("add.rn.f32x2 %0,%1,%2;" : "=l"(s) : "l"(s), "l"(bp));
                int n = n0 + row;
                if (n < GEFFN) {
                    float lo, hi;
                    asm("mov.b64 {%0,%1},%2;" : "=f"(lo), "=f"(hi) : "l"(s));
                    int b0 = bg2 * 4 + p * 2;
                    __stcg(G2 + (size_t)b0 * G2LD + n, lo);
                    __stcg(G2 + (size_t)(b0 + 1) * G2LD + n, hi);
                }
            }
        }
        __threadfence();
        __syncthreads();
        if (tid == 0) red_inc(&g_gcnt);
        // no trailing sync: next sP write is ordered behind next waitge+syncthreads
    }

    // final GRU update: row 63
    if (cta < 64) {
        if (tid == 0) waitge(&g_gcnt, NCTA * 63u);
        __syncthreads();
        int row = 63;
        const float* xi = XIP + ((size_t)b * NSEQ + row) * 1800;
        const float* xp = xi + 900;
        const float* q  = Hin + ((size_t)b * NSEQ + row) * HID;
        float* h1r = H1 + ((size_t)b * NSEQ + row) * HID;
        for (int d = tid; d < HID; d += 256) {
            float Md = __ldcg(G2row + 1800 + d);
            float r  = sigf(xi[d]       + __ldcg(G2row + d));
            float z  = sigf(xi[300 + d] + __ldcg(G2row + 300 + d));
            float nn = tanhfast(xi[600 + d] + r * __ldcg(G2row + 600 + d));
            float Cc = (1.f - z) * nn + z * Md;
            float r2 = sigf(__ldcg(G2row + 900 + d)  + xp[d]);
            float z2 = sigf(__ldcg(G2row + 1200 + d) + xp[300 + d]);
            float n2 = tanhfast(__ldcg(G2row + 1500 + d) + r2 * xp[600 + d]);
            float Pp = (1.f - z2) * n2 + z2 * q[d];
            h1r[d] = Cc + Pp;
        }
    }
}

__global__ void k_concat(const float* __restrict__ feat) {
    int r = blockIdx.x;
    for (int c = threadIdx.x; c < KCAT; c += blockDim.x) {
        float v;
        if (c < 1500) {
            int seg = c / 300, off = c - seg * 300;
            v = g_H[seg * HSZ + r * HID + off];
        } else {
            v = feat[r * EMB + (c - 1500)];
        }
        g_Hcat[r * KCAT + c] = v;
    }
}

extern "C" void kernel_launch(void* const* d_in, const int* in_sizes, int n_in,
                              void* d_out, int out_size) {
    const float* features = (const float*)d_in[0];
    const int*   speakers = (const int*)d_in[1];
    const float* w_in   = (const float*)d_in[2];
    const float* b_in   = (const float*)d_in[3];
    const float* gat_wq = (const float*)d_in[4];
    const float* gat_wk = (const float*)d_in[5];
    const float* gat_b  = (const float*)d_in[6];
    const float* wr0    = (const float*)d_in[7];
    const float* wr1    = (const float*)d_in[8];
    const float* wih_c  = (const float*)d_in[9];
    const float* whh_c  = (const float*)d_in[10];
    const float* bih_c  = (const float*)d_in[11];
    const float* bhh_c  = (const float*)d_in[12];
    const float* wih_p  = (const float*)d_in[13];
    const float* whh_p  = (const float*)d_in[14];
    const float* bih_p  = (const float*)d_in[15];
    const float* bhh_p  = (const float*)d_in[16];
    const float* w1 = (const float*)d_in[17];
    const float* b1 = (const float*)d_in[18];
    const float* w2 = (const float*)d_in[19];
    const float* b2 = (const float*)d_in[20];
    const float* w3 = (const float*)d_in[21];
    const float* b3 = (const float*)d_in[22];

    float *H, *XIPp, *WXp, *bXp, *Geffp, *uTp, *G2p, *Hcatp, *h1p, *h2p;
    int *startp;
    cudaGetSymbolAddress((void**)&H,     g_H);
    cudaGetSymbolAddress((void**)&XIPp,  g_XIP);
    cudaGetSymbolAddress((void**)&WXp,   g_WX);
    cudaGetSymbolAddress((void**)&bXp,   g_bX);
    cudaGetSymbolAddress((void**)&Geffp, g_Geff);
    cudaGetSymbolAddress((void**)&uTp,   g_uT);
    cudaGetSymbolAddress((void**)&G2p,   g_G2);
    cudaGetSymbolAddress((void**)&startp,g_start);
    cudaGetSymbolAddress((void**)&Hcatp, g_Hcat);
    cudaGetSymbolAddress((void**)&h1p,   g_h1);
    cudaGetSymbolAddress((void**)&h2p,   g_h2);

    cudaFuncSetAttribute(persist_layer,
                         cudaFuncAttributeMaxDynamicSharedMemorySize,
                         DSMEM_B);

    const int MROWS = BATCH * NSEQ;
    const int PREP_GRID = EW_BLOCKS + GEFF_TX * GEFF_TY;

    for (int l = 0; l < 4; l++) {
        k_prep2<<<PREP_GRID, 256>>>(
            speakers,
            wih_c + l * G3 * HID, whh_p + l * G3 * HID,
            bih_c + l * G3, bhh_p + l * G3,
            whh_c + l * G3 * HID, wih_p + l * G3 * HID,
            wr0 + l * HID * HID, wr1 + l * HID * HID);

        if (l == 0) {
            gemm8x8<<<dim3((HID + 127) / 128, MROWS / 128), 256>>>(
                features, w_in, b_in, H, MROWS, HID, EMB, 1);
        }
        const float* Hin = H + l * HSZ;
        float* H1 = H + (l + 1) * HSZ;

        gemm8x8<<<dim3((1800 + 127) / 128, MROWS / 128), 256>>>(
            Hin, WXp, bXp, XIPp, MROWS, 1800, HID, 0);

        persist_layer<<<NCTA, 256, DSMEM_B>>>(
            Hin, H1, XIPp, gat_wq + l * HID, gat_wk + l * HID, gat_b, l,
            speakers, startp, bhh_c + l * G3, bih_p + l * G3, Geffp, uTp, G2p);
    }

    k_concat<<<MROWS, 256>>>(features);

    gemm8x8<<<dim3((HID + 127) / 128, MROWS / 128), 256>>>(
        Hcatp, w1, b1, h1p, MROWS, HID, KCAT, 1);
    gemm8x8<<<dim3((HID + 127) / 128, MROWS / 128), 256>>>(
        h1p, w2, b2, h2p, MROWS, HID, HID, 1);
    gemm8x8<<<dim3(1, MROWS / 128), 256>>>(
        h2p, w3, b3, (float*)d_out, MROWS, 7, HID, 0);
}

// round 15
// speedup vs baseline: 1.6987x; 1.0839x over previous
#include <cuda_runtime.h>
#include <math.h>

#define HID   300
#define G3    900
#define NSEQ  64
#define BATCH 64
#define EMB   1024
#define KCAT  2524
#define HSZ   (BATCH*NSEQ*HID)
#define NCTA  132
#define GEFFN 2100
#define G2LD  2112
#define SW64_N 9600                   /* u64 duplicated weight pairs */
#define SP_N   4096                   /* u64 partials */
#define DSMEM_B ((SW64_N + SP_N) * 8) /* 109568 bytes */
#define EW_BLOCKS 704
#define GEFF_TX 10
#define GEFF_TY 29

__device__ float g_H[5 * HSZ];
__device__ float g_XIP[BATCH * NSEQ * 1800];   // [XI | XP] per row
__device__ float g_WX[1800 * HID];             // [wih_c ; whh_p]
__device__ float g_bX[1800];                   // [bih_c ; bhh_p]
__device__ float g_Geff[GEFFN * 600];          // rows 0..1799: WG@Wr2, 1800..2099: Wr2
__device__ float g_uT[600 * BATCH];            // uT[d*64 + b]
__device__ float g_G2[BATCH * G2LD];           // per-batch row-major: G2[b*2112 + n]
__device__ int   g_start[BATCH * NSEQ];
__device__ float g_h1[BATCH * NSEQ * HID];
__device__ float g_h2[BATCH * NSEQ * HID];

__device__ volatile unsigned g_ucnt;   // A arrivals (u ready), 64/step
__device__ volatile unsigned g_gcnt;   // all arrivals (G2 ready), 132/step

__device__ __forceinline__ float sigf(float x) {
    return __fdividef(1.f, 1.f + __expf(-x));
}
__device__ __forceinline__ float tanhfast(float x) {
    return __fdividef(2.f, 1.f + __expf(-2.f * x)) - 1.f;
}

__device__ __forceinline__ float bsum(float v, float* s8) {
    int tid = threadIdx.x;
#pragma unroll
    for (int o = 16; o > 0; o >>= 1) v += __shfl_xor_sync(0xffffffffu, v, o);
    if ((tid & 31) == 0) s8[tid >> 5] = v;
    __syncthreads();
    if (tid < 32) {
        float t = (tid < 8) ? s8[tid] : 0.f;
#pragma unroll
        for (int o = 4; o > 0; o >>= 1) t += __shfl_xor_sync(0xffffffffu, t, o);
        if (tid == 0) s8[0] = t;
    }
    __syncthreads();
    float r = s8[0];
    __syncthreads();
    return r;
}

// release-red: publishes all CTA writes that happen-before (via bar.sync) this op
__device__ __forceinline__ void red_rel(volatile unsigned* p) {
    asm volatile("red.release.gpu.global.add.u32 [%0], %1;"
                 :: "l"((const void*)p), "r"(1u) : "memory");
}
__device__ __forceinline__ unsigned ld_acq(volatile unsigned* p) {
    unsigned v;
    asm volatile("ld.acquire.gpu.global.u32 %0, [%1];"
                 : "=r"(v) : "l"((const void*)p) : "memory");
    return v;
}
__device__ __forceinline__ void waitge(volatile unsigned* p, unsigned t) {
    while (ld_acq(p) < t) { }
}

// ---- merged prep: starts + WX/bX/Geff-bottom elementwise + Geff-top GEMM ----
__global__ void __launch_bounds__(256) k_prep2(
    const int* __restrict__ spk,
    const float* __restrict__ wih_c, const float* __restrict__ whh_p,
    const float* __restrict__ bih_c, const float* __restrict__ bhh_p,
    const float* __restrict__ whh_c, const float* __restrict__ wih_p,
    const float* __restrict__ wr0,   const float* __restrict__ wr1)
{
    int bid = blockIdx.x;
    if (bid < EW_BLOCKS) {
        for (int idx = bid * 256 + threadIdx.x; idx < 1800 * 300; idx += EW_BLOCKS * 256) {
            int n = idx / 300, d = idx - n * 300;
            g_WX[idx] = (n < 900) ? wih_c[n * 300 + d] : whh_p[(n - 900) * 300 + d];
            if (idx < 300 * 600) {
                int d2 = idx / 600, e = idx - d2 * 600;
                g_Geff[(1800 + d2) * 600 + e] =
                    (e < 300) ? wr0[d2 * 300 + e] : wr1[d2 * 300 + (e - 300)];
            }
            if (idx < 1800) g_bX[idx] = (idx < 900) ? bih_c[idx] : bhh_p[idx - 900];
            if (idx < 4096) {
                int b = idx >> 6, i = idx & 63;
                int s = spk[b * NSEQ + i];
                int last = -1;
                for (int j = 0; j < i; j++)
                    if (spk[b * NSEQ + j] == s) last = j;
                g_start[b * NSEQ + i] = last > 0 ? last : 0;
            }
            if (idx == 0) { g_ucnt = 0; g_gcnt = 0; }
        }
        return;
    }
    int gb2 = bid - EW_BLOCKS;
    int n0 = (gb2 / GEFF_TX) * 64, e0 = (gb2 % GEFF_TX) * 64;
    __shared__ float sA[16][65];
    __shared__ float sB[16][65];
    int tid = threadIdx.x;
    int tm = tid >> 4, tn = tid & 15;
    int lr = tid >> 2, lk = (tid & 3) * 4;
    float acc[4][4];
#pragma unroll
    for (int i = 0; i < 4; i++)
#pragma unroll
        for (int j = 0; j < 4; j++) acc[i][j] = 0.f;
    for (int k0 = 0; k0 < 300; k0 += 16) {
#pragma unroll
        for (int q = 0; q < 4; q++) {
            int k = k0 + lk + q;
            int n = n0 + lr;
            float av = 0.f;
            if (k < 300 && n < 1800)
                av = (n < 900) ? whh_c[n * 300 + k] : wih_p[(n - 900) * 300 + k];
            sA[lk + q][lr] = av;
            int e = e0 + lr;
            float bv = 0.f;
            if (k < 300 && e < 600)
                bv = (e < 300) ? wr0[k * 300 + e] : wr1[k * 300 + (e - 300)];
            sB[lk + q][lr] = bv;
        }
        __syncthreads();
#pragma unroll
        for (int kk = 0; kk < 16; kk++) {
            float a[4], bv[4];
#pragma unroll
            for (int i = 0; i < 4; i++) { a[i] = sA[kk][tm * 4 + i]; bv[i] = sB[kk][tn * 4 + i]; }
#pragma unroll
            for (int i = 0; i < 4; i++)
#pragma unroll
                for (int j = 0; j < 4; j++) acc[i][j] += a[i] * bv[j];
        }
        __syncthreads();
    }
#pragma unroll
    for (int i = 0; i < 4; i++) {
        int n = n0 + tm * 4 + i;
        if (n >= 1800) continue;
#pragma unroll
        for (int j = 0; j < 4; j++) {
            int e = e0 + tn * 4 + j;
            if (e >= 600) continue;
            g_Geff[(size_t)n * 600 + e] = acc[i][j];
        }
    }
}

// ---- fetch macro for gemm8x8 prefetch double-buffer ----
#define GFETCH(K0) do { \
    int kb = (K0) + lk; \
    pA0 = make_float4(0.f, 0.f, 0.f, 0.f); pA1 = pA0; pB0 = pA0; pB1 = pA0; \
    int gm0 = m0 + lr, gm1 = m0 + lr + 64; \
    int gn0 = n0 + lr, gn1 = n0 + lr + 64; \
    if (kb + 3 < K) { \
        if (gm0 < M) pA0 = *(const float4*)(A + (size_t)gm0 * K + kb); \
        if (gm1 < M) pA1 = *(const float4*)(A + (size_t)gm1 * K + kb); \
        if (gn0 < N) pB0 = *(const float4*)(B + (size_t)gn0 * K + kb); \
        if (gn1 < N) pB1 = *(const float4*)(B + (size_t)gn1 * K + kb); \
    } else { \
        if (gm0 < M) { if (kb < K) pA0.x = A[(size_t)gm0*K+kb]; if (kb+1 < K) pA0.y = A[(size_t)gm0*K+kb+1]; if (kb+2 < K) pA0.z = A[(size_t)gm0*K+kb+2]; } \
        if (gm1 < M) { if (kb < K) pA1.x = A[(size_t)gm1*K+kb]; if (kb+1 < K) pA1.y = A[(size_t)gm1*K+kb+1]; if (kb+2 < K) pA1.z = A[(size_t)gm1*K+kb+2]; } \
        if (gn0 < N) { if (kb < K) pB0.x = B[(size_t)gn0*K+kb]; if (kb+1 < K) pB0.y = B[(size_t)gn0*K+kb+1]; if (kb+2 < K) pB0.z = B[(size_t)gn0*K+kb+2]; } \
        if (gn1 < N) { if (kb < K) pB1.x = B[(size_t)gn1*K+kb]; if (kb+1 < K) pB1.y = B[(size_t)gn1*K+kb+1]; if (kb+2 < K) pB1.z = B[(size_t)gn1*K+kb+2]; } \
    } \
} while (0)

#define GEMM_TILE_STORE() do { \
    sA[(lk + 0) * 132 + lr] = pA0.x; sA[(lk + 1) * 132 + lr] = pA0.y; \
    sA[(lk + 2) * 132 + lr] = pA0.z; sA[(lk + 3) * 132 + lr] = pA0.w; \
    sA[(lk + 0) * 132 + 64 + lr] = pA1.x; sA[(lk + 1) * 132 + 64 + lr] = pA1.y; \
    sA[(lk + 2) * 132 + 64 + lr] = pA1.z; sA[(lk + 3) * 132 + 64 + lr] = pA1.w; \
    sB[(lk + 0) * 132 + lr] = pB0.x; sB[(lk + 1) * 132 + lr] = pB0.y; \
    sB[(lk + 2) * 132 + lr] = pB0.z; sB[(lk + 3) * 132 + lr] = pB0.w; \
    sB[(lk + 0) * 132 + 64 + lr] = pB1.x; sB[(lk + 1) * 132 + 64 + lr] = pB1.y; \
    sB[(lk + 2) * 132 + 64 + lr] = pB1.z; sB[(lk + 3) * 132 + 64 + lr] = pB1.w; \
} while (0)

#define GEMM_TILE_MATH() do { \
    _Pragma("unroll") \
    for (int kk = 0; kk < 16; kk++) { \
        float4 xa0 = *(const float4*)(sA + kk * 132 + tm * 4); \
        float4 xa1 = *(const float4*)(sA + kk * 132 + 64 + tm * 4); \
        float4 xb0 = *(const float4*)(sB + kk * 132 + tn * 4); \
        float4 xb1 = *(const float4*)(sB + kk * 132 + 64 + tn * 4); \
        unsigned long long bp[4]; \
        asm("mov.b64 %0,{%1,%2};" : "=l"(bp[0]) : "f"(xb0.x), "f"(xb0.y)); \
        asm("mov.b64 %0,{%1,%2};" : "=l"(bp[1]) : "f"(xb0.z), "f"(xb0.w)); \
        asm("mov.b64 %0,{%1,%2};" : "=l"(bp[2]) : "f"(xb1.x), "f"(xb1.y)); \
        asm("mov.b64 %0,{%1,%2};" : "=l"(bp[3]) : "f"(xb1.z), "f"(xb1.w)); \
        float a[8] = {xa0.x, xa0.y, xa0.z, xa0.w, xa1.x, xa1.y, xa1.z, xa1.w}; \
        _Pragma("unroll") \
        for (int i = 0; i < 8; i++) { \
            unsigned long long ap; \
            asm("mov.b64 %0,{%1,%1};" : "=l"(ap) : "f"(a[i])); \
            _Pragma("unroll") \
            for (int j = 0; j < 4; j++) \
                asm("fma.rn.f32x2 %0,%1,%2,%0;" : "+l"(acc2[i][j]) : "l"(ap), "l"(bp[j])); \
        } \
    } \
} while (0)

#define GEMM_EPILOGUE() do { \
    _Pragma("unroll") \
    for (int i = 0; i < 8; i++) { \
        int m = m0 + ((i < 4) ? (tm * 4 + i) : (64 + tm * 4 + i - 4)); \
        if (m >= M) continue; \
        _Pragma("unroll") \
        for (int j = 0; j < 8; j++) { \
            int n = n0 + ((j < 4) ? (tn * 4 + j) : (64 + tn * 4 + j - 4)); \
            if (n >= N) continue; \
            float lo, hi; \
            asm("mov.b64 {%0,%1},%2;" : "=f"(lo), "=f"(hi) : "l"(acc2[i][j >> 1])); \
            float v = ((j & 1) ? hi : lo) + (bias ? bias[n] : 0.f); \
            if (relu) v = fmaxf(v, 0.f); \
            C[(size_t)m * N + n] = v; \
        } \
    } \
} while (0)

// ---- dense GEMM: C=A@B^T+bias (opt relu). BM=128,BN=128,BK=16, 8x8, f32x2 ----
__global__ void __launch_bounds__(256, 2) gemm8x8(
    const float* __restrict__ A, const float* __restrict__ B,
    const float* __restrict__ bias, float* __restrict__ C,
    int M, int N, int K, int relu)
{
    __shared__ float sA[16 * 132];
    __shared__ float sB[16 * 132];
    int tid = threadIdx.x;
    int m0 = blockIdx.y * 128, n0 = blockIdx.x * 128;
    int tm = tid & 15, tn = tid >> 4;
    int lr = tid >> 2, lk = (tid & 3) * 4;
    unsigned long long acc2[8][4];
#pragma unroll
    for (int i = 0; i < 8; i++)
#pragma unroll
        for (int j = 0; j < 4; j++) acc2[i][j] = 0ull;

    float4 pA0, pA1, pB0, pB1;
    int T = (K + 15) / 16;
    GFETCH(0);
    for (int t = 0; t < T; t++) {
        GEMM_TILE_STORE();
        __syncthreads();
        if (t + 1 < T) GFETCH((t + 1) * 16);
        GEMM_TILE_MATH();
        __syncthreads();
    }
    GEMM_EPILOGUE();
}

// ---- head GEMM: A is virtual [4096, 2524] = [H0..H4 | features] ----
__device__ __forceinline__ float4 head_fetch(
    const float* __restrict__ Hbase, const float* __restrict__ feat,
    int m, int kb)
{
    if (kb < 1500) {
        int seg = kb / 300, off = kb - seg * 300;
        return *(const float4*)(Hbase + (size_t)seg * HSZ + (size_t)m * 300 + off);
    }
    return *(const float4*)(feat + (size_t)m * EMB + (kb - 1500));
}

__global__ void __launch_bounds__(256, 2) gemm_head(
    const float* __restrict__ Hbase, const float* __restrict__ feat,
    const float* __restrict__ B,
    const float* __restrict__ bias, float* __restrict__ C,
    int M, int N, int K, int relu)
{
    __shared__ float sA[16 * 132];
    __shared__ float sB[16 * 132];
    int tid = threadIdx.x;
    int m0 = blockIdx.y * 128, n0 = blockIdx.x * 128;
    int tm = tid & 15, tn = tid >> 4;
    int lr = tid >> 2, lk = (tid & 3) * 4;
    unsigned long long acc2[8][4];
#pragma unroll
    for (int i = 0; i < 8; i++)
#pragma unroll
        for (int j = 0; j < 4; j++) acc2[i][j] = 0ull;

    float4 pA0, pA1, pB0, pB1;
    int T = (K + 15) / 16;

#define HFETCH(K0) do { \
    int kb = (K0) + lk; \
    pA0 = make_float4(0.f, 0.f, 0.f, 0.f); pA1 = pA0; pB0 = pA0; pB1 = pA0; \
    int gm0 = m0 + lr, gm1 = m0 + lr + 64; \
    int gn0 = n0 + lr, gn1 = n0 + lr + 64; \
    if (kb < K) { \
        pA0 = head_fetch(Hbase, feat, gm0, kb); \
        pA1 = head_fetch(Hbase, feat, gm1, kb); \
        if (gn0 < N) pB0 = *(const float4*)(B + (size_t)gn0 * K + kb); \
        if (gn1 < N) pB1 = *(const float4*)(B + (size_t)gn1 * K + kb); \
    } \
} while (0)

    HFETCH(0);
    for (int t = 0; t < T; t++) {
        GEMM_TILE_STORE();
        __syncthreads();
        if (t + 1 < T) HFETCH((t + 1) * 16);
        GEMM_TILE_MATH();
        __syncthreads();
    }
    GEMM_EPILOGUE();
#undef HFETCH
}

// ---------------- persistent per-layer scan kernel ----------------
__global__ void __launch_bounds__(256, 1) persist_layer(
    const float* __restrict__ Hin, float* __restrict__ H1,
    const float* __restrict__ XIP,
    const float* __restrict__ wq, const float* __restrict__ wk,
    const float* __restrict__ gatb, int layer,
    const int* __restrict__ spk, const int* __restrict__ start,
    const float* __restrict__ bhh_c, const float* __restrict__ bih_p,
    const float* __restrict__ Geff, float* __restrict__ uT,
    float* __restrict__ G2)
{
    extern __shared__ float dsm[];
    unsigned long long* sW64 = (unsigned long long*)dsm;     // 9600 u64 dup pairs
    unsigned long long* sP   = sW64 + SW64_N;                // 4096 u64 partials

    __shared__ float s8[8];
    __shared__ float s_w0[64];
    __shared__ float s_w1[64];
    __shared__ float s_kdot[64];
    __shared__ float s_qd[64];
    __shared__ float s_bias[16];

    const int tid = threadIdx.x;
    const int cta = blockIdx.x;
    const int b = cta;
    const int n0 = cta * 16;
    const int wid = tid >> 5, lid = tid & 31;

    for (int idx = tid; idx < SW64_N; idx += 256) {
        int k = idx >> 4, r = idx & 15;
        int n = n0 + r;
        float w = (n < GEFFN) ? Geff[(size_t)n * 600 + k] : 0.f;
        unsigned long long p;
        asm("mov.b64 %0,{%1,%1};" : "=l"(p) : "f"(w));
        sW64[idx] = p;
    }
    if (tid < 16) {
        int n = n0 + tid;
        float bv = 0.f;
        if (n < 900) bv = bhh_c[n];
        else if (n < 1800) bv = bih_p[n - 900];
        s_bias[tid] = bv;
    }

    const int bg = tid & 15, rg = (tid >> 4) & 1, ks = tid >> 5;
    const float* G2row = G2 + (size_t)b * G2LD;
    const ulonglong2* uTv = (const ulonglong2*)uT;
    const unsigned sWaddr = (unsigned)__cvta_generic_to_shared(sW64)
                          + (unsigned)(((ks * 75) * 16 + rg * 8) * 8);

    const float gb = gatb[layer];

    if (cta < 64) {
        for (int i = wid; i < 64; i += 8) {
            float p = 0.f;
            const float* hr = Hin + ((size_t)b * NSEQ + i) * HID;
            for (int j = lid; j < HID; j += 32) p += hr[j] * wq[j];
#pragma unroll
            for (int o = 16; o > 0; o >>= 1) p += __shfl_xor_sync(0xffffffffu, p, o);
            if (lid == 0) s_qd[i] = p + gb;
        }
        const float* xi = XIP + (size_t)b * NSEQ * 1800;
        const float* xp = xi + 900;
        const float* x0 = Hin + (size_t)b * NSEQ * HID;
        float* h1 = H1 + (size_t)b * NSEQ * HID;
        float kp = 0.f;
        for (int d = tid; d < HID; d += 256) {
            float r  = sigf(xi[d] + bhh_c[d]);
            float z  = sigf(xi[300 + d] + bhh_c[300 + d]);
            float nn = tanhfast(xi[600 + d] + r * bhh_c[600 + d]);
            float C0 = (1.f - z) * nn;
            float r2 = sigf(bih_p[d] + xp[d]);
            float z2 = sigf(bih_p[300 + d] + xp[300 + d]);
            float n2 = tanhfast(bih_p[600 + d] + r2 * xp[600 + d]);
            float P0 = (1.f - z2) * n2 + z2 * x0[d];
            float h = C0 + P0;
            h1[d] = h;
            kp += h * wk[d];
        }
        float kss = bsum(kp, s8);
        if (tid == 0) s_kdot[0] = kss;
    }
    __syncthreads();

    for (int i = 1; i <= 63; i++) {
        // ===== phase A (CTAs 0..63): GRU row i-1, attention -> uT(i) =====
        if (cta < 64) {
            if (i >= 2) {
                int row = i - 1;
                const float* xi = XIP + ((size_t)b * NSEQ + row) * 1800;
                const float* xp = xi + 900;
                const float* q  = Hin + ((size_t)b * NSEQ + row) * HID;
                float* h1r = H1 + ((size_t)b * NSEQ + row) * HID;
                float pxi[2][3], pxp[2][3], pq[2];
#pragma unroll
                for (int t = 0; t < 2; t++) {
                    int d = tid + t * 256;
                    if (d < HID) {
                        pxi[t][0] = xi[d]; pxi[t][1] = xi[300 + d]; pxi[t][2] = xi[600 + d];
                        pxp[t][0] = xp[d]; pxp[t][1] = xp[300 + d]; pxp[t][2] = xp[600 + d];
                        pq[t] = q[d];
                    }
                }
                if (tid == 0) waitge(&g_gcnt, NCTA * (unsigned)(i - 1));
                __syncthreads();
                float kp = 0.f;
#pragma unroll
                for (int t = 0; t < 2; t++) {
                    int d = tid + t * 256;
                    if (d < HID) {
                        float Md = __ldcg(G2row + 1800 + d);
                        float r  = sigf(pxi[t][0] + __ldcg(G2row + d));
                        float z  = sigf(pxi[t][1] + __ldcg(G2row + 300 + d));
                        float nn = tanhfast(pxi[t][2] + r * __ldcg(G2row + 600 + d));
                        float Cc = (1.f - z) * nn + z * Md;
                        float r2 = sigf(__ldcg(G2row + 900 + d)  + pxp[t][0]);
                        float z2 = sigf(__ldcg(G2row + 1200 + d) + pxp[t][1]);
                        float n2 = tanhfast(__ldcg(G2row + 1500 + d) + r2 * pxp[t][2]);
                        float Pp = (1.f - z2) * n2 + z2 * pq[t];
                        float h = Cc + Pp;
                        h1r[d] = h;
                        kp += h * wk[d];
                    }
                }
                float kss = bsum(kp, s8);
                if (tid == 0) s_kdot[row] = kss;
                __syncthreads();
            }
            int st = start[b * NSEQ + i];
            int cnt = i - st;
            if (tid < 32) {
                int spki = spk[b * NSEQ + i];
                float qd = s_qd[i];
                float a1 = (tid < cnt)      ? qd + s_kdot[st + tid]      : -1e30f;
                float a2 = (tid + 32 < cnt) ? qd + s_kdot[st + tid + 32] : -1e30f;
                float m = fmaxf(a1, a2);
#pragma unroll
                for (int o = 16; o > 0; o >>= 1) m = fmaxf(m, __shfl_xor_sync(0xffffffffu, m, o));
                float e1 = (tid < cnt)      ? __expf(a1 - m) : 0.f;
                float e2 = (tid + 32 < cnt) ? __expf(a2 - m) : 0.f;
                float s = e1 + e2;
#pragma unroll
                for (int o = 16; o > 0; o >>= 1) s += __shfl_xor_sync(0xffffffffu, s, o);
                float inv = __fdividef(1.f, s);
                if (tid < cnt) {
                    float w = e1 * inv;
                    float smv = (spk[b * NSEQ + st + tid] == spki) ? 1.f : 0.f;
                    s_w0[tid] = w * smv;
                    s_w1[tid] = w * (1.f - smv);
                }
                if (tid + 32 < cnt) {
                    float w = e2 * inv;
                    float smv = (spk[b * NSEQ + st + tid + 32] == spki) ? 1.f : 0.f;
                    s_w0[tid + 32] = w * smv;
                    s_w1[tid + 32] = w * (1.f - smv);
                }
            }
            __syncthreads();
            for (int d = tid; d < 600; d += 256) {
                int ei = (d < 300) ? d : d - 300;
                const float* wt = (d < 300) ? s_w0 : s_w1;
                const float* base = H1 + ((size_t)b * NSEQ + st) * HID + ei;
                float acc = 0.f;
                for (int j = 0; j < cnt; j++)
                    acc += wt[j] * base[j * HID];
                __stcg(uT + d * 64 + b, acc);
            }
            __syncthreads();                 // all u-stores sequenced before tid0's release
            if (tid == 0) red_rel(&g_ucnt);
        }
        // ===== all CTAs: wait u(i), then B with direct-L2 u reads =====
        if (tid == 0) waitge(&g_ucnt, 64u * (unsigned)i);
        __syncthreads();

        unsigned long long a01[8], a23[8];
#pragma unroll
        for (int r = 0; r < 8; r++) { a01[r] = 0ull; a23[r] = 0ull; }
        {
            const ulonglong2* up = uTv + (ks * 75) * 16 + bg;
            unsigned wA = sWaddr;
#pragma unroll 5
            for (int kk = 0; kk < 75; kk++) {
                ulonglong2 uv = __ldcg(up);
                up += 16;
                unsigned long long w0, w1, w2, w3, w4, w5, w6, w7;
                asm volatile("ld.shared.v2.u64 {%0,%1},[%2];" : "=l"(w0), "=l"(w1) : "r"(wA));
                asm volatile("ld.shared.v2.u64 {%0,%1},[%2];" : "=l"(w2), "=l"(w3) : "r"(wA + 16u));
                asm volatile("ld.shared.v2.u64 {%0,%1},[%2];" : "=l"(w4), "=l"(w5) : "r"(wA + 32u));
                asm volatile("ld.shared.v2.u64 {%0,%1},[%2];" : "=l"(w6), "=l"(w7) : "r"(wA + 48u));
                wA += 128u;
                asm("fma.rn.f32x2 %0,%1,%2,%0;" : "+l"(a01[0]) : "l"(uv.x), "l"(w0));
                asm("fma.rn.f32x2 %0,%1,%2,%0;" : "+l"(a23[0]) : "l"(uv.y), "l"(w0));
                asm("fma.rn.f32x2 %0,%1,%2,%0;" : "+l"(a01[1]) : "l"(uv.x), "l"(w1));
                asm("fma.rn.f32x2 %0,%1,%2,%0;" : "+l"(a23[1]) : "l"(uv.y), "l"(w1));
                asm("fma.rn.f32x2 %0,%1,%2,%0;" : "+l"(a01[2]) : "l"(uv.x), "l"(w2));
                asm("fma.rn.f32x2 %0,%1,%2,%0;" : "+l"(a23[2]) : "l"(uv.y), "l"(w2));
                asm("fma.rn.f32x2 %0,%1,%2,%0;" : "+l"(a01[3]) : "l"(uv.x), "l"(w3));
                asm("fma.rn.f32x2 %0,%1,%2,%0;" : "+l"(a23[3]) : "l"(uv.y), "l"(w3));
                asm("fma.rn.f32x2 %0,%1,%2,%0;" : "+l"(a01[4]) : "l"(uv.x), "l"(w4));
                asm("fma.rn.f32x2 %0,%1,%2,%0;" : "+l"(a23[4]) : "l"(uv.y), "l"(w4));
                asm("fma.rn.f32x2 %0,%1,%2,%0;" : "+l"(a01[5]) : "l"(uv.x), "l"(w5));
                asm("fma.rn.f32x2 %0,%1,%2,%0;" : "+l"(a23[5]) : "l"(uv.y), "l"(w5));
                asm("fma.rn.f32x2 %0,%1,%2,%0;" : "+l"(a01[6]) : "l"(uv.x), "l"(w6));
                asm("fma.rn.f32x2 %0,%1,%2,%0;" : "+l"(a23[6]) : "l"(uv.y), "l"(w6));
                asm("fma.rn.f32x2 %0,%1,%2,%0;" : "+l"(a01[7]) : "l"(uv.x), "l"(w7));
                asm("fma.rn.f32x2 %0,%1,%2,%0;" : "+l"(a23[7]) : "l"(uv.y), "l"(w7));
            }
        }
#pragma unroll
        for (int r = 0; r < 8; r++) {
            int row = rg * 8 + r;
            sP[((ks * 16 + row) * 16 + bg) * 2 + 0] = a01[r];
            sP[((ks * 16 + row) * 16 + bg) * 2 + 1] = a23[r];
        }
        __syncthreads();
        {
#pragma unroll
            for (int t = 0; t < 2; t++) {
                int o = tid * 2 + t;
                int row = o >> 5, rem = o & 31;
                int bg2 = rem >> 1, p = rem & 1;
                unsigned long long s = sP[(row * 16 + bg2) * 2 + p];
#pragma unroll
                for (int k2 = 1; k2 < 8; k2++) {
                    unsigned long long v = sP[((k2 * 16 + row) * 16 + bg2) * 2 + p];
                    asm("add.rn.f32x2 %0,%1,%2;" : "=l"(s) : "l"(s), "l"(v));
                }
                unsigned long long bp;
                asm("mov.b64 %0,{%1,%1};" : "=l"(bp) : "f"(s_bias[row]));
                asm("add.rn.f32x2 %0,%1,%2;" : "=l"(s) : "l"(s), "l"(bp));
                int n = n0 + row;
                if (n < GEFFN) {
                    float lo, hi;
                    asm("mov.b64 {%0,%1},%2;" : "=f"(lo), "=f"(hi) : "l"(s));
                    int b0 = bg2 * 4 + p * 2;
                    __stcg(G2 + (size_t)b0 * G2LD + n, lo);
                    __stcg(G2 + (size_t)(b0 + 1) * G2LD + n, hi);
                }
            }
        }
        __syncthreads();                     // all G2-stores sequenced before tid0's release
        if (tid == 0) red_rel(&g_gcnt);
    }

    // final GRU update: row 63
    if (cta < 64) {
        if (tid == 0) waitge(&g_gcnt, NCTA * 63u);
        __syncthreads();
        int row = 63;
        const float* xi = XIP + ((size_t)b * NSEQ + row) * 1800;
        const float* xp = xi + 900;
        const float* q  = Hin + ((size_t)b * NSEQ + row) * HID;
        float* h1r = H1 + ((size_t)b * NSEQ + row) * HID;
        for (int d = tid; d < HID; d += 256) {
            float Md = __ldcg(G2row + 1800 + d);
            float r  = sigf(xi[d]       + __ldcg(G2row + d));
            float z  = sigf(xi[300 + d] + __ldcg(G2row + 300 + d));
            float nn = tanhfast(xi[600 + d] + r * __ldcg(G2row + 600 + d));
            float Cc = (1.f - z) * nn + z * Md;
            float r2 = sigf(__ldcg(G2row + 900 + d)  + xp[d]);
            float z2 = sigf(__ldcg(G2row + 1200 + d) + xp[300 + d]);
            float n2 = tanhfast(__ldcg(G2row + 1500 + d) + r2 * xp[600 + d]);
            float Pp = (1.f - z2) * n2 + z2 * q[d];
            h1r[d] = Cc + Pp;
        }
    }
}

extern "C" void kernel_launch(void* const* d_in, const int* in_sizes, int n_in,
                              void* d_out, int out_size) {
    const float* features = (const float*)d_in[0];
    const int*   speakers = (const int*)d_in[1];
    const float* w_in   = (const float*)d_in[2];
    const float* b_in   = (const float*)d_in[3];
    const float* gat_wq = (const float*)d_in[4];
    const float* gat_wk = (const float*)d_in[5];
    const float* gat_b  = (const float*)d_in[6];
    const float* wr0    = (const float*)d_in[7];
    const float* wr1    = (const float*)d_in[8];
    const float* wih_c  = (const float*)d_in[9];
    const float* whh_c  = (const float*)d_in[10];
    const float* bih_c  = (const float*)d_in[11];
    const float* bhh_c  = (const float*)d_in[12];
    const float* wih_p  = (const float*)d_in[13];
    const float* whh_p  = (const float*)d_in[14];
    const float* bih_p  = (const float*)d_in[15];
    const float* bhh_p  = (const float*)d_in[16];
    const float* w1 = (const float*)d_in[17];
    const float* b1 = (const float*)d_in[18];
    const float* w2 = (const float*)d_in[19];
    const float* b2 = (const float*)d_in[20];
    const float* w3 = (const float*)d_in[21];
    const float* b3 = (const float*)d_in[22];

    float *H, *XIPp, *WXp, *bXp, *Geffp, *uTp, *G2p, *h1p, *h2p;
    int *startp;
    cudaGetSymbolAddress((void**)&H,     g_H);
    cudaGetSymbolAddress((void**)&XIPp,  g_XIP);
    cudaGetSymbolAddress((void**)&WXp,   g_WX);
    cudaGetSymbolAddress((void**)&bXp,   g_bX);
    cudaGetSymbolAddress((void**)&Geffp, g_Geff);
    cudaGetSymbolAddress((void**)&uTp,   g_uT);
    cudaGetSymbolAddress((void**)&G2p,   g_G2);
    cudaGetSymbolAddress((void**)&startp,g_start);
    cudaGetSymbolAddress((void**)&h1p,   g_h1);
    cudaGetSymbolAddress((void**)&h2p,   g_h2);

    cudaFuncSetAttribute(persist_layer,
                         cudaFuncAttributeMaxDynamicSharedMemorySize,
                         DSMEM_B);

    const int MROWS = BATCH * NSEQ;
    const int PREP_GRID = EW_BLOCKS + GEFF_TX * GEFF_TY;

    for (int l = 0; l < 4; l++) {
        k_prep2<<<PREP_GRID, 256>>>(
            speakers,
            wih_c + l * G3 * HID, whh_p + l * G3 * HID,
            bih_c + l * G3, bhh_p + l * G3,
            whh_c + l * G3 * HID, wih_p + l * G3 * HID,
            wr0 + l * HID * HID, wr1 + l * HID * HID);

        if (l == 0) {
            gemm8x8<<<dim3((HID + 127) / 128, MROWS / 128), 256>>>(
                features, w_in, b_in, H, MROWS, HID, EMB, 1);
        }
        const float* Hin = H + l * HSZ;
        float* H1 = H + (l + 1) * HSZ;

        gemm8x8<<<dim3((1800 + 127) / 128, MROWS / 128), 256>>>(
            Hin, WXp, bXp, XIPp, MROWS, 1800, HID, 0);

        persist_layer<<<NCTA, 256, DSMEM_B>>>(
            Hin, H1, XIPp, gat_wq + l * HID, gat_wk + l * HID, gat_b, l,
            speakers, startp, bhh_c + l * G3, bih_p + l * G3, Geffp, uTp, G2p);
    }

    // head: h1 = relu([H|feat] @ w1^T + b1) with fused concat
    gemm_head<<<dim3((HID + 127) / 128, MROWS / 128), 256>>>(
        H, features, w1, b1, h1p, MROWS, HID, KCAT, 1);
    gemm8x8<<<dim3((HID + 127) / 128, MROWS / 128), 256>>>(
        h1p, w2, b2, h2p, MROWS, HID, HID, 1);
    gemm8x8<<<dim3(1, MROWS / 128), 256>>>(
        h2p, w3, b3, (float*)d_out, MROWS, 7, HID, 0);
}

// round 16
// speedup vs baseline: 1.8982x; 1.1174x over previous
#include <cuda_runtime.h>
#include <math.h>

#define HID   300
#define G3    900
#define NSEQ  64
#define BATCH 64
#define EMB   1024
#define KCAT  2524
#define HSZ   (BATCH*NSEQ*HID)
#define NCTA  132
#define NTHR  384
#define GEFFN 2100
#define G2LD  2112
#define SW64_N 9600                   /* u64 duplicated weight pairs */
#define SP_N   6144                   /* u64 partials: 12 slices x 16 rows x 16 bg x 2 */
#define DSMEM_B ((SW64_N + SP_N) * 8) /* 125952 bytes */
#define EW_BLOCKS 704
#define GEFF_TX 10
#define GEFF_TY 29

__device__ float g_H[5 * HSZ];
__device__ float g_XIP[BATCH * NSEQ * 1800];   // [XI | XP] per row
__device__ float g_WX[1800 * HID];             // [wih_c ; whh_p]
__device__ float g_bX[1800];                   // [bih_c ; bhh_p]
__device__ float g_Geff[GEFFN * 600];          // rows 0..1799: WG@Wr2, 1800..2099: Wr2
__device__ float g_uT[600 * BATCH];            // uT[d*64 + b]
__device__ float g_G2[BATCH * G2LD];           // per-batch row-major: G2[b*2112 + n]
__device__ int   g_start[BATCH * NSEQ];
__device__ float g_h1[BATCH * NSEQ * HID];
__device__ float g_h2[BATCH * NSEQ * HID];

__device__ volatile unsigned g_ucnt;   // A arrivals (u ready), 64/step
__device__ volatile unsigned g_gcnt;   // all arrivals (G2 ready), 132/step

__device__ __forceinline__ float sigf(float x) {
    return __fdividef(1.f, 1.f + __expf(-x));
}
__device__ __forceinline__ float tanhfast(float x) {
    return __fdividef(2.f, 1.f + __expf(-2.f * x)) - 1.f;
}

// 384-thread block sum: 12 warp partials
__device__ __forceinline__ float bsum384(float v, float* s12) {
    int tid = threadIdx.x;
#pragma unroll
    for (int o = 16; o > 0; o >>= 1) v += __shfl_xor_sync(0xffffffffu, v, o);
    if ((tid & 31) == 0) s12[tid >> 5] = v;
    __syncthreads();
    if (tid < 32) {
        float t = (tid < 12) ? s12[tid] : 0.f;
#pragma unroll
        for (int o = 8; o > 0; o >>= 1) t += __shfl_xor_sync(0xffffffffu, t, o);
        if (tid == 0) s12[0] = t;
    }
    __syncthreads();
    float r = s12[0];
    __syncthreads();
    return r;
}

// release-red: publishes all CTA writes that happen-before (via bar.sync) this op
__device__ __forceinline__ void red_rel(volatile unsigned* p) {
    asm volatile("red.release.gpu.global.add.u32 [%0], %1;"
                 :: "l"((const void*)p), "r"(1u) : "memory");
}
__device__ __forceinline__ unsigned ld_acq(volatile unsigned* p) {
    unsigned v;
    asm volatile("ld.acquire.gpu.global.u32 %0, [%1];"
                 : "=r"(v) : "l"((const void*)p) : "memory");
    return v;
}
__device__ __forceinline__ void waitge(volatile unsigned* p, unsigned t) {
    while (ld_acq(p) < t) { }
}

// ---- merged prep: starts + WX/bX/Geff-bottom elementwise + Geff-top GEMM ----
__global__ void __launch_bounds__(256) k_prep2(
    const int* __restrict__ spk,
    const float* __restrict__ wih_c, const float* __restrict__ whh_p,
    const float* __restrict__ bih_c, const float* __restrict__ bhh_p,
    const float* __restrict__ whh_c, const float* __restrict__ wih_p,
    const float* __restrict__ wr0,   const float* __restrict__ wr1)
{
    int bid = blockIdx.x;
    if (bid < EW_BLOCKS) {
        for (int idx = bid * 256 + threadIdx.x; idx < 1800 * 300; idx += EW_BLOCKS * 256) {
            int n = idx / 300, d = idx - n * 300;
            g_WX[idx] = (n < 900) ? wih_c[n * 300 + d] : whh_p[(n - 900) * 300 + d];
            if (idx < 300 * 600) {
                int d2 = idx / 600, e = idx - d2 * 600;
                g_Geff[(1800 + d2) * 600 + e] =
                    (e < 300) ? wr0[d2 * 300 + e] : wr1[d2 * 300 + (e - 300)];
            }
            if (idx < 1800) g_bX[idx] = (idx < 900) ? bih_c[idx] : bhh_p[idx - 900];
            if (idx < 4096) {
                int b = idx >> 6, i = idx & 63;
                int s = spk[b * NSEQ + i];
                int last = -1;
                for (int j = 0; j < i; j++)
                    if (spk[b * NSEQ + j] == s) last = j;
                g_start[b * NSEQ + i] = last > 0 ? last : 0;
            }
            if (idx == 0) { g_ucnt = 0; g_gcnt = 0; }
        }
        return;
    }
    int gb2 = bid - EW_BLOCKS;
    int n0 = (gb2 / GEFF_TX) * 64, e0 = (gb2 % GEFF_TX) * 64;
    __shared__ float sA[16][65];
    __shared__ float sB[16][65];
    int tid = threadIdx.x;
    int tm = tid >> 4, tn = tid & 15;
    int lr = tid >> 2, lk = (tid & 3) * 4;
    float acc[4][4];
#pragma unroll
    for (int i = 0; i < 4; i++)
#pragma unroll
        for (int j = 0; j < 4; j++) acc[i][j] = 0.f;
    for (int k0 = 0; k0 < 300; k0 += 16) {
#pragma unroll
        for (int q = 0; q < 4; q++) {
            int k = k0 + lk + q;
            int n = n0 + lr;
            float av = 0.f;
            if (k < 300 && n < 1800)
                av = (n < 900) ? whh_c[n * 300 + k] : wih_p[(n - 900) * 300 + k];
            sA[lk + q][lr] = av;
            int e = e0 + lr;
            float bv = 0.f;
            if (k < 300 && e < 600)
                bv = (e < 300) ? wr0[k * 300 + e] : wr1[k * 300 + (e - 300)];
            sB[lk + q][lr] = bv;
        }
        __syncthreads();
#pragma unroll
        for (int kk = 0; kk < 16; kk++) {
            float a[4], bv[4];
#pragma unroll
            for (int i = 0; i < 4; i++) { a[i] = sA[kk][tm * 4 + i]; bv[i] = sB[kk][tn * 4 + i]; }
#pragma unroll
            for (int i = 0; i < 4; i++)
#pragma unroll
                for (int j = 0; j < 4; j++) acc[i][j] += a[i] * bv[j];
        }
        __syncthreads();
    }
#pragma unroll
    for (int i = 0; i < 4; i++) {
        int n = n0 + tm * 4 + i;
        if (n >= 1800) continue;
#pragma unroll
        for (int j = 0; j < 4; j++) {
            int e = e0 + tn * 4 + j;
            if (e >= 600) continue;
            g_Geff[(size_t)n * 600 + e] = acc[i][j];
        }
    }
}

// ---- fetch macro for gemm8x8 prefetch double-buffer ----
#define GFETCH(K0) do { \
    int kb = (K0) + lk; \
    pA0 = make_float4(0.f, 0.f, 0.f, 0.f); pA1 = pA0; pB0 = pA0; pB1 = pA0; \
    int gm0 = m0 + lr, gm1 = m0 + lr + 64; \
    int gn0 = n0 + lr, gn1 = n0 + lr + 64; \
    if (kb + 3 < K) { \
        if (gm0 < M) pA0 = *(const float4*)(A + (size_t)gm0 * K + kb); \
        if (gm1 < M) pA1 = *(const float4*)(A + (size_t)gm1 * K + kb); \
        if (gn0 < N) pB0 = *(const float4*)(B + (size_t)gn0 * K + kb); \
        if (gn1 < N) pB1 = *(const float4*)(B + (size_t)gn1 * K + kb); \
    } else { \
        if (gm0 < M) { if (kb < K) pA0.x = A[(size_t)gm0*K+kb]; if (kb+1 < K) pA0.y = A[(size_t)gm0*K+kb+1]; if (kb+2 < K) pA0.z = A[(size_t)gm0*K+kb+2]; } \
        if (gm1 < M) { if (kb < K) pA1.x = A[(size_t)gm1*K+kb]; if (kb+1 < K) pA1.y = A[(size_t)gm1*K+kb+1]; if (kb+2 < K) pA1.z = A[(size_t)gm1*K+kb+2]; } \
        if (gn0 < N) { if (kb < K) pB0.x = B[(size_t)gn0*K+kb]; if (kb+1 < K) pB0.y = B[(size_t)gn0*K+kb+1]; if (kb+2 < K) pB0.z = B[(size_t)gn0*K+kb+2]; } \
        if (gn1 < N) { if (kb < K) pB1.x = B[(size_t)gn1*K+kb]; if (kb+1 < K) pB1.y = B[(size_t)gn1*K+kb+1]; if (kb+2 < K) pB1.z = B[(size_t)gn1*K+kb+2]; } \
    } \
} while (0)

#define GEMM_TILE_STORE() do { \
    sA[(lk + 0) * 132 + lr] = pA0.x; sA[(lk + 1) * 132 + lr] = pA0.y; \
    sA[(lk + 2) * 132 + lr] = pA0.z; sA[(lk + 3) * 132 + lr] = pA0.w; \
    sA[(lk + 0) * 132 + 64 + lr] = pA1.x; sA[(lk + 1) * 132 + 64 + lr] = pA1.y; \
    sA[(lk + 2) * 132 + 64 + lr] = pA1.z; sA[(lk + 3) * 132 + 64 + lr] = pA1.w; \
    sB[(lk + 0) * 132 + lr] = pB0.x; sB[(lk + 1) * 132 + lr] = pB0.y; \
    sB[(lk + 2) * 132 + lr] = pB0.z; sB[(lk + 3) * 132 + lr] = pB0.w; \
    sB[(lk + 0) * 132 + 64 + lr] = pB1.x; sB[(lk + 1) * 132 + 64 + lr] = pB1.y; \
    sB[(lk + 2) * 132 + 64 + lr] = pB1.z; sB[(lk + 3) * 132 + 64 + lr] = pB1.w; \
} while (0)

#define GEMM_TILE_MATH() do { \
    _Pragma("unroll") \
    for (int kk = 0; kk < 16; kk++) { \
        float4 xa0 = *(const float4*)(sA + kk * 132 + tm * 4); \
        float4 xa1 = *(const float4*)(sA + kk * 132 + 64 + tm * 4); \
        float4 xb0 = *(const float4*)(sB + kk * 132 + tn * 4); \
        float4 xb1 = *(const float4*)(sB + kk * 132 + 64 + tn * 4); \
        unsigned long long bp[4]; \
        asm("mov.b64 %0,{%1,%2};" : "=l"(bp[0]) : "f"(xb0.x), "f"(xb0.y)); \
        asm("mov.b64 %0,{%1,%2};" : "=l"(bp[1]) : "f"(xb0.z), "f"(xb0.w)); \
        asm("mov.b64 %0,{%1,%2};" : "=l"(bp[2]) : "f"(xb1.x), "f"(xb1.y)); \
        asm("mov.b64 %0,{%1,%2};" : "=l"(bp[3]) : "f"(xb1.z), "f"(xb1.w)); \
        float a[8] = {xa0.x, xa0.y, xa0.z, xa0.w, xa1.x, xa1.y, xa1.z, xa1.w}; \
        _Pragma("unroll") \
        for (int i = 0; i < 8; i++) { \
            unsigned long long ap; \
            asm("mov.b64 %0,{%1,%1};" : "=l"(ap) : "f"(a[i])); \
            _Pragma("unroll") \
            for (int j = 0; j < 4; j++) \
                asm("fma.rn.f32x2 %0,%1,%2,%0;" : "+l"(acc2[i][j]) : "l"(ap), "l"(bp[j])); \
        } \
    } \
} while (0)

#define GEMM_EPILOGUE() do { \
    _Pragma("unroll") \
    for (int i = 0; i < 8; i++) { \
        int m = m0 + ((i < 4) ? (tm * 4 + i) : (64 + tm * 4 + i - 4)); \
        if (m >= M) continue; \
        _Pragma("unroll") \
        for (int j = 0; j < 8; j++) { \
            int n = n0 + ((j < 4) ? (tn * 4 + j) : (64 + tn * 4 + j - 4)); \
            if (n >= N) continue; \
            float lo, hi; \
            asm("mov.b64 {%0,%1},%2;" : "=f"(lo), "=f"(hi) : "l"(acc2[i][j >> 1])); \
            float v = ((j & 1) ? hi : lo) + (bias ? bias[n] : 0.f); \
            if (relu) v = fmaxf(v, 0.f); \
            C[(size_t)m * N + n] = v; \
        } \
    } \
} while (0)

// ---- dense GEMM: C=A@B^T+bias (opt relu). BM=128,BN=128,BK=16, 8x8, f32x2 ----
__global__ void __launch_bounds__(256, 2) gemm8x8(
    const float* __restrict__ A, const float* __restrict__ B,
    const float* __restrict__ bias, float* __restrict__ C,
    int M, int N, int K, int relu)
{
    __shared__ float sA[16 * 132];
    __shared__ float sB[16 * 132];
    int tid = threadIdx.x;
    int m0 = blockIdx.y * 128, n0 = blockIdx.x * 128;
    int tm = tid & 15, tn = tid >> 4;
    int lr = tid >> 2, lk = (tid & 3) * 4;
    unsigned long long acc2[8][4];
#pragma unroll
    for (int i = 0; i < 8; i++)
#pragma unroll
        for (int j = 0; j < 4; j++) acc2[i][j] = 0ull;

    float4 pA0, pA1, pB0, pB1;
    int T = (K + 15) / 16;
    GFETCH(0);
    for (int t = 0; t < T; t++) {
        GEMM_TILE_STORE();
        __syncthreads();
        if (t + 1 < T) GFETCH((t + 1) * 16);
        GEMM_TILE_MATH();
        __syncthreads();
    }
    GEMM_EPILOGUE();
}

// ---- head GEMM: A is virtual [4096, 2524] = [H0..H4 | features] ----
__device__ __forceinline__ float4 head_fetch(
    const float* __restrict__ Hbase, const float* __restrict__ feat,
    int m, int kb)
{
    if (kb < 1500) {
        int seg = kb / 300, off = kb - seg * 300;
        return *(const float4*)(Hbase + (size_t)seg * HSZ + (size_t)m * 300 + off);
    }
    return *(const float4*)(feat + (size_t)m * EMB + (kb - 1500));
}

__global__ void __launch_bounds__(256, 2) gemm_head(
    const float* __restrict__ Hbase, const float* __restrict__ feat,
    const float* __restrict__ B,
    const float* __restrict__ bias, float* __restrict__ C,
    int M, int N, int K, int relu)
{
    __shared__ float sA[16 * 132];
    __shared__ float sB[16 * 132];
    int tid = threadIdx.x;
    int m0 = blockIdx.y * 128, n0 = blockIdx.x * 128;
    int tm = tid & 15, tn = tid >> 4;
    int lr = tid >> 2, lk = (tid & 3) * 4;
    unsigned long long acc2[8][4];
#pragma unroll
    for (int i = 0; i < 8; i++)
#pragma unroll
        for (int j = 0; j < 4; j++) acc2[i][j] = 0ull;

    float4 pA0, pA1, pB0, pB1;
    int T = (K + 15) / 16;

#define HFETCH(K0) do { \
    int kb = (K0) + lk; \
    pA0 = make_float4(0.f, 0.f, 0.f, 0.f); pA1 = pA0; pB0 = pA0; pB1 = pA0; \
    int gm0 = m0 + lr, gm1 = m0 + lr + 64; \
    int gn0 = n0 + lr, gn1 = n0 + lr + 64; \
    if (kb < K) { \
        pA0 = head_fetch(Hbase, feat, gm0, kb); \
        pA1 = head_fetch(Hbase, feat, gm1, kb); \
        if (gn0 < N) pB0 = *(const float4*)(B + (size_t)gn0 * K + kb); \
        if (gn1 < N) pB1 = *(const float4*)(B + (size_t)gn1 * K + kb); \
    } \
} while (0)

    HFETCH(0);
    for (int t = 0; t < T; t++) {
        GEMM_TILE_STORE();
        __syncthreads();
        if (t + 1 < T) HFETCH((t + 1) * 16);
        GEMM_TILE_MATH();
        __syncthreads();
    }
    GEMM_EPILOGUE();
#undef HFETCH
}

// ---------------- persistent per-layer scan kernel (384 threads) ----------------
__global__ void __launch_bounds__(NTHR, 1) persist_layer(
    const float* __restrict__ Hin, float* __restrict__ H1,
    const float* __restrict__ XIP,
    const float* __restrict__ wq, const float* __restrict__ wk,
    const float* __restrict__ gatb, int layer,
    const int* __restrict__ spk, const int* __restrict__ start,
    const float* __restrict__ bhh_c, const float* __restrict__ bih_p,
    const float* __restrict__ Geff, float* __restrict__ uT,
    float* __restrict__ G2)
{
    extern __shared__ float dsm[];
    unsigned long long* sW64 = (unsigned long long*)dsm;     // 9600 u64 dup pairs
    unsigned long long* sP   = sW64 + SW64_N;                // 6144 u64 partials

    __shared__ float s12[12];
    __shared__ float s_w0[64];
    __shared__ float s_w1[64];
    __shared__ float s_kdot[64];
    __shared__ float s_qd[64];
    __shared__ float s_bias[16];

    const int tid = threadIdx.x;
    const int cta = blockIdx.x;
    const int b = cta;
    const int n0 = cta * 16;
    const int wid = tid >> 5, lid = tid & 31;

    for (int idx = tid; idx < SW64_N; idx += NTHR) {
        int k = idx >> 4, r = idx & 15;
        int n = n0 + r;
        float w = (n < GEFFN) ? Geff[(size_t)n * 600 + k] : 0.f;
        unsigned long long p;
        asm("mov.b64 %0,{%1,%1};" : "=l"(p) : "f"(w));
        sW64[idx] = p;
    }
    if (tid < 16) {
        int n = n0 + tid;
        float bv = 0.f;
        if (n < 900) bv = bhh_c[n];
        else if (n < 1800) bv = bih_p[n - 900];
        s_bias[tid] = bv;
    }

    // phase-B mapping: 12 warps = 12 k-slices of 50
    const int bg = tid & 15, rg = (tid >> 4) & 1, ks = tid >> 5;
    const float* G2row = G2 + (size_t)b * G2LD;
    const ulonglong2* uTv = (const ulonglong2*)uT;
    const unsigned sWaddr = (unsigned)__cvta_generic_to_shared(sW64)
                          + (unsigned)(((ks * 50) * 16 + rg * 8) * 8);

    const float gb = gatb[layer];

    if (cta < 64) {
        for (int i = wid; i < 64; i += 12) {
            float p = 0.f;
            const float* hr = Hin + ((size_t)b * NSEQ + i) * HID;
            for (int j = lid; j < HID; j += 32) p += hr[j] * wq[j];
#pragma unroll
            for (int o = 16; o > 0; o >>= 1) p += __shfl_xor_sync(0xffffffffu, p, o);
            if (lid == 0) s_qd[i] = p + gb;
        }
        const float* xi = XIP + (size_t)b * NSEQ * 1800;
        const float* xp = xi + 900;
        const float* x0 = Hin + (size_t)b * NSEQ * HID;
        float* h1 = H1 + (size_t)b * NSEQ * HID;
        float kp = 0.f;
        int d = tid;
        if (d < HID) {
            float r  = sigf(xi[d] + bhh_c[d]);
            float z  = sigf(xi[300 + d] + bhh_c[300 + d]);
            float nn = tanhfast(xi[600 + d] + r * bhh_c[600 + d]);
            float C0 = (1.f - z) * nn;
            float r2 = sigf(bih_p[d] + xp[d]);
            float z2 = sigf(bih_p[300 + d] + xp[300 + d]);
            float n2 = tanhfast(bih_p[600 + d] + r2 * xp[600 + d]);
            float P0 = (1.f - z2) * n2 + z2 * x0[d];
            float h = C0 + P0;
            h1[d] = h;
            kp = h * wk[d];
        }
        float kss = bsum384(kp, s12);
        if (tid == 0) s_kdot[0] = kss;
    }
    __syncthreads();

    for (int i = 1; i <= 63; i++) {
        // ===== phase A (CTAs 0..63): GRU row i-1, attention -> uT(i) =====
        if (cta < 64) {
            if (i >= 2) {
                int row = i - 1;
                const float* xi = XIP + ((size_t)b * NSEQ + row) * 1800;
                const float* xp = xi + 900;
                const float* q  = Hin + ((size_t)b * NSEQ + row) * HID;
                float* h1r = H1 + ((size_t)b * NSEQ + row) * HID;
                int d = tid;
                float xiv0 = 0.f, xiv1 = 0.f, xiv2 = 0.f;
                float xpv0 = 0.f, xpv1 = 0.f, xpv2 = 0.f, qv = 0.f;
                if (d < HID) {   // prefetch layer-constant inputs before the wait
                    xiv0 = xi[d]; xiv1 = xi[300 + d]; xiv2 = xi[600 + d];
                    xpv0 = xp[d]; xpv1 = xp[300 + d]; xpv2 = xp[600 + d];
                    qv = q[d];
                }
                if (tid == 0) waitge(&g_gcnt, NCTA * (unsigned)(i - 1));
                __syncthreads();
                float kp = 0.f;
                if (d < HID) {
                    float Md = __ldcg(G2row + 1800 + d);
                    float r  = sigf(xiv0 + __ldcg(G2row + d));
                    float z  = sigf(xiv1 + __ldcg(G2row + 300 + d));
                    float nn = tanhfast(xiv2 + r * __ldcg(G2row + 600 + d));
                    float Cc = (1.f - z) * nn + z * Md;
                    float r2 = sigf(__ldcg(G2row + 900 + d)  + xpv0);
                    float z2 = sigf(__ldcg(G2row + 1200 + d) + xpv1);
                    float n2 = tanhfast(__ldcg(G2row + 1500 + d) + r2 * xpv2);
                    float Pp = (1.f - z2) * n2 + z2 * qv;
                    float h = Cc + Pp;
                    h1r[d] = h;
                    kp = h * wk[d];
                }
                float kss = bsum384(kp, s12);
                if (tid == 0) s_kdot[row] = kss;
                __syncthreads();
            }
            int st = start[b * NSEQ + i];
            int cnt = i - st;
            if (tid < 32) {
                int spki = spk[b * NSEQ + i];
                float qd = s_qd[i];
                float a1 = (tid < cnt)      ? qd + s_kdot[st + tid]      : -1e30f;
                float a2 = (tid + 32 < cnt) ? qd + s_kdot[st + tid + 32] : -1e30f;
                float m = fmaxf(a1, a2);
#pragma unroll
                for (int o = 16; o > 0; o >>= 1) m = fmaxf(m, __shfl_xor_sync(0xffffffffu, m, o));
                float e1 = (tid < cnt)      ? __expf(a1 - m) : 0.f;
                float e2 = (tid + 32 < cnt) ? __expf(a2 - m) : 0.f;
                float s = e1 + e2;
#pragma unroll
                for (int o = 16; o > 0; o >>= 1) s += __shfl_xor_sync(0xffffffffu, s, o);
                float inv = __fdividef(1.f, s);
                if (tid < cnt) {
                    float w = e1 * inv;
                    float smv = (spk[b * NSEQ + st + tid] == spki) ? 1.f : 0.f;
                    s_w0[tid] = w * smv;
                    s_w1[tid] = w * (1.f - smv);
                }
                if (tid + 32 < cnt) {
                    float w = e2 * inv;
                    float smv = (spk[b * NSEQ + st + tid + 32] == spki) ? 1.f : 0.f;
                    s_w0[tid + 32] = w * smv;
                    s_w1[tid + 32] = w * (1.f - smv);
                }
            }
            __syncthreads();
            for (int d = tid; d < 600; d += NTHR) {
                int ei = (d < 300) ? d : d - 300;
                const float* wt = (d < 300) ? s_w0 : s_w1;
                const float* base = H1 + ((size_t)b * NSEQ + st) * HID + ei;
                float acc = 0.f;
#pragma unroll 4
                for (int j = 0; j < cnt; j++)
                    acc += wt[j] * base[j * HID];
                __stcg(uT + d * 64 + b, acc);
            }
            __syncthreads();                 // all u-stores sequenced before tid0's release
            if (tid == 0) red_rel(&g_ucnt);
        }
        // ===== all CTAs: wait u(i), then B with direct-L2 u reads =====
        if (tid == 0) waitge(&g_ucnt, 64u * (unsigned)i);
        __syncthreads();

        unsigned long long a01[8], a23[8];
#pragma unroll
        for (int r = 0; r < 8; r++) { a01[r] = 0ull; a23[r] = 0ull; }
        {
            const ulonglong2* up = uTv + (ks * 50) * 16 + bg;
            unsigned wA = sWaddr;
#pragma unroll 5
            for (int kk = 0; kk < 50; kk++) {
                ulonglong2 uv = __ldcg(up);
                up += 16;
                unsigned long long w0, w1, w2, w3, w4, w5, w6, w7;
                asm volatile("ld.shared.v2.u64 {%0,%1},[%2];" : "=l"(w0), "=l"(w1) : "r"(wA));
                asm volatile("ld.shared.v2.u64 {%0,%1},[%2];" : "=l"(w2), "=l"(w3) : "r"(wA + 16u));
                asm volatile("ld.shared.v2.u64 {%0,%1},[%2];" : "=l"(w4), "=l"(w5) : "r"(wA + 32u));
                asm volatile("ld.shared.v2.u64 {%0,%1},[%2];" : "=l"(w6), "=l"(w7) : "r"(wA + 48u));
                wA += 128u;
                asm("fma.rn.f32x2 %0,%1,%2,%0;" : "+l"(a01[0]) : "l"(uv.x), "l"(w0));
                asm("fma.rn.f32x2 %0,%1,%2,%0;" : "+l"(a23[0]) : "l"(uv.y), "l"(w0));
                asm("fma.rn.f32x2 %0,%1,%2,%0;" : "+l"(a01[1]) : "l"(uv.x), "l"(w1));
                asm("fma.rn.f32x2 %0,%1,%2,%0;" : "+l"(a23[1]) : "l"(uv.y), "l"(w1));
                asm("fma.rn.f32x2 %0,%1,%2,%0;" : "+l"(a01[2]) : "l"(uv.x), "l"(w2));
                asm("fma.rn.f32x2 %0,%1,%2,%0;" : "+l"(a23[2]) : "l"(uv.y), "l"(w2));
                asm("fma.rn.f32x2 %0,%1,%2,%0;" : "+l"(a01[3]) : "l"(uv.x), "l"(w3));
                asm("fma.rn.f32x2 %0,%1,%2,%0;" : "+l"(a23[3]) : "l"(uv.y), "l"(w3));
                asm("fma.rn.f32x2 %0,%1,%2,%0;" : "+l"(a01[4]) : "l"(uv.x), "l"(w4));
                asm("fma.rn.f32x2 %0,%1,%2,%0;" : "+l"(a23[4]) : "l"(uv.y), "l"(w4));
                asm("fma.rn.f32x2 %0,%1,%2,%0;" : "+l"(a01[5]) : "l"(uv.x), "l"(w5));
                asm("fma.rn.f32x2 %0,%1,%2,%0;" : "+l"(a23[5]) : "l"(uv.y), "l"(w5));
                asm("fma.rn.f32x2 %0,%1,%2,%0;" : "+l"(a01[6]) : "l"(uv.x), "l"(w6));
                asm("fma.rn.f32x2 %0,%1,%2,%0;" : "+l"(a23[6]) : "l"(uv.y), "l"(w6));
                asm("fma.rn.f32x2 %0,%1,%2,%0;" : "+l"(a01[7]) : "l"(uv.x), "l"(w7));
                asm("fma.rn.f32x2 %0,%1,%2,%0;" : "+l"(a23[7]) : "l"(uv.y), "l"(w7));
            }
        }
#pragma unroll
        for (int r = 0; r < 8; r++) {
            int row = rg * 8 + r;
            sP[((ks * 16 + row) * 16 + bg) * 2 + 0] = a01[r];
            sP[((ks * 16 + row) * 16 + bg) * 2 + 1] = a23[r];
        }
        __syncthreads();
        {
#pragma unroll
            for (int t = 0; t < 2; t++) {
                int o = tid + t * NTHR;
                if (o >= 512) break;
                int row = o >> 5, rem = o & 31;
                int bg2 = rem >> 1, p = rem & 1;
                unsigned long long s = sP[(row * 16 + bg2) * 2 + p];
#pragma unroll
                for (int k2 = 1; k2 < 12; k2++) {
                    unsigned long long v = sP[((k2 * 16 + row) * 16 + bg2) * 2 + p];
                    asm("add.rn.f32x2 %0,%1,%2;" : "=l"(s) : "l"(s), "l"(v));
                }
                unsigned long long bp;
                asm("mov.b64 %0,{%1,%1};" : "=l"(bp) : "f"(s_bias[row]));
                asm("add.rn.f32x2 %0,%1,%2;" : "=l"(s) : "l"(s), "l"(bp));
                int n = n0 + row;
                if (n < GEFFN) {
                    float lo, hi;
                    asm("mov.b64 {%0,%1},%2;" : "=f"(lo), "=f"(hi) : "l"(s));
                    int b0 = bg2 * 4 + p * 2;
                    __stcg(G2 + (size_t)b0 * G2LD + n, lo);
                    __stcg(G2 + (size_t)(b0 + 1) * G2LD + n, hi);
                }
            }
        }
        __syncthreads();                     // all G2-stores sequenced before tid0's release
        if (tid == 0) red_rel(&g_gcnt);
    }

    // final GRU update: row 63
    if (cta < 64) {
        if (tid == 0) waitge(&g_gcnt, NCTA * 63u);
        __syncthreads();
        int row = 63;
        const float* xi = XIP + ((size_t)b * NSEQ + row) * 1800;
        const float* xp = xi + 900;
        const float* q  = Hin + ((size_t)b * NSEQ + row) * HID;
        float* h1r = H1 + ((size_t)b * NSEQ + row) * HID;
        int d = tid;
        if (d < HID) {
            float Md = __ldcg(G2row + 1800 + d);
            float r  = sigf(xi[d]       + __ldcg(G2row + d));
            float z  = sigf(xi[300 + d] + __ldcg(G2row + 300 + d));
            float nn = tanhfast(xi[600 + d] + r * __ldcg(G2row + 600 + d));
            float Cc = (1.f - z) * nn + z * Md;
            float r2 = sigf(__ldcg(G2row + 900 + d)  + xp[d]);
            float z2 = sigf(__ldcg(G2row + 1200 + d) + xp[300 + d]);
            float n2 = tanhfast(__ldcg(G2row + 1500 + d) + r2 * xp[600 + d]);
            float Pp = (1.f - z2) * n2 + z2 * q[d];
            h1r[d] = Cc + Pp;
        }
    }
}

extern "C" void kernel_launch(void* const* d_in, const int* in_sizes, int n_in,
                              void* d_out, int out_size) {
    const float* features = (const float*)d_in[0];
    const int*   speakers = (const int*)d_in[1];
    const float* w_in   = (const float*)d_in[2];
    const float* b_in   = (const float*)d_in[3];
    const float* gat_wq = (const float*)d_in[4];
    const float* gat_wk = (const float*)d_in[5];
    const float* gat_b  = (const float*)d_in[6];
    const float* wr0    = (const float*)d_in[7];
    const float* wr1    = (const float*)d_in[8];
    const float* wih_c  = (const float*)d_in[9];
    const float* whh_c  = (const float*)d_in[10];
    const float* bih_c  = (const float*)d_in[11];
    const float* bhh_c  = (const float*)d_in[12];
    const float* wih_p  = (const float*)d_in[13];
    const float* whh_p  = (const float*)d_in[14];
    const float* bih_p  = (const float*)d_in[15];
    const float* bhh_p  = (const float*)d_in[16];
    const float* w1 = (const float*)d_in[17];
    const float* b1 = (const float*)d_in[18];
    const float* w2 = (const float*)d_in[19];
    const float* b2 = (const float*)d_in[20];
    const float* w3 = (const float*)d_in[21];
    const float* b3 = (const float*)d_in[22];

    float *H, *XIPp, *WXp, *bXp, *Geffp, *uTp, *G2p, *h1p, *h2p;
    int *startp;
    cudaGetSymbolAddress((void**)&H,     g_H);
    cudaGetSymbolAddress((void**)&XIPp,  g_XIP);
    cudaGetSymbolAddress((void**)&WXp,   g_WX);
    cudaGetSymbolAddress((void**)&bXp,   g_bX);
    cudaGetSymbolAddress((void**)&Geffp, g_Geff);
    cudaGetSymbolAddress((void**)&uTp,   g_uT);
    cudaGetSymbolAddress((void**)&G2p,   g_G2);
    cudaGetSymbolAddress((void**)&startp,g_start);
    cudaGetSymbolAddress((void**)&h1p,   g_h1);
    cudaGetSymbolAddress((void**)&h2p,   g_h2);

    cudaFuncSetAttribute(persist_layer,
                         cudaFuncAttributeMaxDynamicSharedMemorySize,
                         DSMEM_B);

    const int MROWS = BATCH * NSEQ;
    const int PREP_GRID = EW_BLOCKS + GEFF_TX * GEFF_TY;

    for (int l = 0; l < 4; l++) {
        k_prep2<<<PREP_GRID, 256>>>(
            speakers,
            wih_c + l * G3 * HID, whh_p + l * G3 * HID,
            bih_c + l * G3, bhh_p + l * G3,
            whh_c + l * G3 * HID, wih_p + l * G3 * HID,
            wr0 + l * HID * HID, wr1 + l * HID * HID);

        if (l == 0) {
            gemm8x8<<<dim3((HID + 127) / 128, MROWS / 128), 256>>>(
                features, w_in, b_in, H, MROWS, HID, EMB, 1);
        }
        const float* Hin = H + l * HSZ;
        float* H1 = H + (l + 1) * HSZ;

        gemm8x8<<<dim3((1800 + 127) / 128, MROWS / 128), 256>>>(
            Hin, WXp, bXp, XIPp, MROWS, 1800, HID, 0);

        persist_layer<<<NCTA, NTHR, DSMEM_B>>>(
            Hin, H1, XIPp, gat_wq + l * HID, gat_wk + l * HID, gat_b, l,
            speakers, startp, bhh_c + l * G3, bih_p + l * G3, Geffp, uTp, G2p);
    }

    // head: h1 = relu([H|feat] @ w1^T + b1) with fused concat
    gemm_head<<<dim3((HID + 127) / 128, MROWS / 128), 256>>>(
        H, features, w1, b1, h1p, MROWS, HID, KCAT, 1);
    gemm8x8<<<dim3((HID + 127) / 128, MROWS / 128), 256>>>(
        h1p, w2, b2, h2p, MROWS, HID, HID, 1);
    gemm8x8<<<dim3(1, MROWS / 128), 256>>>(
        h2p, w3, b3, (float*)d_out, MROWS, 7, HID, 0);
}